// round 8
// baseline (speedup 1.0000x reference)
#include <cuda_runtime.h>
#include <math.h>
#include <stdint.h>

#define B_  8
#define C_  512
#define DD_ 256
#define HW_ 4096
#define HEADS_ 8
#define CPH_ 32
#define HID_ 16
#define KSPLIT 8

// ---------------- scratch ----------------
__device__ __align__(16) float  g_wt[9*256*512];   // conv weights [tap][co][cin]
__device__ float2 g_twid[4096];
__device__ float  g_y   [(size_t)B_*DD_*HW_];
__device__ float  g_fre [(size_t)B_*DD_*HW_];
__device__ float  g_fim [(size_t)B_*DD_*HW_];
__device__ float  g_g1  [(size_t)B_*HID_*HW_];
__device__ float  g_attnS[KSPLIT*64*64*64];
__device__ float2 g_attn2[64*1024];
__device__ float  g_or  [(size_t)B_*DD_*HW_];
__device__ float  g_oi  [(size_t)B_*DD_*HW_];
__device__ float  g_out2[(size_t)B_*C_*HW_];

// ---------------- tf32 helpers ----------------
__device__ __forceinline__ uint32_t f2tf(float f) {
    uint32_t u;
    asm("cvt.rna.tf32.f32 %0, %1;" : "=r"(u) : "f"(f));
    return u;
}
__device__ __forceinline__ void mma8(float c[4], const uint32_t a[4], uint32_t b0, uint32_t b1) {
    asm volatile("mma.sync.aligned.m16n8k8.row.col.f32.tf32.tf32.f32 "
        "{%0,%1,%2,%3}, {%4,%5,%6,%7}, {%8,%9}, {%0,%1,%2,%3};"
        : "+f"(c[0]), "+f"(c[1]), "+f"(c[2]), "+f"(c[3])
        : "r"(a[0]), "r"(a[1]), "r"(a[2]), "r"(a[3]), "r"(b0), "r"(b1));
}

__device__ __forceinline__ int dig4_6(int x) {
    int b = __brev(x) >> 26;
    return ((b & 0x15) << 1) | ((b >> 1) & 0x15);
}
__device__ __forceinline__ int dig4_12(int x) {
    int b = __brev(x) >> 20;
    return ((b & 0x555) << 1) | ((b >> 1) & 0x555);
}

// ---------------- prep ----------------
__global__ void prep_kernel(const float* __restrict__ cw) {
    int tid = blockIdx.x*blockDim.x + threadIdx.x;
    int stride = gridDim.x*blockDim.x;
    if (tid < 4096) {
        float s, c;
        sincosf(-6.28318530717958647692f * (float)tid / 4096.f, &s, &c);
        g_twid[tid] = make_float2(c, s);
    }
    for (int e = tid; e < 9*256*512; e += stride) {
        int tap = e / (256*512);
        int rem = e - tap*256*512;
        int co = rem >> 9;
        int cin = rem & 511;
        g_wt[e] = cw[(co*512 + cin)*9 + tap];
    }
}

// ---------------- conv via tf32 mma + cp.async double buffer, K-chunk 16 ---------
// grid (2 co-tiles, 32 pos-tiles, 8 b), 256 threads; 288 rounds (9 taps x 32 kc)
__global__ void conv_mma_kernel(const float* __restrict__ x, const float* __restrict__ cb,
                                const float* __restrict__ bg, const float* __restrict__ bb,
                                const float* __restrict__ bm, const float* __restrict__ bv) {
    __shared__ __align__(16) float xs[2][128][20];
    __shared__ __align__(16) float ws[2][128][20];
    int b = blockIdx.z, pt = blockIdx.y, ct = blockIdx.x;
    int tid = threadIdx.x, lane = tid & 31, warp = tid >> 5;
    int wm = warp & 3, wn = warp >> 2;
    int g = lane >> 2, t = lane & 3;
    float acc[2][8][4];
#pragma unroll
    for (int i = 0; i < 2; i++)
#pragma unroll
        for (int j = 0; j < 8; j++)
#pragma unroll
            for (int q = 0; q < 4; q++) acc[i][j][q] = 0.f;

    int pos0 = pt*128;
    // per-thread fill coordinates (2 transfers per array per round)
    int e0 = tid,        pA = e0 >> 2, cA = (e0 & 3) * 4;
    int e1 = tid + 256,  pB = e1 >> 2, cB = (e1 & 3) * 4;
    uint32_t xsA[2], xsB[2], wsA[2], wsB[2];
#pragma unroll
    for (int bf = 0; bf < 2; bf++) {
        xsA[bf] = (uint32_t)__cvta_generic_to_shared(&xs[bf][pA][cA]);
        xsB[bf] = (uint32_t)__cvta_generic_to_shared(&xs[bf][pB][cB]);
        wsA[bf] = (uint32_t)__cvta_generic_to_shared(&ws[bf][pA][cA]);
        wsB[bf] = (uint32_t)__cvta_generic_to_shared(&ws[bf][pB][cB]);
    }

#define CONV_ISSUE(rd, bf)                                                          \
    {                                                                               \
        int tap = (rd) >> 5;                                                        \
        int kc  = ((rd) & 31) << 4;                                                 \
        int dh = 3*((tap/3) - 1), dw = 3*((tap - (tap/3)*3) - 1);                   \
        const float* wtp = g_wt + ((size_t)tap*256 + ct*128)*512;                   \
        int gpA = pos0 + pA;                                                        \
        int ihA = (gpA >> 6) + dh, iwA = (gpA & 63) + dw;                           \
        const float* sA = &x[((size_t)(b*HW_) + ihA*64 + iwA)*C_ + kc + cA];        \
        int vzA = ((unsigned)ihA < 64u && (unsigned)iwA < 64u) ? 16 : 0;            \
        asm volatile("cp.async.ca.shared.global [%0], [%1], 16, %2;"                \
                     :: "r"(xsA[bf]), "l"(sA), "r"(vzA));                           \
        int gpB = pos0 + pB;                                                        \
        int ihB = (gpB >> 6) + dh, iwB = (gpB & 63) + dw;                           \
        const float* sB = &x[((size_t)(b*HW_) + ihB*64 + iwB)*C_ + kc + cB];        \
        int vzB = ((unsigned)ihB < 64u && (unsigned)iwB < 64u) ? 16 : 0;            \
        asm volatile("cp.async.ca.shared.global [%0], [%1], 16, %2;"                \
                     :: "r"(xsB[bf]), "l"(sB), "r"(vzB));                           \
        asm volatile("cp.async.ca.shared.global [%0], [%1], 16;"                    \
                     :: "r"(wsA[bf]), "l"(&wtp[(size_t)pA*512 + kc + cA]));         \
        asm volatile("cp.async.ca.shared.global [%0], [%1], 16;"                    \
                     :: "r"(wsB[bf]), "l"(&wtp[(size_t)pB*512 + kc + cB]));         \
        asm volatile("cp.async.commit_group;" ::: "memory");                        \
    }

    CONV_ISSUE(0, 0);
    CONV_ISSUE(1, 1);
    for (int rd = 0; rd < 288; rd++) {
        int cur = rd & 1;
        if (rd < 287) asm volatile("cp.async.wait_group 1;" ::: "memory");
        else          asm volatile("cp.async.wait_group 0;" ::: "memory");
        __syncthreads();
#pragma unroll
        for (int ks = 0; ks < 16; ks += 8) {
            int kr = ks + t;
            uint32_t a[2][4];
#pragma unroll
            for (int mi = 0; mi < 2; mi++) {
                int m0 = wm*32 + mi*16 + g;
                a[mi][0] = __float_as_uint(ws[cur][m0][kr]);
                a[mi][1] = __float_as_uint(ws[cur][m0+8][kr]);
                a[mi][2] = __float_as_uint(ws[cur][m0][kr+4]);
                a[mi][3] = __float_as_uint(ws[cur][m0+8][kr+4]);
            }
#pragma unroll
            for (int ni = 0; ni < 8; ni++) {
                int n0 = wn*64 + ni*8 + g;
                uint32_t b0 = __float_as_uint(xs[cur][n0][kr]);
                uint32_t b1 = __float_as_uint(xs[cur][n0][kr+4]);
                mma8(acc[0][ni], a[0], b0, b1);
                mma8(acc[1][ni], a[1], b0, b1);
            }
        }
        __syncthreads();
        if (rd + 2 < 288) CONV_ISSUE(rd + 2, cur);
    }
#undef CONV_ISSUE

#pragma unroll
    for (int mi = 0; mi < 2; mi++) {
#pragma unroll
        for (int half = 0; half < 2; half++) {
            int o = ct*128 + wm*32 + mi*16 + g + half*8;
            float s = bg[o] * rsqrtf(bv[o] + 1e-5f);
            float t0 = cb[o]*s + bb[o] - bm[o]*s;
            float* dst = g_y + ((size_t)(b*DD_ + o))*HW_;
#pragma unroll
            for (int ni = 0; ni < 8; ni++) {
                int pos = pos0 + wn*64 + ni*8 + 2*t;
                float v0 = fmaxf(acc[mi][ni][half*2+0]*s + t0, 0.f);
                float v1 = fmaxf(acc[mi][ni][half*2+1]*s + t0, 0.f);
                *(float2*)&dst[pos] = make_float2(v0, v1);
            }
        }
    }
}

// ---------------- 64x64 2D FFT core, radix-4 ----------------
__device__ __forceinline__ void fft64_2d_r4(float* sr, float* si, int tid, int nt, float sign) {
#pragma unroll
    for (int s = 0; s < 3; s++) {
        int L = 1 << (2*s);
        int stp = 1024 >> (2*s);
        __syncthreads();
        for (int t = tid; t < 1024; t += nt) {
            int row = t >> 4, q = t & 15;
            int j = q & (L-1);
            int grp = q >> (2*s);
            int base = row*65 + grp*(L<<2) + j;
            float2 w1 = g_twid[j*stp];
            float2 w2 = g_twid[2*j*stp];
            float2 w3 = g_twid[3*j*stp];
            float w1i = sign*w1.y, w2i = sign*w2.y, w3i = sign*w3.y;
            float ar = sr[base],       ai = si[base];
            float x1r = sr[base+L],    x1i = si[base+L];
            float x2r = sr[base+2*L],  x2i = si[base+2*L];
            float x3r = sr[base+3*L],  x3i = si[base+3*L];
            float br = x1r*w1.x - x1i*w1i, bi = x1r*w1i + x1i*w1.x;
            float cr = x2r*w2.x - x2i*w2i, ci = x2r*w2i + x2i*w2.x;
            float dr = x3r*w3.x - x3i*w3i, di = x3r*w3i + x3i*w3.x;
            float t0r = ar+cr, t0i = ai+ci;
            float t1r = ar-cr, t1i = ai-ci;
            float t2r = br+dr, t2i = bi+di;
            float t3r = br-dr, t3i = bi-di;
            sr[base]     = t0r+t2r;        si[base]     = t0i+t2i;
            sr[base+2*L] = t0r-t2r;        si[base+2*L] = t0i-t2i;
            sr[base+L]   = t1r + sign*t3i; si[base+L]   = t1i - sign*t3r;
            sr[base+3*L] = t1r - sign*t3i; si[base+3*L] = t1i + sign*t3r;
        }
    }
    __syncthreads();
    for (int e = tid; e < 4096; e += nt) {
        int r = e >> 6, cc = e & 63;
        int d4 = dig4_6(r);
        if (r < d4) {
            float a = sr[r*65+cc]; sr[r*65+cc] = sr[d4*65+cc]; sr[d4*65+cc] = a;
            float b = si[r*65+cc]; si[r*65+cc] = si[d4*65+cc]; si[d4*65+cc] = b;
        }
    }
#pragma unroll
    for (int s = 0; s < 3; s++) {
        int L = 1 << (2*s);
        int stp = 1024 >> (2*s);
        __syncthreads();
        for (int t = tid; t < 1024; t += nt) {
            int col = t & 63, q = t >> 6;
            int j = q & (L-1);
            int grp = q >> (2*s);
            int base = (grp*(L<<2) + j)*65 + col;
            int LL = L*65;
            float2 w1 = g_twid[j*stp];
            float2 w2 = g_twid[2*j*stp];
            float2 w3 = g_twid[3*j*stp];
            float w1i = sign*w1.y, w2i = sign*w2.y, w3i = sign*w3.y;
            float ar = sr[base],       ai = si[base];
            float x1r = sr[base+LL],   x1i = si[base+LL];
            float x2r = sr[base+2*LL], x2i = si[base+2*LL];
            float x3r = sr[base+3*LL], x3i = si[base+3*LL];
            float br = x1r*w1.x - x1i*w1i, bi = x1r*w1i + x1i*w1.x;
            float cr = x2r*w2.x - x2i*w2i, ci = x2r*w2i + x2i*w2.x;
            float dr = x3r*w3.x - x3i*w3i, di = x3r*w3i + x3i*w3.x;
            float t0r = ar+cr, t0i = ai+ci;
            float t1r = ar-cr, t1i = ai-ci;
            float t2r = br+dr, t2i = bi+di;
            float t3r = br-dr, t3i = bi-di;
            sr[base]      = t0r+t2r;        si[base]      = t0i+t2i;
            sr[base+2*LL] = t0r-t2r;        si[base+2*LL] = t0i-t2i;
            sr[base+LL]   = t1r + sign*t3i; si[base+LL]   = t1i - sign*t3r;
            sr[base+3*LL] = t1r - sign*t3i; si[base+3*LL] = t1i + sign*t3r;
        }
    }
    __syncthreads();
}

__global__ void fft2_fwd_kernel() {
    __shared__ float sr[64*65], si[64*65];
    int bc = blockIdx.x;
    int tid = threadIdx.x;
    const float* src = g_y + (size_t)bc*HW_;
    for (int e = tid; e < 4096; e += 512) {
        int r = e >> 6, w = e & 63;
        sr[r*65 + dig4_6(w)] = src[e];
        si[r*65 + dig4_6(w)] = 0.f;
    }
    fft64_2d_r4(sr, si, tid, 512, 1.f);
    float* dr = g_fre + (size_t)bc*HW_;
    float* di = g_fim + (size_t)bc*HW_;
    for (int e = tid; e < 4096; e += 512) {
        dr[e] = sr[(e>>6)*65 + (e&63)];
        di[e] = si[(e>>6)*65 + (e&63)];
    }
}

// ---------------- attention scores ----------------
__global__ void attn_gemm64_kernel() {
    __shared__ uint32_t gs[64][36];
    int bh = blockIdx.x, kq = blockIdx.y;
    int tid = threadIdx.x, lane = tid & 31, warp = tid >> 5;
    int wm = warp & 3, wn = warp >> 2;
    int g = lane >> 2, t = lane & 3;
    float acc[4][4];
#pragma unroll
    for (int i = 0; i < 4; i++)
#pragma unroll
        for (int q = 0; q < 4; q++) acc[i][q] = 0.f;
    const float* fr = g_fre + (size_t)bh*CPH_*HW_;
    const float* fi = g_fim + (size_t)bh*CPH_*HW_;
    int kbeg = kq*(HW_/KSPLIT), kend = kbeg + HW_/KSPLIT;
    for (int k0 = kbeg; k0 < kend; k0 += 32) {
        __syncthreads();
#pragma unroll
        for (int r = 0; r < 2; r++) {
            int e = tid + r*256;
            int row = e >> 3, kqq = e & 7;
            const float* src = (row < 32) ? (fr + (size_t)row*HW_) : (fi + (size_t)(row-32)*HW_);
            float4 v = *(const float4*)&src[k0 + kqq*4];
            uint4 u = make_uint4(f2tf(v.x), f2tf(v.y), f2tf(v.z), f2tf(v.w));
            *(uint4*)&gs[row][kqq*4] = u;
        }
        __syncthreads();
#pragma unroll
        for (int ks = 0; ks < 32; ks += 8) {
            int kr = ks + t;
            uint32_t a[4];
            a[0] = gs[wm*16+g][kr];
            a[1] = gs[wm*16+g+8][kr];
            a[2] = gs[wm*16+g][kr+4];
            a[3] = gs[wm*16+g+8][kr+4];
#pragma unroll
            for (int ni = 0; ni < 4; ni++) {
                int n0 = wn*32 + ni*8 + g;
                mma8(acc[ni], a, gs[n0][kr], gs[n0][kr+4]);
            }
        }
    }
    float* S = g_attnS + ((size_t)(kq*64 + bh))*4096;
#pragma unroll
    for (int ni = 0; ni < 4; ni++) {
        int d = wn*32 + ni*8 + 2*t;
        int c0 = wm*16 + g;
        *(float2*)&S[(size_t)c0*64 + d]     = make_float2(acc[ni][0], acc[ni][1]);
        *(float2*)&S[(size_t)(c0+8)*64 + d] = make_float2(acc[ni][2], acc[ni][3]);
    }
}

// ---------------- attn finalize ----------------
__global__ void attn_fin_kernel(const float* __restrict__ temp) {
    int bh = blockIdx.x;
    int head = bh & 7;
    int tid = threadIdx.x;
    __shared__ float Ss[4096];
    __shared__ float ar_[32*33], ai_[32*33];
    __shared__ float inv[32];
    for (int p = tid; p < 4096; p += 256) {
        float s = 0.f;
#pragma unroll
        for (int q = 0; q < KSPLIT; q++)
            s += g_attnS[((size_t)(q*64 + bh))*4096 + p];
        Ss[p] = s;
    }
    __syncthreads();
    if (tid < 32)
        inv[tid] = rsqrtf(fmaxf(Ss[tid*64 + tid] + Ss[(32+tid)*64 + 32+tid], 1e-24f));
    __syncthreads();
    float tmp = temp[head];
    for (int p = tid; p < 1024; p += 256) {
        int cc = p >> 5, dd = p & 31;
        float sre = Ss[cc*64 + dd] - Ss[(32+cc)*64 + (32+dd)];
        float sim = Ss[cc*64 + (32+dd)] + Ss[(32+cc)*64 + dd];
        float sc = inv[cc] * inv[dd] * tmp;
        ar_[cc*33+dd] = sre*sc;
        ai_[cc*33+dd] = sim*sc;
    }
    __syncthreads();
    int w = tid >> 5, lane = tid & 31;
    for (int r = w; r < 32; r += 8) {
        float vr = ar_[r*33+lane];
        float m = vr;
        for (int o = 16; o; o >>= 1) m = fmaxf(m, __shfl_xor_sync(0xffffffffu, m, o));
        float e = expf(vr - m); float s = e;
        for (int o = 16; o; o >>= 1) s += __shfl_xor_sync(0xffffffffu, s, o);
        ar_[r*33+lane] = e / s;
        float vi = ai_[r*33+lane];
        m = vi;
        for (int o = 16; o; o >>= 1) m = fmaxf(m, __shfl_xor_sync(0xffffffffu, m, o));
        e = expf(vi - m); s = e;
        for (int o = 16; o; o >>= 1) s += __shfl_xor_sync(0xffffffffu, s, o);
        ai_[r*33+lane] = e / s;
    }
    __syncthreads();
    for (int p = tid; p < 1024; p += 256) {
        int k = p >> 5, dd = p & 31;
        float accr = 0.f, acci = 0.f;
#pragma unroll
        for (int cc = 0; cc < 32; cc++) {
            float2 w2 = g_twid[((k*cc) & 31) * 128];
            float wr = w2.x, wi = -w2.y;
            float xr = ar_[cc*33+dd], xi = ai_[cc*33+dd];
            accr += wr*xr - wi*xi;
            acci += wr*xi + wi*xr;
        }
        g_attn2[(size_t)bh*1024 + p] = make_float2(accr*(1.f/32.f), acci*(1.f/32.f));
    }
}

// ---------------- attn apply ----------------
__global__ void attn_apply_kernel() {
    __shared__ float sfr[32][132], sfi[32][132];
    __shared__ float2 a2s[32][32];
    int nc = blockIdx.x, bh = blockIdx.y;
    int tid = threadIdx.x;
    for (int p = tid; p < 1024; p += 256)
        a2s[p>>5][p&31] = g_attn2[(size_t)bh*1024 + p];
    const float* fr = g_fre + (size_t)bh*CPH_*HW_ + nc*128;
    const float* fi = g_fim + (size_t)bh*CPH_*HW_ + nc*128;
    for (int e = tid; e < 1024; e += 256) {
        int d = e >> 5, j = e & 31;
        *(float4*)&sfr[d][j*4] = *(const float4*)&fr[(size_t)d*HW_ + j*4];
        *(float4*)&sfi[d][j*4] = *(const float4*)&fi[(size_t)d*HW_ + j*4];
    }
    __syncthreads();
    int tx = tid & 15, ty = tid >> 4;
    int k0 = ty*2, n0 = tx*8;
    float ar0[8], ai0[8], ar1[8], ai1[8];
#pragma unroll
    for (int j = 0; j < 8; j++) { ar0[j]=0.f; ai0[j]=0.f; ar1[j]=0.f; ai1[j]=0.f; }
#pragma unroll
    for (int d = 0; d < 32; d++) {
        float2 a0 = a2s[k0][d], a1 = a2s[k0+1][d];
        float4 f0 = *(float4*)&sfr[d][n0], f1 = *(float4*)&sfr[d][n0+4];
        float4 h0 = *(float4*)&sfi[d][n0], h1 = *(float4*)&sfi[d][n0+4];
        float frv[8] = {f0.x,f0.y,f0.z,f0.w,f1.x,f1.y,f1.z,f1.w};
        float fiv[8] = {h0.x,h0.y,h0.z,h0.w,h1.x,h1.y,h1.z,h1.w};
#pragma unroll
        for (int j = 0; j < 8; j++) {
            ar0[j] += a0.x*frv[j] - a0.y*fiv[j];
            ai0[j] += a0.x*fiv[j] + a0.y*frv[j];
            ar1[j] += a1.x*frv[j] - a1.y*fiv[j];
            ai1[j] += a1.x*fiv[j] + a1.y*frv[j];
        }
    }
    size_t base0 = ((size_t)(bh*32 + k0))*HW_ + nc*128 + n0;
    size_t base1 = base0 + HW_;
    *(float4*)&g_or[base0]   = make_float4(ar0[0],ar0[1],ar0[2],ar0[3]);
    *(float4*)&g_or[base0+4] = make_float4(ar0[4],ar0[5],ar0[6],ar0[7]);
    *(float4*)&g_oi[base0]   = make_float4(ai0[0],ai0[1],ai0[2],ai0[3]);
    *(float4*)&g_oi[base0+4] = make_float4(ai0[4],ai0[5],ai0[6],ai0[7]);
    *(float4*)&g_or[base1]   = make_float4(ar1[0],ar1[1],ar1[2],ar1[3]);
    *(float4*)&g_or[base1+4] = make_float4(ar1[4],ar1[5],ar1[6],ar1[7]);
    *(float4*)&g_oi[base1]   = make_float4(ai1[0],ai1[1],ai1[2],ai1[3]);
    *(float4*)&g_oi[base1+4] = make_float4(ai1[4],ai1[5],ai1[6],ai1[7]);
}

// ---------------- row ifft4096 radix-4 + abs + residual ----------------
#define SKW(i) ((i) + ((i) >> 7))
__global__ void ifft_row_kernel(const float* __restrict__ x) {
    __shared__ float sr[4128], si[4128];
    int gid = blockIdx.x;
    int b = gid >> 8, cg = gid & 255;
    int tid = threadIdx.x;
    const float* pr = g_or + (size_t)gid*HW_;
    const float* pi = g_oi + (size_t)gid*HW_;
    for (int nn = tid; nn < 4096; nn += 512) {
        int d = SKW(dig4_12(nn));
        sr[d] = pr[nn];
        si[d] = pi[nn];
    }
#pragma unroll
    for (int s = 0; s < 6; s++) {
        int L = 1 << (2*s);
        int stp = 1024 >> (2*s);
        __syncthreads();
        for (int t = tid; t < 1024; t += 512) {
            int j = t & (L-1);
            int grp = t >> (2*s);
            int base = grp*(L<<2) + j;
            int i0 = SKW(base), i1 = SKW(base+L), i2 = SKW(base+2*L), i3 = SKW(base+3*L);
            float2 w1 = g_twid[j*stp];
            float2 w2 = g_twid[2*j*stp];
            float2 w3 = g_twid[3*j*stp];
            float ar = sr[i0],  ai = si[i0];
            float x1r = sr[i1], x1i = si[i1];
            float x2r = sr[i2], x2i = si[i2];
            float x3r = sr[i3], x3i = si[i3];
            float br = x1r*w1.x + x1i*w1.y, bi = -x1r*w1.y + x1i*w1.x;
            float cr = x2r*w2.x + x2i*w2.y, ci = -x2r*w2.y + x2i*w2.x;
            float dr = x3r*w3.x + x3i*w3.y, di = -x3r*w3.y + x3i*w3.x;
            float t0r = ar+cr, t0i = ai+ci;
            float t1r = ar-cr, t1i = ai-ci;
            float t2r = br+dr, t2i = bi+di;
            float t3r = br-dr, t3i = bi-di;
            sr[i0] = t0r+t2r;  si[i0] = t0i+t2i;
            sr[i2] = t0r-t2r;  si[i2] = t0i-t2i;
            sr[i1] = t1r - t3i; si[i1] = t1i + t3r;
            sr[i3] = t1r + t3i; si[i3] = t1i - t3r;
        }
    }
    __syncthreads();
    for (int nn = tid; nn < 4096; nn += 512) {
        float re = sr[SKW(nn)], im = si[SKW(nn)];
        float v = sqrtf(re*re + im*im) * (1.f/4096.f)
                + x[((size_t)b*HW_ + nn)*C_ + cg];
        g_out2[((size_t)(b*512) + cg)*HW_ + nn] = v;
    }
}

// ---------------- gating MLP stage 1 ----------------
__global__ void g1_kernel(const float* __restrict__ w1w, const float* __restrict__ w1b,
                          const float* __restrict__ bg, const float* __restrict__ bb,
                          const float* __restrict__ bm, const float* __restrict__ bv) {
    __shared__ float sw[HID_*DD_];
    __shared__ float sa[HID_], st[HID_];
    int b = blockIdx.y;
    int tid = threadIdx.x;
    int n = blockIdx.x*256 + tid;
    for (int e = tid; e < HID_*DD_; e += 256) sw[e] = w1w[e];
    if (tid < HID_) {
        float s = bg[tid] * rsqrtf(bv[tid] + 1e-5f);
        sa[tid] = s;
        st[tid] = w1b[tid]*s + bb[tid] - bm[tid]*s;
    }
    __syncthreads();
    float acc[HID_];
#pragma unroll
    for (int o = 0; o < HID_; o++) acc[o] = 0.f;
    const float* fr = g_fre + (size_t)b*DD_*HW_ + n;
    for (int c = 0; c < DD_; c++) {
        float v = fr[(size_t)c*HW_];
#pragma unroll
        for (int o = 0; o < HID_; o++) acc[o] += v * sw[o*DD_ + c];
    }
#pragma unroll
    for (int o = 0; o < HID_; o++)
        g_g1[((size_t)(b*HID_ + o))*HW_ + n] = fmaxf(acc[o]*sa[o] + st[o], 0.f);
}

// ---------------- fused gate + ifft2 + abs + residual ----------------
__global__ void ifft2_gate_kernel(const float* __restrict__ x,
                                  const float* __restrict__ w2w,
                                  const float* __restrict__ w2b) {
    __shared__ float sr[64*65], si[64*65];
    __shared__ float w2s[HID_];
    int bc = blockIdx.x;
    int b = bc >> 8, c = bc & 255;
    int tid = threadIdx.x;
    if (tid < HID_) w2s[tid] = w2w[c*HID_ + tid];
    __syncthreads();
    float bias = w2b[c];
    float acc[8];
#pragma unroll
    for (int j = 0; j < 8; j++) acc[j] = bias;
    const float* g1p = g_g1 + (size_t)b*HID_*HW_;
#pragma unroll
    for (int o = 0; o < HID_; o++) {
        float w = w2s[o];
        const float* row = g1p + (size_t)o*HW_;
#pragma unroll
        for (int j = 0; j < 8; j++) acc[j] += w * row[tid + j*512];
    }
    const float* fre = g_fre + (size_t)bc*HW_;
    const float* fim = g_fim + (size_t)bc*HW_;
#pragma unroll
    for (int j = 0; j < 8; j++) {
        int e = tid + j*512;
        float gt = 1.f / (1.f + expf(-acc[j]));
        int r = e >> 6, w = e & 63;
        int dw = dig4_6(w);
        sr[r*65 + dw] = gt * fre[e];
        si[r*65 + dw] = gt * fim[e];
    }
    fft64_2d_r4(sr, si, tid, 512, -1.f);
    for (int e = tid; e < 4096; e += 512) {
        float re = sr[(e>>6)*65 + (e&63)], im = si[(e>>6)*65 + (e&63)];
        float v = sqrtf(re*re + im*im) * (1.f/4096.f)
                + x[((size_t)b*HW_ + e)*C_ + (256 + c)];
        g_out2[((size_t)(b*512 + 256 + c))*HW_ + e] = v;
    }
}

// ---------------- final projection via tf32 mma, KC=32 (R6 form) ----------------
__global__ void proj_mma_kernel(const float* __restrict__ pw, const float* __restrict__ pb,
                                float* __restrict__ out) {
    __shared__ uint32_t xs[128][36];
    __shared__ uint32_t ws[128][36];
    int b = blockIdx.z, nt = blockIdx.y, ot = blockIdx.x;
    int tid = threadIdx.x, lane = tid & 31, warp = tid >> 5;
    int wm = warp & 3, wn = warp >> 2;
    int g = lane >> 2, t = lane & 3;
    float acc[2][8][4];
#pragma unroll
    for (int i = 0; i < 2; i++)
#pragma unroll
        for (int j = 0; j < 8; j++)
#pragma unroll
            for (int q = 0; q < 4; q++) acc[i][j][q] = 0.f;

    int n0g = nt*128, o0g = ot*128;
    for (int kc = 0; kc < 512; kc += 32) {
        __syncthreads();
#pragma unroll
        for (int r = 0; r < 4; r++) {
            int e = tid + r*256;
            int k = e >> 5, n4 = e & 31;
            float4 v = *(const float4*)&g_out2[((size_t)(b*512 + kc + k))*HW_ + n0g + n4*4];
            xs[n4*4+0][k] = f2tf(v.x);
            xs[n4*4+1][k] = f2tf(v.y);
            xs[n4*4+2][k] = f2tf(v.z);
            xs[n4*4+3][k] = f2tf(v.w);
        }
#pragma unroll
        for (int r = 0; r < 4; r++) {
            int e = tid + r*256;
            int o = e >> 3, ch = e & 7;
            float4 v = *(const float4*)&pw[(size_t)(o0g + o)*512 + kc + ch*4];
            uint4 u = make_uint4(f2tf(v.x), f2tf(v.y), f2tf(v.z), f2tf(v.w));
            *(uint4*)&ws[o][ch*4] = u;
        }
        __syncthreads();
#pragma unroll
        for (int ks = 0; ks < 32; ks += 8) {
            int kr = ks + t;
            uint32_t a[2][4];
#pragma unroll
            for (int mi = 0; mi < 2; mi++) {
                int m0 = wm*32 + mi*16 + g;
                a[mi][0] = xs[m0][kr];
                a[mi][1] = xs[m0+8][kr];
                a[mi][2] = xs[m0][kr+4];
                a[mi][3] = xs[m0+8][kr+4];
            }
#pragma unroll
            for (int ni = 0; ni < 8; ni++) {
                int n0 = wn*64 + ni*8 + g;
                uint32_t b0 = ws[n0][kr];
                uint32_t b1 = ws[n0][kr+4];
                mma8(acc[0][ni], a[0], b0, b1);
                mma8(acc[1][ni], a[1], b0, b1);
            }
        }
    }
#pragma unroll
    for (int mi = 0; mi < 2; mi++) {
#pragma unroll
        for (int half = 0; half < 2; half++) {
            int n = n0g + wm*32 + mi*16 + g + half*8;
#pragma unroll
            for (int ni = 0; ni < 8; ni++) {
                int o = o0g + wn*64 + ni*8 + 2*t;
                float2 bias = *(const float2*)&pb[o];
                float v0 = acc[mi][ni][half*2+0] + bias.x;
                float v1 = acc[mi][ni][half*2+1] + bias.y;
                *(float2*)&out[((size_t)b*HW_ + n)*C_ + o] = make_float2(v0, v1);
            }
        }
    }
}

// ---------------- launch ----------------
extern "C" void kernel_launch(void* const* d_in, const int* in_sizes, int n_in,
                              void* d_out, int out_size) {
    const float* x       = (const float*)d_in[0];
    const float* conv2_w = (const float*)d_in[1];
    const float* conv2_b = (const float*)d_in[2];
    const float* bn2_g   = (const float*)d_in[3];
    const float* bn2_b   = (const float*)d_in[4];
    const float* bn2_m   = (const float*)d_in[5];
    const float* bn2_v   = (const float*)d_in[6];
    const float* temp    = (const float*)d_in[7];
    const float* w1_w    = (const float*)d_in[8];
    const float* w1_b    = (const float*)d_in[9];
    const float* bnw_g   = (const float*)d_in[10];
    const float* bnw_b   = (const float*)d_in[11];
    const float* bnw_m   = (const float*)d_in[12];
    const float* bnw_v   = (const float*)d_in[13];
    const float* w2_w    = (const float*)d_in[14];
    const float* w2_b    = (const float*)d_in[15];
    const float* proj_w  = (const float*)d_in[16];
    const float* proj_b  = (const float*)d_in[17];
    float* out = (float*)d_out;

    prep_kernel<<<1024, 256>>>(conv2_w);
    conv_mma_kernel<<<dim3(2, 32, 8), 256>>>(x, conv2_b, bn2_g, bn2_b, bn2_m, bn2_v);
    fft2_fwd_kernel<<<2048, 512>>>();
    attn_gemm64_kernel<<<dim3(64, KSPLIT), 256>>>();
    attn_fin_kernel<<<64, 256>>>(temp);
    attn_apply_kernel<<<dim3(32, 64), 256>>>();
    ifft_row_kernel<<<2048, 512>>>(x);
    g1_kernel<<<dim3(16, 8), 256>>>(w1_w, w1_b, bnw_g, bnw_b, bnw_m, bnw_v);
    ifft2_gate_kernel<<<2048, 512>>>(x, w2_w, w2_b);
    proj_mma_kernel<<<dim3(4, 32, 8), 256>>>(proj_w, proj_b, out);
}

// round 9
// speedup vs baseline: 1.0806x; 1.0806x over previous
#include <cuda_runtime.h>
#include <math.h>
#include <stdint.h>

#define B_  8
#define C_  512
#define DD_ 256
#define HW_ 4096
#define HEADS_ 8
#define CPH_ 32
#define HID_ 16
#define KSPLIT 8

// ---------------- scratch ----------------
__device__ __align__(16) uint32_t g_wt[9*256*512];   // conv weights tf32 [tap][co][cin]
__device__ __align__(16) uint32_t g_pw[512*512];     // proj weights tf32 [o][c]
__device__ float2 g_twid[4096];
__device__ float  g_y   [(size_t)B_*DD_*HW_];
__device__ float  g_fre [(size_t)B_*DD_*HW_];
__device__ float  g_fim [(size_t)B_*DD_*HW_];
__device__ float  g_g1  [(size_t)B_*HID_*HW_];
__device__ float  g_attnS[KSPLIT*64*64*64];
__device__ float2 g_attn2[64*1024];
__device__ float  g_or  [(size_t)B_*DD_*HW_];
__device__ float  g_oi  [(size_t)B_*DD_*HW_];
__device__ float  g_out2[(size_t)B_*C_*HW_];

// ---------------- tf32 helpers ----------------
__device__ __forceinline__ uint32_t f2tf(float f) {
    uint32_t u;
    asm("cvt.rna.tf32.f32 %0, %1;" : "=r"(u) : "f"(f));
    return u;
}
__device__ __forceinline__ void mma8(float c[4], const uint32_t a[4], uint32_t b0, uint32_t b1) {
    asm volatile("mma.sync.aligned.m16n8k8.row.col.f32.tf32.tf32.f32 "
        "{%0,%1,%2,%3}, {%4,%5,%6,%7}, {%8,%9}, {%0,%1,%2,%3};"
        : "+f"(c[0]), "+f"(c[1]), "+f"(c[2]), "+f"(c[3])
        : "r"(a[0]), "r"(a[1]), "r"(a[2]), "r"(a[3]), "r"(b0), "r"(b1));
}

__device__ __forceinline__ int dig4_6(int x) {
    int b = __brev(x) >> 26;
    return ((b & 0x15) << 1) | ((b >> 1) & 0x15);
}
__device__ __forceinline__ int dig4_12(int x) {
    int b = __brev(x) >> 20;
    return ((b & 0x555) << 1) | ((b >> 1) & 0x555);
}

// ---------------- prep: twiddles + weight transposes + tf32 pre-convert ----------
__global__ void prep_kernel(const float* __restrict__ cw, const float* __restrict__ pw) {
    int tid = blockIdx.x*blockDim.x + threadIdx.x;
    int stride = gridDim.x*blockDim.x;
    if (tid < 4096) {
        float s, c;
        sincosf(-6.28318530717958647692f * (float)tid / 4096.f, &s, &c);
        g_twid[tid] = make_float2(c, s);
    }
    for (int e = tid; e < 9*256*512; e += stride) {
        int tap = e / (256*512);
        int rem = e - tap*256*512;
        int co = rem >> 9;
        int cin = rem & 511;
        g_wt[e] = f2tf(cw[(co*512 + cin)*9 + tap]);
    }
    for (int e = tid; e < 512*512; e += stride)
        g_pw[e] = f2tf(pw[e]);
}

// ---------------- conv via tf32 mma: 128co x 128pos tiles, KC=32, no cvt ---------
__global__ void conv_mma_kernel(const float* __restrict__ x, const float* __restrict__ cb,
                                const float* __restrict__ bg, const float* __restrict__ bb,
                                const float* __restrict__ bm, const float* __restrict__ bv) {
    __shared__ uint32_t xs[128][36];
    __shared__ uint32_t ws[128][36];
    int b = blockIdx.z, pt = blockIdx.y, ct = blockIdx.x;
    int tid = threadIdx.x, lane = tid & 31, warp = tid >> 5;
    int wm = warp & 3, wn = warp >> 2;
    int g = lane >> 2, t = lane & 3;
    float acc[2][8][4];
#pragma unroll
    for (int i = 0; i < 2; i++)
#pragma unroll
        for (int j = 0; j < 8; j++)
#pragma unroll
            for (int q = 0; q < 4; q++) acc[i][j][q] = 0.f;

    int pos0 = pt*128;
    for (int tap = 0; tap < 9; tap++) {
        int dh = 3*((tap/3) - 1), dw = 3*((tap%3) - 1);
        const uint32_t* wtp = g_wt + ((size_t)tap*256 + ct*128)*512;
        for (int kc = 0; kc < 512; kc += 32) {
            __syncthreads();
#pragma unroll
            for (int r = 0; r < 4; r++) {
                int e = tid + r*256;
                int pos = e >> 3, ch = e & 7;
                int gp = pos0 + pos;
                int ih = (gp >> 6) + dh, iw = (gp & 63) + dw;
                uint4 u = make_uint4(0u, 0u, 0u, 0u);
                if ((unsigned)ih < 64u && (unsigned)iw < 64u)
                    u = *(const uint4*)&x[((size_t)(b*HW_) + ih*64 + iw)*C_ + kc + ch*4];
                *(uint4*)&xs[pos][ch*4] = u;        // truncated tf32 (raw fp32 bits)
            }
#pragma unroll
            for (int r = 0; r < 4; r++) {
                int e = tid + r*256;
                int co = e >> 3, ch = e & 7;
                *(uint4*)&ws[co][ch*4] = *(const uint4*)&wtp[(size_t)co*512 + kc + ch*4];
            }
            __syncthreads();
#pragma unroll
            for (int ks = 0; ks < 32; ks += 8) {
                int kr = ks + t;
                uint32_t a[2][4];
#pragma unroll
                for (int mi = 0; mi < 2; mi++) {
                    int m0 = wm*32 + mi*16 + g;
                    a[mi][0] = ws[m0][kr];
                    a[mi][1] = ws[m0+8][kr];
                    a[mi][2] = ws[m0][kr+4];
                    a[mi][3] = ws[m0+8][kr+4];
                }
#pragma unroll
                for (int ni = 0; ni < 8; ni++) {
                    int n0 = wn*64 + ni*8 + g;
                    uint32_t b0 = xs[n0][kr];
                    uint32_t b1 = xs[n0][kr+4];
                    mma8(acc[0][ni], a[0], b0, b1);
                    mma8(acc[1][ni], a[1], b0, b1);
                }
            }
        }
    }
#pragma unroll
    for (int mi = 0; mi < 2; mi++) {
#pragma unroll
        for (int half = 0; half < 2; half++) {
            int o = ct*128 + wm*32 + mi*16 + g + half*8;
            float s = bg[o] * rsqrtf(bv[o] + 1e-5f);
            float t0 = cb[o]*s + bb[o] - bm[o]*s;
            float* dst = g_y + ((size_t)(b*DD_ + o))*HW_;
#pragma unroll
            for (int ni = 0; ni < 8; ni++) {
                int pos = pos0 + wn*64 + ni*8 + 2*t;
                float v0 = fmaxf(acc[mi][ni][half*2+0]*s + t0, 0.f);
                float v1 = fmaxf(acc[mi][ni][half*2+1]*s + t0, 0.f);
                *(float2*)&dst[pos] = make_float2(v0, v1);
            }
        }
    }
}

// ---------------- 64x64 2D FFT core, radix-4 ----------------
__device__ __forceinline__ void fft64_2d_r4(float* sr, float* si, int tid, int nt, float sign) {
#pragma unroll
    for (int s = 0; s < 3; s++) {
        int L = 1 << (2*s);
        int stp = 1024 >> (2*s);
        __syncthreads();
        for (int t = tid; t < 1024; t += nt) {
            int row = t >> 4, q = t & 15;
            int j = q & (L-1);
            int grp = q >> (2*s);
            int base = row*65 + grp*(L<<2) + j;
            float2 w1 = g_twid[j*stp];
            float2 w2 = g_twid[2*j*stp];
            float2 w3 = g_twid[3*j*stp];
            float w1i = sign*w1.y, w2i = sign*w2.y, w3i = sign*w3.y;
            float ar = sr[base],       ai = si[base];
            float x1r = sr[base+L],    x1i = si[base+L];
            float x2r = sr[base+2*L],  x2i = si[base+2*L];
            float x3r = sr[base+3*L],  x3i = si[base+3*L];
            float br = x1r*w1.x - x1i*w1i, bi = x1r*w1i + x1i*w1.x;
            float cr = x2r*w2.x - x2i*w2i, ci = x2r*w2i + x2i*w2.x;
            float dr = x3r*w3.x - x3i*w3i, di = x3r*w3i + x3i*w3.x;
            float t0r = ar+cr, t0i = ai+ci;
            float t1r = ar-cr, t1i = ai-ci;
            float t2r = br+dr, t2i = bi+di;
            float t3r = br-dr, t3i = bi-di;
            sr[base]     = t0r+t2r;        si[base]     = t0i+t2i;
            sr[base+2*L] = t0r-t2r;        si[base+2*L] = t0i-t2i;
            sr[base+L]   = t1r + sign*t3i; si[base+L]   = t1i - sign*t3r;
            sr[base+3*L] = t1r - sign*t3i; si[base+3*L] = t1i + sign*t3r;
        }
    }
    __syncthreads();
    for (int e = tid; e < 4096; e += nt) {
        int r = e >> 6, cc = e & 63;
        int d4 = dig4_6(r);
        if (r < d4) {
            float a = sr[r*65+cc]; sr[r*65+cc] = sr[d4*65+cc]; sr[d4*65+cc] = a;
            float b = si[r*65+cc]; si[r*65+cc] = si[d4*65+cc]; si[d4*65+cc] = b;
        }
    }
#pragma unroll
    for (int s = 0; s < 3; s++) {
        int L = 1 << (2*s);
        int stp = 1024 >> (2*s);
        __syncthreads();
        for (int t = tid; t < 1024; t += nt) {
            int col = t & 63, q = t >> 6;
            int j = q & (L-1);
            int grp = q >> (2*s);
            int base = (grp*(L<<2) + j)*65 + col;
            int LL = L*65;
            float2 w1 = g_twid[j*stp];
            float2 w2 = g_twid[2*j*stp];
            float2 w3 = g_twid[3*j*stp];
            float w1i = sign*w1.y, w2i = sign*w2.y, w3i = sign*w3.y;
            float ar = sr[base],       ai = si[base];
            float x1r = sr[base+LL],   x1i = si[base+LL];
            float x2r = sr[base+2*LL], x2i = si[base+2*LL];
            float x3r = sr[base+3*LL], x3i = si[base+3*LL];
            float br = x1r*w1.x - x1i*w1i, bi = x1r*w1i + x1i*w1.x;
            float cr = x2r*w2.x - x2i*w2i, ci = x2r*w2i + x2i*w2.x;
            float dr = x3r*w3.x - x3i*w3i, di = x3r*w3i + x3i*w3.x;
            float t0r = ar+cr, t0i = ai+ci;
            float t1r = ar-cr, t1i = ai-ci;
            float t2r = br+dr, t2i = bi+di;
            float t3r = br-dr, t3i = bi-di;
            sr[base]      = t0r+t2r;        si[base]      = t0i+t2i;
            sr[base+2*LL] = t0r-t2r;        si[base+2*LL] = t0i-t2i;
            sr[base+LL]   = t1r + sign*t3i; si[base+LL]   = t1i - sign*t3r;
            sr[base+3*LL] = t1r - sign*t3i; si[base+3*LL] = t1i + sign*t3r;
        }
    }
    __syncthreads();
}

__global__ void fft2_fwd_kernel() {
    __shared__ float sr[64*65], si[64*65];
    int bc = blockIdx.x;
    int tid = threadIdx.x;
    const float* src = g_y + (size_t)bc*HW_;
    for (int e = tid; e < 4096; e += 512) {
        int r = e >> 6, w = e & 63;
        sr[r*65 + dig4_6(w)] = src[e];
        si[r*65 + dig4_6(w)] = 0.f;
    }
    fft64_2d_r4(sr, si, tid, 512, 1.f);
    float* dr = g_fre + (size_t)bc*HW_;
    float* di = g_fim + (size_t)bc*HW_;
    for (int e = tid; e < 4096; e += 512) {
        dr[e] = sr[(e>>6)*65 + (e&63)];
        di[e] = si[(e>>6)*65 + (e&63)];
    }
}

// ---------------- attention scores ----------------
__global__ void attn_gemm64_kernel() {
    __shared__ uint32_t gs[64][36];
    int bh = blockIdx.x, kq = blockIdx.y;
    int tid = threadIdx.x, lane = tid & 31, warp = tid >> 5;
    int wm = warp & 3, wn = warp >> 2;
    int g = lane >> 2, t = lane & 3;
    float acc[4][4];
#pragma unroll
    for (int i = 0; i < 4; i++)
#pragma unroll
        for (int q = 0; q < 4; q++) acc[i][q] = 0.f;
    const float* fr = g_fre + (size_t)bh*CPH_*HW_;
    const float* fi = g_fim + (size_t)bh*CPH_*HW_;
    int kbeg = kq*(HW_/KSPLIT), kend = kbeg + HW_/KSPLIT;
    for (int k0 = kbeg; k0 < kend; k0 += 32) {
        __syncthreads();
#pragma unroll
        for (int r = 0; r < 2; r++) {
            int e = tid + r*256;
            int row = e >> 3, kqq = e & 7;
            const float* src = (row < 32) ? (fr + (size_t)row*HW_) : (fi + (size_t)(row-32)*HW_);
            float4 v = *(const float4*)&src[k0 + kqq*4];
            uint4 u = make_uint4(f2tf(v.x), f2tf(v.y), f2tf(v.z), f2tf(v.w));
            *(uint4*)&gs[row][kqq*4] = u;
        }
        __syncthreads();
#pragma unroll
        for (int ks = 0; ks < 32; ks += 8) {
            int kr = ks + t;
            uint32_t a[4];
            a[0] = gs[wm*16+g][kr];
            a[1] = gs[wm*16+g+8][kr];
            a[2] = gs[wm*16+g][kr+4];
            a[3] = gs[wm*16+g+8][kr+4];
#pragma unroll
            for (int ni = 0; ni < 4; ni++) {
                int n0 = wn*32 + ni*8 + g;
                mma8(acc[ni], a, gs[n0][kr], gs[n0][kr+4]);
            }
        }
    }
    float* S = g_attnS + ((size_t)(kq*64 + bh))*4096;
#pragma unroll
    for (int ni = 0; ni < 4; ni++) {
        int d = wn*32 + ni*8 + 2*t;
        int c0 = wm*16 + g;
        *(float2*)&S[(size_t)c0*64 + d]     = make_float2(acc[ni][0], acc[ni][1]);
        *(float2*)&S[(size_t)(c0+8)*64 + d] = make_float2(acc[ni][2], acc[ni][3]);
    }
}

// ---------------- attn finalize ----------------
__global__ void attn_fin_kernel(const float* __restrict__ temp) {
    int bh = blockIdx.x;
    int head = bh & 7;
    int tid = threadIdx.x;
    __shared__ float Ss[4096];
    __shared__ float ar_[32*33], ai_[32*33];
    __shared__ float inv[32];
    for (int p = tid; p < 4096; p += 256) {
        float s = 0.f;
#pragma unroll
        for (int q = 0; q < KSPLIT; q++)
            s += g_attnS[((size_t)(q*64 + bh))*4096 + p];
        Ss[p] = s;
    }
    __syncthreads();
    if (tid < 32)
        inv[tid] = rsqrtf(fmaxf(Ss[tid*64 + tid] + Ss[(32+tid)*64 + 32+tid], 1e-24f));
    __syncthreads();
    float tmp = temp[head];
    for (int p = tid; p < 1024; p += 256) {
        int cc = p >> 5, dd = p & 31;
        float sre = Ss[cc*64 + dd] - Ss[(32+cc)*64 + (32+dd)];
        float sim = Ss[cc*64 + (32+dd)] + Ss[(32+cc)*64 + dd];
        float sc = inv[cc] * inv[dd] * tmp;
        ar_[cc*33+dd] = sre*sc;
        ai_[cc*33+dd] = sim*sc;
    }
    __syncthreads();
    int w = tid >> 5, lane = tid & 31;
    for (int r = w; r < 32; r += 8) {
        float vr = ar_[r*33+lane];
        float m = vr;
        for (int o = 16; o; o >>= 1) m = fmaxf(m, __shfl_xor_sync(0xffffffffu, m, o));
        float e = expf(vr - m); float s = e;
        for (int o = 16; o; o >>= 1) s += __shfl_xor_sync(0xffffffffu, s, o);
        ar_[r*33+lane] = e / s;
        float vi = ai_[r*33+lane];
        m = vi;
        for (int o = 16; o; o >>= 1) m = fmaxf(m, __shfl_xor_sync(0xffffffffu, m, o));
        e = expf(vi - m); s = e;
        for (int o = 16; o; o >>= 1) s += __shfl_xor_sync(0xffffffffu, s, o);
        ai_[r*33+lane] = e / s;
    }
    __syncthreads();
    for (int p = tid; p < 1024; p += 256) {
        int k = p >> 5, dd = p & 31;
        float accr = 0.f, acci = 0.f;
#pragma unroll
        for (int cc = 0; cc < 32; cc++) {
            float2 w2 = g_twid[((k*cc) & 31) * 128];
            float wr = w2.x, wi = -w2.y;
            float xr = ar_[cc*33+dd], xi = ai_[cc*33+dd];
            accr += wr*xr - wi*xi;
            acci += wr*xi + wi*xr;
        }
        g_attn2[(size_t)bh*1024 + p] = make_float2(accr*(1.f/32.f), acci*(1.f/32.f));
    }
}

// ---------------- attn apply ----------------
__global__ void attn_apply_kernel() {
    __shared__ float sfr[32][132], sfi[32][132];
    __shared__ float2 a2s[32][32];
    int nc = blockIdx.x, bh = blockIdx.y;
    int tid = threadIdx.x;
    for (int p = tid; p < 1024; p += 256)
        a2s[p>>5][p&31] = g_attn2[(size_t)bh*1024 + p];
    const float* fr = g_fre + (size_t)bh*CPH_*HW_ + nc*128;
    const float* fi = g_fim + (size_t)bh*CPH_*HW_ + nc*128;
    for (int e = tid; e < 1024; e += 256) {
        int d = e >> 5, j = e & 31;
        *(float4*)&sfr[d][j*4] = *(const float4*)&fr[(size_t)d*HW_ + j*4];
        *(float4*)&sfi[d][j*4] = *(const float4*)&fi[(size_t)d*HW_ + j*4];
    }
    __syncthreads();
    int tx = tid & 15, ty = tid >> 4;
    int k0 = ty*2, n0 = tx*8;
    float ar0[8], ai0[8], ar1[8], ai1[8];
#pragma unroll
    for (int j = 0; j < 8; j++) { ar0[j]=0.f; ai0[j]=0.f; ar1[j]=0.f; ai1[j]=0.f; }
#pragma unroll
    for (int d = 0; d < 32; d++) {
        float2 a0 = a2s[k0][d], a1 = a2s[k0+1][d];
        float4 f0 = *(float4*)&sfr[d][n0], f1 = *(float4*)&sfr[d][n0+4];
        float4 h0 = *(float4*)&sfi[d][n0], h1 = *(float4*)&sfi[d][n0+4];
        float frv[8] = {f0.x,f0.y,f0.z,f0.w,f1.x,f1.y,f1.z,f1.w};
        float fiv[8] = {h0.x,h0.y,h0.z,h0.w,h1.x,h1.y,h1.z,h1.w};
#pragma unroll
        for (int j = 0; j < 8; j++) {
            ar0[j] += a0.x*frv[j] - a0.y*fiv[j];
            ai0[j] += a0.x*fiv[j] + a0.y*frv[j];
            ar1[j] += a1.x*frv[j] - a1.y*fiv[j];
            ai1[j] += a1.x*fiv[j] + a1.y*frv[j];
        }
    }
    size_t base0 = ((size_t)(bh*32 + k0))*HW_ + nc*128 + n0;
    size_t base1 = base0 + HW_;
    *(float4*)&g_or[base0]   = make_float4(ar0[0],ar0[1],ar0[2],ar0[3]);
    *(float4*)&g_or[base0+4] = make_float4(ar0[4],ar0[5],ar0[6],ar0[7]);
    *(float4*)&g_oi[base0]   = make_float4(ai0[0],ai0[1],ai0[2],ai0[3]);
    *(float4*)&g_oi[base0+4] = make_float4(ai0[4],ai0[5],ai0[6],ai0[7]);
    *(float4*)&g_or[base1]   = make_float4(ar1[0],ar1[1],ar1[2],ar1[3]);
    *(float4*)&g_or[base1+4] = make_float4(ar1[4],ar1[5],ar1[6],ar1[7]);
    *(float4*)&g_oi[base1]   = make_float4(ai1[0],ai1[1],ai1[2],ai1[3]);
    *(float4*)&g_oi[base1+4] = make_float4(ai1[4],ai1[5],ai1[6],ai1[7]);
}

// ---------------- row ifft4096 radix-4 + abs + residual ----------------
#define SKW(i) ((i) + ((i) >> 7))
__global__ void ifft_row_kernel(const float* __restrict__ x) {
    __shared__ float sr[4128], si[4128];
    int gid = blockIdx.x;
    int b = gid >> 8, cg = gid & 255;
    int tid = threadIdx.x;
    const float* pr = g_or + (size_t)gid*HW_;
    const float* pi = g_oi + (size_t)gid*HW_;
    for (int nn = tid; nn < 4096; nn += 512) {
        int d = SKW(dig4_12(nn));
        sr[d] = pr[nn];
        si[d] = pi[nn];
    }
#pragma unroll
    for (int s = 0; s < 6; s++) {
        int L = 1 << (2*s);
        int stp = 1024 >> (2*s);
        __syncthreads();
        for (int t = tid; t < 1024; t += 512) {
            int j = t & (L-1);
            int grp = t >> (2*s);
            int base = grp*(L<<2) + j;
            int i0 = SKW(base), i1 = SKW(base+L), i2 = SKW(base+2*L), i3 = SKW(base+3*L);
            float2 w1 = g_twid[j*stp];
            float2 w2 = g_twid[2*j*stp];
            float2 w3 = g_twid[3*j*stp];
            float ar = sr[i0],  ai = si[i0];
            float x1r = sr[i1], x1i = si[i1];
            float x2r = sr[i2], x2i = si[i2];
            float x3r = sr[i3], x3i = si[i3];
            float br = x1r*w1.x + x1i*w1.y, bi = -x1r*w1.y + x1i*w1.x;
            float cr = x2r*w2.x + x2i*w2.y, ci = -x2r*w2.y + x2i*w2.x;
            float dr = x3r*w3.x + x3i*w3.y, di = -x3r*w3.y + x3i*w3.x;
            float t0r = ar+cr, t0i = ai+ci;
            float t1r = ar-cr, t1i = ai-ci;
            float t2r = br+dr, t2i = bi+di;
            float t3r = br-dr, t3i = bi-di;
            sr[i0] = t0r+t2r;  si[i0] = t0i+t2i;
            sr[i2] = t0r-t2r;  si[i2] = t0i-t2i;
            sr[i1] = t1r - t3i; si[i1] = t1i + t3r;
            sr[i3] = t1r + t3i; si[i3] = t1i - t3r;
        }
    }
    __syncthreads();
    for (int nn = tid; nn < 4096; nn += 512) {
        float re = sr[SKW(nn)], im = si[SKW(nn)];
        float v = sqrtf(re*re + im*im) * (1.f/4096.f)
                + x[((size_t)b*HW_ + nn)*C_ + cg];
        g_out2[((size_t)(b*512) + cg)*HW_ + nn] = v;
    }
}

// ---------------- gating MLP stage 1 ----------------
__global__ void g1_kernel(const float* __restrict__ w1w, const float* __restrict__ w1b,
                          const float* __restrict__ bg, const float* __restrict__ bb,
                          const float* __restrict__ bm, const float* __restrict__ bv) {
    __shared__ float sw[HID_*DD_];
    __shared__ float sa[HID_], st[HID_];
    int b = blockIdx.y;
    int tid = threadIdx.x;
    int n = blockIdx.x*256 + tid;
    for (int e = tid; e < HID_*DD_; e += 256) sw[e] = w1w[e];
    if (tid < HID_) {
        float s = bg[tid] * rsqrtf(bv[tid] + 1e-5f);
        sa[tid] = s;
        st[tid] = w1b[tid]*s + bb[tid] - bm[tid]*s;
    }
    __syncthreads();
    float acc[HID_];
#pragma unroll
    for (int o = 0; o < HID_; o++) acc[o] = 0.f;
    const float* fr = g_fre + (size_t)b*DD_*HW_ + n;
    for (int c = 0; c < DD_; c++) {
        float v = fr[(size_t)c*HW_];
#pragma unroll
        for (int o = 0; o < HID_; o++) acc[o] += v * sw[o*DD_ + c];
    }
#pragma unroll
    for (int o = 0; o < HID_; o++)
        g_g1[((size_t)(b*HID_ + o))*HW_ + n] = fmaxf(acc[o]*sa[o] + st[o], 0.f);
}

// ---------------- fused gate + ifft2 + abs + residual ----------------
__global__ void ifft2_gate_kernel(const float* __restrict__ x,
                                  const float* __restrict__ w2w,
                                  const float* __restrict__ w2b) {
    __shared__ float sr[64*65], si[64*65];
    __shared__ float w2s[HID_];
    int bc = blockIdx.x;
    int b = bc >> 8, c = bc & 255;
    int tid = threadIdx.x;
    if (tid < HID_) w2s[tid] = w2w[c*HID_ + tid];
    __syncthreads();
    float bias = w2b[c];
    float acc[8];
#pragma unroll
    for (int j = 0; j < 8; j++) acc[j] = bias;
    const float* g1p = g_g1 + (size_t)b*HID_*HW_;
#pragma unroll
    for (int o = 0; o < HID_; o++) {
        float w = w2s[o];
        const float* row = g1p + (size_t)o*HW_;
#pragma unroll
        for (int j = 0; j < 8; j++) acc[j] += w * row[tid + j*512];
    }
    const float* fre = g_fre + (size_t)bc*HW_;
    const float* fim = g_fim + (size_t)bc*HW_;
#pragma unroll
    for (int j = 0; j < 8; j++) {
        int e = tid + j*512;
        float gt = 1.f / (1.f + expf(-acc[j]));
        int r = e >> 6, w = e & 63;
        int dw = dig4_6(w);
        sr[r*65 + dw] = gt * fre[e];
        si[r*65 + dw] = gt * fim[e];
    }
    fft64_2d_r4(sr, si, tid, 512, -1.f);
    for (int e = tid; e < 4096; e += 512) {
        float re = sr[(e>>6)*65 + (e&63)], im = si[(e>>6)*65 + (e&63)];
        float v = sqrtf(re*re + im*im) * (1.f/4096.f)
                + x[((size_t)b*HW_ + e)*C_ + (256 + c)];
        g_out2[((size_t)(b*512 + 256 + c))*HW_ + e] = v;
    }
}

// ---------------- final projection via tf32 mma, KC=32, no cvt ----------------
__global__ void proj_mma_kernel(const float* __restrict__ pb, float* __restrict__ out) {
    __shared__ uint32_t xs[128][36];
    __shared__ uint32_t ws[128][36];
    int b = blockIdx.z, nt = blockIdx.y, ot = blockIdx.x;
    int tid = threadIdx.x, lane = tid & 31, warp = tid >> 5;
    int wm = warp & 3, wn = warp >> 2;
    int g = lane >> 2, t = lane & 3;
    float acc[2][8][4];
#pragma unroll
    for (int i = 0; i < 2; i++)
#pragma unroll
        for (int j = 0; j < 8; j++)
#pragma unroll
            for (int q = 0; q < 4; q++) acc[i][j][q] = 0.f;

    int n0g = nt*128, o0g = ot*128;
    for (int kc = 0; kc < 512; kc += 32) {
        __syncthreads();
#pragma unroll
        for (int r = 0; r < 4; r++) {
            int e = tid + r*256;
            int k = e >> 5, n4 = e & 31;
            uint4 v = *(const uint4*)&g_out2[((size_t)(b*512 + kc + k))*HW_ + n0g + n4*4];
            xs[n4*4+0][k] = v.x;       // truncated tf32
            xs[n4*4+1][k] = v.y;
            xs[n4*4+2][k] = v.z;
            xs[n4*4+3][k] = v.w;
        }
#pragma unroll
        for (int r = 0; r < 4; r++) {
            int e = tid + r*256;
            int o = e >> 3, ch = e & 7;
            *(uint4*)&ws[o][ch*4] = *(const uint4*)&g_pw[(size_t)(o0g + o)*512 + kc + ch*4];
        }
        __syncthreads();
#pragma unroll
        for (int ks = 0; ks < 32; ks += 8) {
            int kr = ks + t;
            uint32_t a[2][4];
#pragma unroll
            for (int mi = 0; mi < 2; mi++) {
                int m0 = wm*32 + mi*16 + g;
                a[mi][0] = xs[m0][kr];
                a[mi][1] = xs[m0+8][kr];
                a[mi][2] = xs[m0][kr+4];
                a[mi][3] = xs[m0+8][kr+4];
            }
#pragma unroll
            for (int ni = 0; ni < 8; ni++) {
                int n0 = wn*64 + ni*8 + g;
                uint32_t b0 = ws[n0][kr];
                uint32_t b1 = ws[n0][kr+4];
                mma8(acc[0][ni], a[0], b0, b1);
                mma8(acc[1][ni], a[1], b0, b1);
            }
        }
    }
#pragma unroll
    for (int mi = 0; mi < 2; mi++) {
#pragma unroll
        for (int half = 0; half < 2; half++) {
            int n = n0g + wm*32 + mi*16 + g + half*8;
#pragma unroll
            for (int ni = 0; ni < 8; ni++) {
                int o = o0g + wn*64 + ni*8 + 2*t;
                float2 bias = *(const float2*)&pb[o];
                float v0 = acc[mi][ni][half*2+0] + bias.x;
                float v1 = acc[mi][ni][half*2+1] + bias.y;
                *(float2*)&out[((size_t)b*HW_ + n)*C_ + o] = make_float2(v0, v1);
            }
        }
    }
}

// ---------------- launch ----------------
extern "C" void kernel_launch(void* const* d_in, const int* in_sizes, int n_in,
                              void* d_out, int out_size) {
    const float* x       = (const float*)d_in[0];
    const float* conv2_w = (const float*)d_in[1];
    const float* conv2_b = (const float*)d_in[2];
    const float* bn2_g   = (const float*)d_in[3];
    const float* bn2_b   = (const float*)d_in[4];
    const float* bn2_m   = (const float*)d_in[5];
    const float* bn2_v   = (const float*)d_in[6];
    const float* temp    = (const float*)d_in[7];
    const float* w1_w    = (const float*)d_in[8];
    const float* w1_b    = (const float*)d_in[9];
    const float* bnw_g   = (const float*)d_in[10];
    const float* bnw_b   = (const float*)d_in[11];
    const float* bnw_m   = (const float*)d_in[12];
    const float* bnw_v   = (const float*)d_in[13];
    const float* w2_w    = (const float*)d_in[14];
    const float* w2_b    = (const float*)d_in[15];
    const float* proj_w  = (const float*)d_in[16];
    const float* proj_b  = (const float*)d_in[17];
    float* out = (float*)d_out;

    prep_kernel<<<1024, 256>>>(conv2_w, proj_w);
    conv_mma_kernel<<<dim3(2, 32, 8), 256>>>(x, conv2_b, bn2_g, bn2_b, bn2_m, bn2_v);
    fft2_fwd_kernel<<<2048, 512>>>();
    attn_gemm64_kernel<<<dim3(64, KSPLIT), 256>>>();
    attn_fin_kernel<<<64, 256>>>(temp);
    attn_apply_kernel<<<dim3(32, 64), 256>>>();
    ifft_row_kernel<<<2048, 512>>>(x);
    g1_kernel<<<dim3(16, 8), 256>>>(w1_w, w1_b, bnw_g, bnw_b, bnw_m, bnw_v);
    ifft2_gate_kernel<<<2048, 512>>>(x, w2_w, w2_b);
    proj_mma_kernel<<<dim3(4, 32, 8), 256>>>(proj_b, out);
}

// round 11
// speedup vs baseline: 1.1204x; 1.0368x over previous
#include <cuda_runtime.h>
#include <math.h>
#include <stdint.h>

#define B_  8
#define C_  512
#define DD_ 256
#define HW_ 4096
#define HEADS_ 8
#define CPH_ 32
#define HID_ 16
#define KSPLIT 8

// ---------------- scratch ----------------
__device__ __align__(16) uint32_t g_wt[9*256*512];   // conv weights tf32 [tap][co][cin]
__device__ float2 g_twid[4096];
__device__ float  g_y   [(size_t)B_*DD_*HW_];
__device__ float  g_fre [(size_t)B_*DD_*HW_];
__device__ float  g_fim [(size_t)B_*DD_*HW_];
__device__ float  g_g1  [(size_t)B_*HID_*HW_];
__device__ float  g_attnS[KSPLIT*64*64*64];
__device__ float2 g_attn2[64*1024];
__device__ float  g_or  [(size_t)B_*DD_*HW_];
__device__ float  g_oi  [(size_t)B_*DD_*HW_];
__device__ float  g_out2[(size_t)B_*C_*HW_];

// ---------------- tf32 helpers ----------------
__device__ __forceinline__ uint32_t f2tf(float f) {
    uint32_t u;
    asm("cvt.rna.tf32.f32 %0, %1;" : "=r"(u) : "f"(f));
    return u;
}
__device__ __forceinline__ void mma8(float c[4], const uint32_t a[4], uint32_t b0, uint32_t b1) {
    asm volatile("mma.sync.aligned.m16n8k8.row.col.f32.tf32.tf32.f32 "
        "{%0,%1,%2,%3}, {%4,%5,%6,%7}, {%8,%9}, {%0,%1,%2,%3};"
        : "+f"(c[0]), "+f"(c[1]), "+f"(c[2]), "+f"(c[3])
        : "r"(a[0]), "r"(a[1]), "r"(a[2]), "r"(a[3]), "r"(b0), "r"(b1));
}
__device__ __forceinline__ int dig4_6(int x) {
    int b = __brev(x) >> 26;
    return ((b & 0x15) << 1) | ((b >> 1) & 0x15);
}
__device__ __forceinline__ int dig4_12(int x) {
    int b = __brev(x) >> 20;
    return ((b & 0x555) << 1) | ((b >> 1) & 0x555);
}

// ---------------- prep ----------------
__global__ void prep_kernel(const float* __restrict__ cw) {
    int tid = blockIdx.x*blockDim.x + threadIdx.x;
    int stride = gridDim.x*blockDim.x;
    if (tid < 4096) {
        float s, c;
        sincosf(-6.28318530717958647692f * (float)tid / 4096.f, &s, &c);
        g_twid[tid] = make_float2(c, s);
    }
    for (int e = tid; e < 9*256*512; e += stride) {
        int tap = e / (256*512);
        int rem = e - tap*256*512;
        int co = rem >> 9;
        int cin = rem & 511;
        g_wt[e] = f2tf(cw[(co*512 + cin)*9 + tap]);
    }
}

// ---------------- conv via tf32 mma: 128co x 128pos tiles, 4 warps of 64x64 ------
// grid (2 co-tiles, 32 pos-tiles, 8 b), 128 threads
__global__ void conv_mma_kernel(const float* __restrict__ x, const float* __restrict__ cb,
                                const float* __restrict__ bg, const float* __restrict__ bb,
                                const float* __restrict__ bm, const float* __restrict__ bv) {
    __shared__ uint32_t xs[128][36];
    __shared__ uint32_t ws[128][36];
    int b = blockIdx.z, pt = blockIdx.y, ct = blockIdx.x;
    int tid = threadIdx.x, lane = tid & 31, warp = tid >> 5;   // 4 warps
    int wm = warp & 1, wn = warp >> 1;                         // 2 x 2 of 64x64
    int g = lane >> 2, t = lane & 3;
    float acc[4][8][4];
#pragma unroll
    for (int i = 0; i < 4; i++)
#pragma unroll
        for (int j = 0; j < 8; j++)
#pragma unroll
            for (int q = 0; q < 4; q++) acc[i][j][q] = 0.f;

    int pos0 = pt*128;
    for (int tap = 0; tap < 9; tap++) {
        int dh = 3*((tap/3) - 1), dw = 3*((tap%3) - 1);
        const uint32_t* wtp = g_wt + ((size_t)tap*256 + ct*128)*512;
        for (int kc = 0; kc < 512; kc += 32) {
            __syncthreads();
#pragma unroll
            for (int r = 0; r < 8; r++) {
                int e = tid + r*128;
                int pos = e >> 3, ch = e & 7;
                int gp = pos0 + pos;
                int ih = (gp >> 6) + dh, iw = (gp & 63) + dw;
                uint4 u = make_uint4(0u, 0u, 0u, 0u);
                if ((unsigned)ih < 64u && (unsigned)iw < 64u)
                    u = *(const uint4*)&x[((size_t)(b*HW_) + ih*64 + iw)*C_ + kc + ch*4];
                *(uint4*)&xs[pos][ch*4] = u;        // truncated tf32 (raw fp32 bits)
            }
#pragma unroll
            for (int r = 0; r < 8; r++) {
                int e = tid + r*128;
                int co = e >> 3, ch = e & 7;
                *(uint4*)&ws[co][ch*4] = *(const uint4*)&wtp[(size_t)co*512 + kc + ch*4];
            }
            __syncthreads();
#pragma unroll
            for (int ks = 0; ks < 32; ks += 8) {
                int kr = ks + t;
                uint32_t a[4][4];
#pragma unroll
                for (int mi = 0; mi < 4; mi++) {
                    int m0 = wm*64 + mi*16 + g;
                    a[mi][0] = ws[m0][kr];
                    a[mi][1] = ws[m0+8][kr];
                    a[mi][2] = ws[m0][kr+4];
                    a[mi][3] = ws[m0+8][kr+4];
                }
#pragma unroll
                for (int ni = 0; ni < 8; ni++) {
                    int n0 = wn*64 + ni*8 + g;
                    uint32_t b0 = xs[n0][kr];
                    uint32_t b1 = xs[n0][kr+4];
                    mma8(acc[0][ni], a[0], b0, b1);
                    mma8(acc[1][ni], a[1], b0, b1);
                    mma8(acc[2][ni], a[2], b0, b1);
                    mma8(acc[3][ni], a[3], b0, b1);
                }
            }
        }
    }
#pragma unroll
    for (int mi = 0; mi < 4; mi++) {
#pragma unroll
        for (int half = 0; half < 2; half++) {
            int o = ct*128 + wm*64 + mi*16 + g + half*8;
            float s = bg[o] * rsqrtf(bv[o] + 1e-5f);
            float t0 = cb[o]*s + bb[o] - bm[o]*s;
            float* dst = g_y + ((size_t)(b*DD_ + o))*HW_;
#pragma unroll
            for (int ni = 0; ni < 8; ni++) {
                int pos = pos0 + wn*64 + ni*8 + 2*t;
                float v0 = fmaxf(acc[mi][ni][half*2+0]*s + t0, 0.f);
                float v1 = fmaxf(acc[mi][ni][half*2+1]*s + t0, 0.f);
                *(float2*)&dst[pos] = make_float2(v0, v1);
            }
        }
    }
}

// ---------------- 64x64 2D FFT core, radix-4 ----------------
__device__ __forceinline__ void fft64_2d_r4(float* sr, float* si, int tid, int nt, float sign) {
#pragma unroll
    for (int s = 0; s < 3; s++) {
        int L = 1 << (2*s);
        int stp = 1024 >> (2*s);
        __syncthreads();
        for (int t = tid; t < 1024; t += nt) {
            int row = t >> 4, q = t & 15;
            int j = q & (L-1);
            int grp = q >> (2*s);
            int base = row*65 + grp*(L<<2) + j;
            float2 w1 = g_twid[j*stp];
            float2 w2 = g_twid[2*j*stp];
            float2 w3 = g_twid[3*j*stp];
            float w1i = sign*w1.y, w2i = sign*w2.y, w3i = sign*w3.y;
            float ar = sr[base],       ai = si[base];
            float x1r = sr[base+L],    x1i = si[base+L];
            float x2r = sr[base+2*L],  x2i = si[base+2*L];
            float x3r = sr[base+3*L],  x3i = si[base+3*L];
            float br = x1r*w1.x - x1i*w1i, bi = x1r*w1i + x1i*w1.x;
            float cr = x2r*w2.x - x2i*w2i, ci = x2r*w2i + x2i*w2.x;
            float dr = x3r*w3.x - x3i*w3i, di = x3r*w3i + x3i*w3.x;
            float t0r = ar+cr, t0i = ai+ci;
            float t1r = ar-cr, t1i = ai-ci;
            float t2r = br+dr, t2i = bi+di;
            float t3r = br-dr, t3i = bi-di;
            sr[base]     = t0r+t2r;        si[base]     = t0i+t2i;
            sr[base+2*L] = t0r-t2r;        si[base+2*L] = t0i-t2i;
            sr[base+L]   = t1r + sign*t3i; si[base+L]   = t1i - sign*t3r;
            sr[base+3*L] = t1r - sign*t3i; si[base+3*L] = t1i + sign*t3r;
        }
    }
    __syncthreads();
    for (int e = tid; e < 4096; e += nt) {
        int r = e >> 6, cc = e & 63;
        int d4 = dig4_6(r);
        if (r < d4) {
            float a = sr[r*65+cc]; sr[r*65+cc] = sr[d4*65+cc]; sr[d4*65+cc] = a;
            float b = si[r*65+cc]; si[r*65+cc] = si[d4*65+cc]; si[d4*65+cc] = b;
        }
    }
#pragma unroll
    for (int s = 0; s < 3; s++) {
        int L = 1 << (2*s);
        int stp = 1024 >> (2*s);
        __syncthreads();
        for (int t = tid; t < 1024; t += nt) {
            int col = t & 63, q = t >> 6;
            int j = q & (L-1);
            int grp = q >> (2*s);
            int base = (grp*(L<<2) + j)*65 + col;
            int LL = L*65;
            float2 w1 = g_twid[j*stp];
            float2 w2 = g_twid[2*j*stp];
            float2 w3 = g_twid[3*j*stp];
            float w1i = sign*w1.y, w2i = sign*w2.y, w3i = sign*w3.y;
            float ar = sr[base],       ai = si[base];
            float x1r = sr[base+LL],   x1i = si[base+LL];
            float x2r = sr[base+2*LL], x2i = si[base+2*LL];
            float x3r = sr[base+3*LL], x3i = si[base+3*LL];
            float br = x1r*w1.x - x1i*w1i, bi = x1r*w1i + x1i*w1.x;
            float cr = x2r*w2.x - x2i*w2i, ci = x2r*w2i + x2i*w2.x;
            float dr = x3r*w3.x - x3i*w3i, di = x3r*w3i + x3i*w3.x;
            float t0r = ar+cr, t0i = ai+ci;
            float t1r = ar-cr, t1i = ai-ci;
            float t2r = br+dr, t2i = bi+di;
            float t3r = br-dr, t3i = bi-di;
            sr[base]      = t0r+t2r;        si[base]      = t0i+t2i;
            sr[base+2*LL] = t0r-t2r;        si[base+2*LL] = t0i-t2i;
            sr[base+LL]   = t1r + sign*t3i; si[base+LL]   = t1i - sign*t3r;
            sr[base+3*LL] = t1r - sign*t3i; si[base+3*LL] = t1i + sign*t3r;
        }
    }
    __syncthreads();
}

__global__ void fft2_fwd_kernel() {
    __shared__ float sr[64*65], si[64*65];
    int bc = blockIdx.x;
    int tid = threadIdx.x;
    const float* src = g_y + (size_t)bc*HW_;
    for (int e = tid; e < 4096; e += 512) {
        int r = e >> 6, w = e & 63;
        sr[r*65 + dig4_6(w)] = src[e];
        si[r*65 + dig4_6(w)] = 0.f;
    }
    fft64_2d_r4(sr, si, tid, 512, 1.f);
    float* dr = g_fre + (size_t)bc*HW_;
    float* di = g_fim + (size_t)bc*HW_;
    for (int e = tid; e < 4096; e += 512) {
        dr[e] = sr[(e>>6)*65 + (e&63)];
        di[e] = si[(e>>6)*65 + (e&63)];
    }
}

// ---------------- attention scores ----------------
__global__ void attn_gemm64_kernel() {
    __shared__ uint32_t gs[64][36];
    int bh = blockIdx.x, kq = blockIdx.y;
    int tid = threadIdx.x, lane = tid & 31, warp = tid >> 5;
    int wm = warp & 3, wn = warp >> 2;
    int g = lane >> 2, t = lane & 3;
    float acc[4][4];
#pragma unroll
    for (int i = 0; i < 4; i++)
#pragma unroll
        for (int q = 0; q < 4; q++) acc[i][q] = 0.f;
    const float* fr = g_fre + (size_t)bh*CPH_*HW_;
    const float* fi = g_fim + (size_t)bh*CPH_*HW_;
    int kbeg = kq*(HW_/KSPLIT), kend = kbeg + HW_/KSPLIT;
    for (int k0 = kbeg; k0 < kend; k0 += 32) {
        __syncthreads();
#pragma unroll
        for (int r = 0; r < 2; r++) {
            int e = tid + r*256;
            int row = e >> 3, kqq = e & 7;
            const float* src = (row < 32) ? (fr + (size_t)row*HW_) : (fi + (size_t)(row-32)*HW_);
            float4 v = *(const float4*)&src[k0 + kqq*4];
            uint4 u = make_uint4(f2tf(v.x), f2tf(v.y), f2tf(v.z), f2tf(v.w));
            *(uint4*)&gs[row][kqq*4] = u;
        }
        __syncthreads();
#pragma unroll
        for (int ks = 0; ks < 32; ks += 8) {
            int kr = ks + t;
            uint32_t a[4];
            a[0] = gs[wm*16+g][kr];
            a[1] = gs[wm*16+g+8][kr];
            a[2] = gs[wm*16+g][kr+4];
            a[3] = gs[wm*16+g+8][kr+4];
#pragma unroll
            for (int ni = 0; ni < 4; ni++) {
                int n0 = wn*32 + ni*8 + g;
                mma8(acc[ni], a, gs[n0][kr], gs[n0][kr+4]);
            }
        }
    }
    float* S = g_attnS + ((size_t)(kq*64 + bh))*4096;
#pragma unroll
    for (int ni = 0; ni < 4; ni++) {
        int d = wn*32 + ni*8 + 2*t;
        int c0 = wm*16 + g;
        *(float2*)&S[(size_t)c0*64 + d]     = make_float2(acc[ni][0], acc[ni][1]);
        *(float2*)&S[(size_t)(c0+8)*64 + d] = make_float2(acc[ni][2], acc[ni][3]);
    }
}

// ---------------- attn finalize ----------------
__global__ void attn_fin_kernel(const float* __restrict__ temp) {
    int bh = blockIdx.x;
    int head = bh & 7;
    int tid = threadIdx.x;
    __shared__ float Ss[4096];
    __shared__ float ar_[32*33], ai_[32*33];
    __shared__ float inv[32];
    for (int p = tid; p < 4096; p += 256) {
        float s = 0.f;
#pragma unroll
        for (int q = 0; q < KSPLIT; q++)
            s += g_attnS[((size_t)(q*64 + bh))*4096 + p];
        Ss[p] = s;
    }
    __syncthreads();
    if (tid < 32)
        inv[tid] = rsqrtf(fmaxf(Ss[tid*64 + tid] + Ss[(32+tid)*64 + 32+tid], 1e-24f));
    __syncthreads();
    float tmp = temp[head];
    for (int p = tid; p < 1024; p += 256) {
        int cc = p >> 5, dd = p & 31;
        float sre = Ss[cc*64 + dd] - Ss[(32+cc)*64 + (32+dd)];
        float sim = Ss[cc*64 + (32+dd)] + Ss[(32+cc)*64 + dd];
        float sc = inv[cc] * inv[dd] * tmp;
        ar_[cc*33+dd] = sre*sc;
        ai_[cc*33+dd] = sim*sc;
    }
    __syncthreads();
    int w = tid >> 5, lane = tid & 31;
    for (int r = w; r < 32; r += 8) {
        float vr = ar_[r*33+lane];
        float m = vr;
        for (int o = 16; o; o >>= 1) m = fmaxf(m, __shfl_xor_sync(0xffffffffu, m, o));
        float e = expf(vr - m); float s = e;
        for (int o = 16; o; o >>= 1) s += __shfl_xor_sync(0xffffffffu, s, o);
        ar_[r*33+lane] = e / s;
        float vi = ai_[r*33+lane];
        m = vi;
        for (int o = 16; o; o >>= 1) m = fmaxf(m, __shfl_xor_sync(0xffffffffu, m, o));
        e = expf(vi - m); s = e;
        for (int o = 16; o; o >>= 1) s += __shfl_xor_sync(0xffffffffu, s, o);
        ai_[r*33+lane] = e / s;
    }
    __syncthreads();
    for (int p = tid; p < 1024; p += 256) {
        int k = p >> 5, dd = p & 31;
        float accr = 0.f, acci = 0.f;
#pragma unroll
        for (int cc = 0; cc < 32; cc++) {
            float2 w2 = g_twid[((k*cc) & 31) * 128];
            float wr = w2.x, wi = -w2.y;
            float xr = ar_[cc*33+dd], xi = ai_[cc*33+dd];
            accr += wr*xr - wi*xi;
            acci += wr*xi + wi*xr;
        }
        g_attn2[(size_t)bh*1024 + p] = make_float2(accr*(1.f/32.f), acci*(1.f/32.f));
    }
}

// ---------------- attn apply ----------------
__global__ void attn_apply_kernel() {
    __shared__ float sfr[32][132], sfi[32][132];
    __shared__ float2 a2s[32][32];
    int nc = blockIdx.x, bh = blockIdx.y;
    int tid = threadIdx.x;
    for (int p = tid; p < 1024; p += 256)
        a2s[p>>5][p&31] = g_attn2[(size_t)bh*1024 + p];
    const float* fr = g_fre + (size_t)bh*CPH_*HW_ + nc*128;
    const float* fi = g_fim + (size_t)bh*CPH_*HW_ + nc*128;
    for (int e = tid; e < 1024; e += 256) {
        int d = e >> 5, j = e & 31;
        *(float4*)&sfr[d][j*4] = *(const float4*)&fr[(size_t)d*HW_ + j*4];
        *(float4*)&sfi[d][j*4] = *(const float4*)&fi[(size_t)d*HW_ + j*4];
    }
    __syncthreads();
    int tx = tid & 15, ty = tid >> 4;
    int k0 = ty*2, n0 = tx*8;
    float ar0[8], ai0[8], ar1[8], ai1[8];
#pragma unroll
    for (int j = 0; j < 8; j++) { ar0[j]=0.f; ai0[j]=0.f; ar1[j]=0.f; ai1[j]=0.f; }
#pragma unroll
    for (int d = 0; d < 32; d++) {
        float2 a0 = a2s[k0][d], a1 = a2s[k0+1][d];
        float4 f0 = *(float4*)&sfr[d][n0], f1 = *(float4*)&sfr[d][n0+4];
        float4 h0 = *(float4*)&sfi[d][n0], h1 = *(float4*)&sfi[d][n0+4];
        float frv[8] = {f0.x,f0.y,f0.z,f0.w,f1.x,f1.y,f1.z,f1.w};
        float fiv[8] = {h0.x,h0.y,h0.z,h0.w,h1.x,h1.y,h1.z,h1.w};
#pragma unroll
        for (int j = 0; j < 8; j++) {
            ar0[j] += a0.x*frv[j] - a0.y*fiv[j];
            ai0[j] += a0.x*fiv[j] + a0.y*frv[j];
            ar1[j] += a1.x*frv[j] - a1.y*fiv[j];
            ai1[j] += a1.x*fiv[j] + a1.y*frv[j];
        }
    }
    size_t base0 = ((size_t)(bh*32 + k0))*HW_ + nc*128 + n0;
    size_t base1 = base0 + HW_;
    *(float4*)&g_or[base0]   = make_float4(ar0[0],ar0[1],ar0[2],ar0[3]);
    *(float4*)&g_or[base0+4] = make_float4(ar0[4],ar0[5],ar0[6],ar0[7]);
    *(float4*)&g_oi[base0]   = make_float4(ai0[0],ai0[1],ai0[2],ai0[3]);
    *(float4*)&g_oi[base0+4] = make_float4(ai0[4],ai0[5],ai0[6],ai0[7]);
    *(float4*)&g_or[base1]   = make_float4(ar1[0],ar1[1],ar1[2],ar1[3]);
    *(float4*)&g_or[base1+4] = make_float4(ar1[4],ar1[5],ar1[6],ar1[7]);
    *(float4*)&g_oi[base1]   = make_float4(ai1[0],ai1[1],ai1[2],ai1[3]);
    *(float4*)&g_oi[base1+4] = make_float4(ai1[4],ai1[5],ai1[6],ai1[7]);
}

// ---------------- row ifft4096 radix-4 + abs + residual ----------------
#define SKW(i) ((i) + ((i) >> 7))
__global__ void ifft_row_kernel(const float* __restrict__ x) {
    __shared__ float sr[4128], si[4128];
    int gid = blockIdx.x;
    int b = gid >> 8, cg = gid & 255;
    int tid = threadIdx.x;
    const float* pr = g_or + (size_t)gid*HW_;
    const float* pi = g_oi + (size_t)gid*HW_;
    for (int nn = tid; nn < 4096; nn += 512) {
        int d = SKW(dig4_12(nn));
        sr[d] = pr[nn];
        si[d] = pi[nn];
    }
#pragma unroll
    for (int s = 0; s < 6; s++) {
        int L = 1 << (2*s);
        int stp = 1024 >> (2*s);
        __syncthreads();
        for (int t = tid; t < 1024; t += 512) {
            int j = t & (L-1);
            int grp = t >> (2*s);
            int base = grp*(L<<2) + j;
            int i0 = SKW(base), i1 = SKW(base+L), i2 = SKW(base+2*L), i3 = SKW(base+3*L);
            float2 w1 = g_twid[j*stp];
            float2 w2 = g_twid[2*j*stp];
            float2 w3 = g_twid[3*j*stp];
            float ar = sr[i0],  ai = si[i0];
            float x1r = sr[i1], x1i = si[i1];
            float x2r = sr[i2], x2i = si[i2];
            float x3r = sr[i3], x3i = si[i3];
            float br = x1r*w1.x + x1i*w1.y, bi = -x1r*w1.y + x1i*w1.x;
            float cr = x2r*w2.x + x2i*w2.y, ci = -x2r*w2.y + x2i*w2.x;
            float dr = x3r*w3.x + x3i*w3.y, di = -x3r*w3.y + x3i*w3.x;
            float t0r = ar+cr, t0i = ai+ci;
            float t1r = ar-cr, t1i = ai-ci;
            float t2r = br+dr, t2i = bi+di;
            float t3r = br-dr, t3i = bi-di;
            sr[i0] = t0r+t2r;  si[i0] = t0i+t2i;
            sr[i2] = t0r-t2r;  si[i2] = t0i-t2i;
            sr[i1] = t1r - t3i; si[i1] = t1i + t3r;
            sr[i3] = t1r + t3i; si[i3] = t1i - t3r;
        }
    }
    __syncthreads();
    for (int nn = tid; nn < 4096; nn += 512) {
        float re = sr[SKW(nn)], im = si[SKW(nn)];
        float v = sqrtf(re*re + im*im) * (1.f/4096.f)
                + x[((size_t)b*HW_ + nn)*C_ + cg];
        g_out2[((size_t)(b*512) + cg)*HW_ + nn] = v;
    }
}

// ---------------- gating MLP stage 1 ----------------
__global__ void g1_kernel(const float* __restrict__ w1w, const float* __restrict__ w1b,
                          const float* __restrict__ bg, const float* __restrict__ bb,
                          const float* __restrict__ bm, const float* __restrict__ bv) {
    __shared__ float sw[HID_*DD_];
    __shared__ float sa[HID_], st[HID_];
    int b = blockIdx.y;
    int tid = threadIdx.x;
    int n = blockIdx.x*256 + tid;
    for (int e = tid; e < HID_*DD_; e += 256) sw[e] = w1w[e];
    if (tid < HID_) {
        float s = bg[tid] * rsqrtf(bv[tid] + 1e-5f);
        sa[tid] = s;
        st[tid] = w1b[tid]*s + bb[tid] - bm[tid]*s;
    }
    __syncthreads();
    float acc[HID_];
#pragma unroll
    for (int o = 0; o < HID_; o++) acc[o] = 0.f;
    const float* fr = g_fre + (size_t)b*DD_*HW_ + n;
    for (int c = 0; c < DD_; c++) {
        float v = fr[(size_t)c*HW_];
#pragma unroll
        for (int o = 0; o < HID_; o++) acc[o] += v * sw[o*DD_ + c];
    }
#pragma unroll
    for (int o = 0; o < HID_; o++)
        g_g1[((size_t)(b*HID_ + o))*HW_ + n] = fmaxf(acc[o]*sa[o] + st[o], 0.f);
}

// ---------------- fused gate + ifft2 + abs + residual ----------------
__global__ void ifft2_gate_kernel(const float* __restrict__ x,
                                  const float* __restrict__ w2w,
                                  const float* __restrict__ w2b) {
    __shared__ float sr[64*65], si[64*65];
    __shared__ float w2s[HID_];
    int bc = blockIdx.x;
    int b = bc >> 8, c = bc & 255;
    int tid = threadIdx.x;
    if (tid < HID_) w2s[tid] = w2w[c*HID_ + tid];
    __syncthreads();
    float bias = w2b[c];
    float acc[8];
#pragma unroll
    for (int j = 0; j < 8; j++) acc[j] = bias;
    const float* g1p = g_g1 + (size_t)b*HID_*HW_;
#pragma unroll
    for (int o = 0; o < HID_; o++) {
        float w = w2s[o];
        const float* row = g1p + (size_t)o*HW_;
#pragma unroll
        for (int j = 0; j < 8; j++) acc[j] += w * row[tid + j*512];
    }
    const float* fre = g_fre + (size_t)bc*HW_;
    const float* fim = g_fim + (size_t)bc*HW_;
#pragma unroll
    for (int j = 0; j < 8; j++) {
        int e = tid + j*512;
        float gt = 1.f / (1.f + expf(-acc[j]));
        int r = e >> 6, w = e & 63;
        int dw = dig4_6(w);
        sr[r*65 + dw] = gt * fre[e];
        si[r*65 + dw] = gt * fim[e];
    }
    fft64_2d_r4(sr, si, tid, 512, -1.f);
    for (int e = tid; e < 4096; e += 512) {
        float re = sr[(e>>6)*65 + (e&63)], im = si[(e>>6)*65 + (e&63)];
        float v = sqrtf(re*re + im*im) * (1.f/4096.f)
                + x[((size_t)b*HW_ + e)*C_ + (256 + c)];
        g_out2[((size_t)(b*512 + 256 + c))*HW_ + e] = v;
    }
}

// ---------------- final projection via tf32 mma, KC=32 (R6 form) ----------------
__global__ void proj_mma_kernel(const float* __restrict__ pw, const float* __restrict__ pb,
                                float* __restrict__ out) {
    __shared__ uint32_t xs[128][36];
    __shared__ uint32_t ws[128][36];
    int b = blockIdx.z, nt = blockIdx.y, ot = blockIdx.x;
    int tid = threadIdx.x, lane = tid & 31, warp = tid >> 5;
    int wm = warp & 3, wn = warp >> 2;
    int g = lane >> 2, t = lane & 3;
    float acc[2][8][4];
#pragma unroll
    for (int i = 0; i < 2; i++)
#pragma unroll
        for (int j = 0; j < 8; j++)
#pragma unroll
            for (int q = 0; q < 4; q++) acc[i][j][q] = 0.f;

    int n0g = nt*128, o0g = ot*128;
    for (int kc = 0; kc < 512; kc += 32) {
        __syncthreads();
#pragma unroll
        for (int r = 0; r < 4; r++) {
            int e = tid + r*256;
            int k = e >> 5, n4 = e & 31;
            float4 v = *(const float4*)&g_out2[((size_t)(b*512 + kc + k))*HW_ + n0g + n4*4];
            xs[n4*4+0][k] = f2tf(v.x);
            xs[n4*4+1][k] = f2tf(v.y);
            xs[n4*4+2][k] = f2tf(v.z);
            xs[n4*4+3][k] = f2tf(v.w);
        }
#pragma unroll
        for (int r = 0; r < 4; r++) {
            int e = tid + r*256;
            int o = e >> 3, ch = e & 7;
            float4 v = *(const float4*)&pw[(size_t)(o0g + o)*512 + kc + ch*4];
            uint4 u = make_uint4(f2tf(v.x), f2tf(v.y), f2tf(v.z), f2tf(v.w));
            *(uint4*)&ws[o][ch*4] = u;
        }
        __syncthreads();
#pragma unroll
        for (int ks = 0; ks < 32; ks += 8) {
            int kr = ks + t;
            uint32_t a[2][4];
#pragma unroll
            for (int mi = 0; mi < 2; mi++) {
                int m0 = wm*32 + mi*16 + g;
                a[mi][0] = xs[m0][kr];
                a[mi][1] = xs[m0+8][kr];
                a[mi][2] = xs[m0][kr+4];
                a[mi][3] = xs[m0+8][kr+4];
            }
#pragma unroll
            for (int ni = 0; ni < 8; ni++) {
                int n0 = wn*64 + ni*8 + g;
                uint32_t b0 = ws[n0][kr];
                uint32_t b1 = ws[n0][kr+4];
                mma8(acc[0][ni], a[0], b0, b1);
                mma8(acc[1][ni], a[1], b0, b1);
            }
        }
    }
#pragma unroll
    for (int mi = 0; mi < 2; mi++) {
#pragma unroll
        for (int half = 0; half < 2; half++) {
            int n = n0g + wm*32 + mi*16 + g + half*8;
#pragma unroll
            for (int ni = 0; ni < 8; ni++) {
                int o = o0g + wn*64 + ni*8 + 2*t;
                float2 bias = *(const float2*)&pb[o];
                float v0 = acc[mi][ni][half*2+0] + bias.x;
                float v1 = acc[mi][ni][half*2+1] + bias.y;
                *(float2*)&out[((size_t)b*HW_ + n)*C_ + o] = make_float2(v0, v1);
            }
        }
    }
}

// ---------------- launch ----------------
extern "C" void kernel_launch(void* const* d_in, const int* in_sizes, int n_in,
                              void* d_out, int out_size) {
    const float* x       = (const float*)d_in[0];
    const float* conv2_w = (const float*)d_in[1];
    const float* conv2_b = (const float*)d_in[2];
    const float* bn2_g   = (const float*)d_in[3];
    const float* bn2_b   = (const float*)d_in[4];
    const float* bn2_m   = (const float*)d_in[5];
    const float* bn2_v   = (const float*)d_in[6];
    const float* temp    = (const float*)d_in[7];
    const float* w1_w    = (const float*)d_in[8];
    const float* w1_b    = (const float*)d_in[9];
    const float* bnw_g   = (const float*)d_in[10];
    const float* bnw_b   = (const float*)d_in[11];
    const float* bnw_m   = (const float*)d_in[12];
    const float* bnw_v   = (const float*)d_in[13];
    const float* w2_w    = (const float*)d_in[14];
    const float* w2_b    = (const float*)d_in[15];
    const float* proj_w  = (const float*)d_in[16];
    const float* proj_b  = (const float*)d_in[17];
    float* out = (float*)d_out;

    prep_kernel<<<1024, 256>>>(conv2_w);
    conv_mma_kernel<<<dim3(2, 32, 8), 128>>>(x, conv2_b, bn2_g, bn2_b, bn2_m, bn2_v);
    fft2_fwd_kernel<<<2048, 512>>>();
    attn_gemm64_kernel<<<dim3(64, KSPLIT), 256>>>();
    attn_fin_kernel<<<64, 256>>>(temp);
    attn_apply_kernel<<<dim3(32, 64), 256>>>();
    ifft_row_kernel<<<2048, 512>>>(x);
    g1_kernel<<<dim3(16, 8), 256>>>(w1_w, w1_b, bnw_g, bnw_b, bnw_m, bnw_v);
    ifft2_gate_kernel<<<2048, 512>>>(x, w2_w, w2_b);
    proj_mma_kernel<<<dim3(4, 32, 8), 256>>>(proj_w, proj_b, out);
}

// round 12
// speedup vs baseline: 1.1819x; 1.0549x over previous
#include <cuda_runtime.h>
#include <math.h>
#include <stdint.h>

#define B_  8
#define C_  512
#define DD_ 256
#define HW_ 4096
#define HEADS_ 8
#define CPH_ 32
#define HID_ 16
#define KSPLIT 8

// ---------------- scratch ----------------
__device__ __align__(16) uint32_t g_wt[9*256*512];   // conv weights tf32 [tap][co][cin]
__device__ float2 g_twid[4096];
__device__ float  g_y   [(size_t)B_*DD_*HW_];
__device__ float  g_fre [(size_t)B_*DD_*HW_];
__device__ float  g_fim [(size_t)B_*DD_*HW_];
__device__ float  g_g1  [(size_t)B_*HID_*HW_];
__device__ float  g_attnS[KSPLIT*64*64*64];
__device__ float2 g_attn2[64*1024];
__device__ float  g_or  [(size_t)B_*DD_*HW_];
__device__ float  g_oi  [(size_t)B_*DD_*HW_];
__device__ float  g_out2[(size_t)B_*C_*HW_];

// ---------------- tf32 helpers ----------------
__device__ __forceinline__ uint32_t f2tf(float f) {
    uint32_t u;
    asm("cvt.rna.tf32.f32 %0, %1;" : "=r"(u) : "f"(f));
    return u;
}
__device__ __forceinline__ void mma8(float c[4], const uint32_t a[4], uint32_t b0, uint32_t b1) {
    asm volatile("mma.sync.aligned.m16n8k8.row.col.f32.tf32.tf32.f32 "
        "{%0,%1,%2,%3}, {%4,%5,%6,%7}, {%8,%9}, {%0,%1,%2,%3};"
        : "+f"(c[0]), "+f"(c[1]), "+f"(c[2]), "+f"(c[3])
        : "r"(a[0]), "r"(a[1]), "r"(a[2]), "r"(a[3]), "r"(b0), "r"(b1));
}
__device__ __forceinline__ int dig4_6(int x) {
    int b = __brev(x) >> 26;
    return ((b & 0x15) << 1) | ((b >> 1) & 0x15);
}
__device__ __forceinline__ int dig4_12(int x) {
    int b = __brev(x) >> 20;
    return ((b & 0x555) << 1) | ((b >> 1) & 0x555);
}

// ---------------- prep ----------------
__global__ void prep_kernel(const float* __restrict__ cw) {
    int tid = blockIdx.x*blockDim.x + threadIdx.x;
    int stride = gridDim.x*blockDim.x;
    if (tid < 4096) {
        float s, c;
        sincosf(-6.28318530717958647692f * (float)tid / 4096.f, &s, &c);
        g_twid[tid] = make_float2(c, s);
    }
    for (int e = tid; e < 9*256*512; e += stride) {
        int tap = e / (256*512);
        int rem = e - tap*256*512;
        int co = rem >> 9;
        int cin = rem & 511;
        g_wt[e] = f2tf(cw[(co*512 + cin)*9 + tap]);
    }
}

// ---------------- conv via tf32 mma: 128co x 128pos tiles, 4 warps of 64x64 ------
__global__ void conv_mma_kernel(const float* __restrict__ x, const float* __restrict__ cb,
                                const float* __restrict__ bg, const float* __restrict__ bb,
                                const float* __restrict__ bm, const float* __restrict__ bv) {
    __shared__ uint32_t xs[128][36];
    __shared__ uint32_t ws[128][36];
    int b = blockIdx.z, pt = blockIdx.y, ct = blockIdx.x;
    int tid = threadIdx.x, lane = tid & 31, warp = tid >> 5;   // 4 warps
    int wm = warp & 1, wn = warp >> 1;                         // 2 x 2 of 64x64
    int g = lane >> 2, t = lane & 3;
    float acc[4][8][4];
#pragma unroll
    for (int i = 0; i < 4; i++)
#pragma unroll
        for (int j = 0; j < 8; j++)
#pragma unroll
            for (int q = 0; q < 4; q++) acc[i][j][q] = 0.f;

    int pos0 = pt*128;
    for (int tap = 0; tap < 9; tap++) {
        int dh = 3*((tap/3) - 1), dw = 3*((tap%3) - 1);
        const uint32_t* wtp = g_wt + ((size_t)tap*256 + ct*128)*512;
        for (int kc = 0; kc < 512; kc += 32) {
            __syncthreads();
#pragma unroll
            for (int r = 0; r < 8; r++) {
                int e = tid + r*128;
                int pos = e >> 3, ch = e & 7;
                int gp = pos0 + pos;
                int ih = (gp >> 6) + dh, iw = (gp & 63) + dw;
                uint4 u = make_uint4(0u, 0u, 0u, 0u);
                if ((unsigned)ih < 64u && (unsigned)iw < 64u)
                    u = *(const uint4*)&x[((size_t)(b*HW_) + ih*64 + iw)*C_ + kc + ch*4];
                *(uint4*)&xs[pos][ch*4] = u;
            }
#pragma unroll
            for (int r = 0; r < 8; r++) {
                int e = tid + r*128;
                int co = e >> 3, ch = e & 7;
                *(uint4*)&ws[co][ch*4] = *(const uint4*)&wtp[(size_t)co*512 + kc + ch*4];
            }
            __syncthreads();
#pragma unroll
            for (int ks = 0; ks < 32; ks += 8) {
                int kr = ks + t;
                uint32_t a[4][4];
#pragma unroll
                for (int mi = 0; mi < 4; mi++) {
                    int m0 = wm*64 + mi*16 + g;
                    a[mi][0] = ws[m0][kr];
                    a[mi][1] = ws[m0+8][kr];
                    a[mi][2] = ws[m0][kr+4];
                    a[mi][3] = ws[m0+8][kr+4];
                }
#pragma unroll
                for (int ni = 0; ni < 8; ni++) {
                    int n0 = wn*64 + ni*8 + g;
                    uint32_t b0 = xs[n0][kr];
                    uint32_t b1 = xs[n0][kr+4];
                    mma8(acc[0][ni], a[0], b0, b1);
                    mma8(acc[1][ni], a[1], b0, b1);
                    mma8(acc[2][ni], a[2], b0, b1);
                    mma8(acc[3][ni], a[3], b0, b1);
                }
            }
        }
    }
#pragma unroll
    for (int mi = 0; mi < 4; mi++) {
#pragma unroll
        for (int half = 0; half < 2; half++) {
            int o = ct*128 + wm*64 + mi*16 + g + half*8;
            float s = bg[o] * rsqrtf(bv[o] + 1e-5f);
            float t0 = cb[o]*s + bb[o] - bm[o]*s;
            float* dst = g_y + ((size_t)(b*DD_ + o))*HW_;
#pragma unroll
            for (int ni = 0; ni < 8; ni++) {
                int pos = pos0 + wn*64 + ni*8 + 2*t;
                float v0 = fmaxf(acc[mi][ni][half*2+0]*s + t0, 0.f);
                float v1 = fmaxf(acc[mi][ni][half*2+1]*s + t0, 0.f);
                *(float2*)&dst[pos] = make_float2(v0, v1);
            }
        }
    }
}

// ---------------- 64x64 2D FFT core, radix-4 ----------------
__device__ __forceinline__ void fft64_2d_r4(float* sr, float* si, int tid, int nt, float sign) {
#pragma unroll
    for (int s = 0; s < 3; s++) {
        int L = 1 << (2*s);
        int stp = 1024 >> (2*s);
        __syncthreads();
        for (int t = tid; t < 1024; t += nt) {
            int row = t >> 4, q = t & 15;
            int j = q & (L-1);
            int grp = q >> (2*s);
            int base = row*65 + grp*(L<<2) + j;
            float2 w1 = g_twid[j*stp];
            float2 w2 = g_twid[2*j*stp];
            float2 w3 = g_twid[3*j*stp];
            float w1i = sign*w1.y, w2i = sign*w2.y, w3i = sign*w3.y;
            float ar = sr[base],       ai = si[base];
            float x1r = sr[base+L],    x1i = si[base+L];
            float x2r = sr[base+2*L],  x2i = si[base+2*L];
            float x3r = sr[base+3*L],  x3i = si[base+3*L];
            float br = x1r*w1.x - x1i*w1i, bi = x1r*w1i + x1i*w1.x;
            float cr = x2r*w2.x - x2i*w2i, ci = x2r*w2i + x2i*w2.x;
            float dr = x3r*w3.x - x3i*w3i, di = x3r*w3i + x3i*w3.x;
            float t0r = ar+cr, t0i = ai+ci;
            float t1r = ar-cr, t1i = ai-ci;
            float t2r = br+dr, t2i = bi+di;
            float t3r = br-dr, t3i = bi-di;
            sr[base]     = t0r+t2r;        si[base]     = t0i+t2i;
            sr[base+2*L] = t0r-t2r;        si[base+2*L] = t0i-t2i;
            sr[base+L]   = t1r + sign*t3i; si[base+L]   = t1i - sign*t3r;
            sr[base+3*L] = t1r - sign*t3i; si[base+3*L] = t1i + sign*t3r;
        }
    }
    __syncthreads();
    for (int e = tid; e < 4096; e += nt) {
        int r = e >> 6, cc = e & 63;
        int d4 = dig4_6(r);
        if (r < d4) {
            float a = sr[r*65+cc]; sr[r*65+cc] = sr[d4*65+cc]; sr[d4*65+cc] = a;
            float b = si[r*65+cc]; si[r*65+cc] = si[d4*65+cc]; si[d4*65+cc] = b;
        }
    }
#pragma unroll
    for (int s = 0; s < 3; s++) {
        int L = 1 << (2*s);
        int stp = 1024 >> (2*s);
        __syncthreads();
        for (int t = tid; t < 1024; t += nt) {
            int col = t & 63, q = t >> 6;
            int j = q & (L-1);
            int grp = q >> (2*s);
            int base = (grp*(L<<2) + j)*65 + col;
            int LL = L*65;
            float2 w1 = g_twid[j*stp];
            float2 w2 = g_twid[2*j*stp];
            float2 w3 = g_twid[3*j*stp];
            float w1i = sign*w1.y, w2i = sign*w2.y, w3i = sign*w3.y;
            float ar = sr[base],       ai = si[base];
            float x1r = sr[base+LL],   x1i = si[base+LL];
            float x2r = sr[base+2*LL], x2i = si[base+2*LL];
            float x3r = sr[base+3*LL], x3i = si[base+3*LL];
            float br = x1r*w1.x - x1i*w1i, bi = x1r*w1i + x1i*w1.x;
            float cr = x2r*w2.x - x2i*w2i, ci = x2r*w2i + x2i*w2.x;
            float dr = x3r*w3.x - x3i*w3i, di = x3r*w3i + x3i*w3.x;
            float t0r = ar+cr, t0i = ai+ci;
            float t1r = ar-cr, t1i = ai-ci;
            float t2r = br+dr, t2i = bi+di;
            float t3r = br-dr, t3i = bi-di;
            sr[base]      = t0r+t2r;        si[base]      = t0i+t2i;
            sr[base+2*LL] = t0r-t2r;        si[base+2*LL] = t0i-t2i;
            sr[base+LL]   = t1r + sign*t3i; si[base+LL]   = t1i - sign*t3r;
            sr[base+3*LL] = t1r - sign*t3i; si[base+3*LL] = t1i + sign*t3r;
        }
    }
    __syncthreads();
}

// forward fft2 of real conv output, TWO channels per block via packing
// grid 1024: b*128 + cpair
__global__ void fft2_fwd_kernel() {
    __shared__ float sr[64*65], si[64*65];
    int bp = blockIdx.x;
    int b = bp >> 7, cp = bp & 127;
    int c0 = cp*2;
    int tid = threadIdx.x;
    const float* s0 = g_y + ((size_t)(b*DD_ + c0))*HW_;
    const float* s1 = s0 + HW_;
    for (int e = tid; e < 4096; e += 512) {
        int r = e >> 6, w = e & 63;
        int dw = dig4_6(w);
        sr[r*65 + dw] = s0[e];
        si[r*65 + dw] = s1[e];
    }
    fft64_2d_r4(sr, si, tid, 512, 1.f);
    float* f0r = g_fre + ((size_t)(b*DD_ + c0))*HW_;
    float* f0i = g_fim + ((size_t)(b*DD_ + c0))*HW_;
    float* f1r = f0r + HW_;
    float* f1i = f0i + HW_;
    for (int e = tid; e < 4096; e += 512) {
        int r = e >> 6, w = e & 63;
        int rn = (64 - r) & 63, wn = (64 - w) & 63;
        float Zr  = sr[r*65 + w],   Zi  = si[r*65 + w];
        float Z2r = sr[rn*65 + wn], Z2i = si[rn*65 + wn];
        f0r[e] = 0.5f*(Zr + Z2r);
        f0i[e] = 0.5f*(Zi - Z2i);
        f1r[e] = 0.5f*(Zi + Z2i);
        f1i[e] = 0.5f*(Z2r - Zr);
    }
}

// ---------------- attention scores ----------------
__global__ void attn_gemm64_kernel() {
    __shared__ uint32_t gs[64][36];
    int bh = blockIdx.x, kq = blockIdx.y;
    int tid = threadIdx.x, lane = tid & 31, warp = tid >> 5;
    int wm = warp & 3, wn = warp >> 2;
    int g = lane >> 2, t = lane & 3;
    float acc[4][4];
#pragma unroll
    for (int i = 0; i < 4; i++)
#pragma unroll
        for (int q = 0; q < 4; q++) acc[i][q] = 0.f;
    const float* fr = g_fre + (size_t)bh*CPH_*HW_;
    const float* fi = g_fim + (size_t)bh*CPH_*HW_;
    int kbeg = kq*(HW_/KSPLIT), kend = kbeg + HW_/KSPLIT;
    for (int k0 = kbeg; k0 < kend; k0 += 32) {
        __syncthreads();
#pragma unroll
        for (int r = 0; r < 2; r++) {
            int e = tid + r*256;
            int row = e >> 3, kqq = e & 7;
            const float* src = (row < 32) ? (fr + (size_t)row*HW_) : (fi + (size_t)(row-32)*HW_);
            float4 v = *(const float4*)&src[k0 + kqq*4];
            uint4 u = make_uint4(f2tf(v.x), f2tf(v.y), f2tf(v.z), f2tf(v.w));
            *(uint4*)&gs[row][kqq*4] = u;
        }
        __syncthreads();
#pragma unroll
        for (int ks = 0; ks < 32; ks += 8) {
            int kr = ks + t;
            uint32_t a[4];
            a[0] = gs[wm*16+g][kr];
            a[1] = gs[wm*16+g+8][kr];
            a[2] = gs[wm*16+g][kr+4];
            a[3] = gs[wm*16+g+8][kr+4];
#pragma unroll
            for (int ni = 0; ni < 4; ni++) {
                int n0 = wn*32 + ni*8 + g;
                mma8(acc[ni], a, gs[n0][kr], gs[n0][kr+4]);
            }
        }
    }
    float* S = g_attnS + ((size_t)(kq*64 + bh))*4096;
#pragma unroll
    for (int ni = 0; ni < 4; ni++) {
        int d = wn*32 + ni*8 + 2*t;
        int c0 = wm*16 + g;
        *(float2*)&S[(size_t)c0*64 + d]     = make_float2(acc[ni][0], acc[ni][1]);
        *(float2*)&S[(size_t)(c0+8)*64 + d] = make_float2(acc[ni][2], acc[ni][3]);
    }
}

// ---------------- attn finalize ----------------
__global__ void attn_fin_kernel(const float* __restrict__ temp) {
    int bh = blockIdx.x;
    int head = bh & 7;
    int tid = threadIdx.x;
    __shared__ float Ss[4096];
    __shared__ float ar_[32*33], ai_[32*33];
    __shared__ float inv[32];
    for (int p = tid; p < 4096; p += 256) {
        float s = 0.f;
#pragma unroll
        for (int q = 0; q < KSPLIT; q++)
            s += g_attnS[((size_t)(q*64 + bh))*4096 + p];
        Ss[p] = s;
    }
    __syncthreads();
    if (tid < 32)
        inv[tid] = rsqrtf(fmaxf(Ss[tid*64 + tid] + Ss[(32+tid)*64 + 32+tid], 1e-24f));
    __syncthreads();
    float tmp = temp[head];
    for (int p = tid; p < 1024; p += 256) {
        int cc = p >> 5, dd = p & 31;
        float sre = Ss[cc*64 + dd] - Ss[(32+cc)*64 + (32+dd)];
        float sim = Ss[cc*64 + (32+dd)] + Ss[(32+cc)*64 + dd];
        float sc = inv[cc] * inv[dd] * tmp;
        ar_[cc*33+dd] = sre*sc;
        ai_[cc*33+dd] = sim*sc;
    }
    __syncthreads();
    int w = tid >> 5, lane = tid & 31;
    for (int r = w; r < 32; r += 8) {
        float vr = ar_[r*33+lane];
        float m = vr;
        for (int o = 16; o; o >>= 1) m = fmaxf(m, __shfl_xor_sync(0xffffffffu, m, o));
        float e = expf(vr - m); float s = e;
        for (int o = 16; o; o >>= 1) s += __shfl_xor_sync(0xffffffffu, s, o);
        ar_[r*33+lane] = e / s;
        float vi = ai_[r*33+lane];
        m = vi;
        for (int o = 16; o; o >>= 1) m = fmaxf(m, __shfl_xor_sync(0xffffffffu, m, o));
        e = expf(vi - m); s = e;
        for (int o = 16; o; o >>= 1) s += __shfl_xor_sync(0xffffffffu, s, o);
        ai_[r*33+lane] = e / s;
    }
    __syncthreads();
    for (int p = tid; p < 1024; p += 256) {
        int k = p >> 5, dd = p & 31;
        float accr = 0.f, acci = 0.f;
#pragma unroll
        for (int cc = 0; cc < 32; cc++) {
            float2 w2 = g_twid[((k*cc) & 31) * 128];
            float wr = w2.x, wi = -w2.y;
            float xr = ar_[cc*33+dd], xi = ai_[cc*33+dd];
            accr += wr*xr - wi*xi;
            acci += wr*xi + wi*xr;
        }
        g_attn2[(size_t)bh*1024 + p] = make_float2(accr*(1.f/32.f), acci*(1.f/32.f));
    }
}

// ---------------- attn apply ----------------
__global__ void attn_apply_kernel() {
    __shared__ float sfr[32][132], sfi[32][132];
    __shared__ float2 a2s[32][32];
    int nc = blockIdx.x, bh = blockIdx.y;
    int tid = threadIdx.x;
    for (int p = tid; p < 1024; p += 256)
        a2s[p>>5][p&31] = g_attn2[(size_t)bh*1024 + p];
    const float* fr = g_fre + (size_t)bh*CPH_*HW_ + nc*128;
    const float* fi = g_fim + (size_t)bh*CPH_*HW_ + nc*128;
    for (int e = tid; e < 1024; e += 256) {
        int d = e >> 5, j = e & 31;
        *(float4*)&sfr[d][j*4] = *(const float4*)&fr[(size_t)d*HW_ + j*4];
        *(float4*)&sfi[d][j*4] = *(const float4*)&fi[(size_t)d*HW_ + j*4];
    }
    __syncthreads();
    int tx = tid & 15, ty = tid >> 4;
    int k0 = ty*2, n0 = tx*8;
    float ar0[8], ai0[8], ar1[8], ai1[8];
#pragma unroll
    for (int j = 0; j < 8; j++) { ar0[j]=0.f; ai0[j]=0.f; ar1[j]=0.f; ai1[j]=0.f; }
#pragma unroll
    for (int d = 0; d < 32; d++) {
        float2 a0 = a2s[k0][d], a1 = a2s[k0+1][d];
        float4 f0 = *(float4*)&sfr[d][n0], f1 = *(float4*)&sfr[d][n0+4];
        float4 h0 = *(float4*)&sfi[d][n0], h1 = *(float4*)&sfi[d][n0+4];
        float frv[8] = {f0.x,f0.y,f0.z,f0.w,f1.x,f1.y,f1.z,f1.w};
        float fiv[8] = {h0.x,h0.y,h0.z,h0.w,h1.x,h1.y,h1.z,h1.w};
#pragma unroll
        for (int j = 0; j < 8; j++) {
            ar0[j] += a0.x*frv[j] - a0.y*fiv[j];
            ai0[j] += a0.x*fiv[j] + a0.y*frv[j];
            ar1[j] += a1.x*frv[j] - a1.y*fiv[j];
            ai1[j] += a1.x*fiv[j] + a1.y*frv[j];
        }
    }
    size_t base0 = ((size_t)(bh*32 + k0))*HW_ + nc*128 + n0;
    size_t base1 = base0 + HW_;
    *(float4*)&g_or[base0]   = make_float4(ar0[0],ar0[1],ar0[2],ar0[3]);
    *(float4*)&g_or[base0+4] = make_float4(ar0[4],ar0[5],ar0[6],ar0[7]);
    *(float4*)&g_oi[base0]   = make_float4(ai0[0],ai0[1],ai0[2],ai0[3]);
    *(float4*)&g_oi[base0+4] = make_float4(ai0[4],ai0[5],ai0[6],ai0[7]);
    *(float4*)&g_or[base1]   = make_float4(ar1[0],ar1[1],ar1[2],ar1[3]);
    *(float4*)&g_or[base1+4] = make_float4(ar1[4],ar1[5],ar1[6],ar1[7]);
    *(float4*)&g_oi[base1]   = make_float4(ai1[0],ai1[1],ai1[2],ai1[3]);
    *(float4*)&g_oi[base1+4] = make_float4(ai1[4],ai1[5],ai1[6],ai1[7]);
}

// ---------------- row ifft4096 radix-4 + abs + residual ----------------
#define SKW(i) ((i) + ((i) >> 7))
__global__ void ifft_row_kernel(const float* __restrict__ x) {
    __shared__ float sr[4128], si[4128];
    int gid = blockIdx.x;
    int b = gid >> 8, cg = gid & 255;
    int tid = threadIdx.x;
    const float* pr = g_or + (size_t)gid*HW_;
    const float* pi = g_oi + (size_t)gid*HW_;
    for (int nn = tid; nn < 4096; nn += 512) {
        int d = SKW(dig4_12(nn));
        sr[d] = pr[nn];
        si[d] = pi[nn];
    }
#pragma unroll
    for (int s = 0; s < 6; s++) {
        int L = 1 << (2*s);
        int stp = 1024 >> (2*s);
        __syncthreads();
        for (int t = tid; t < 1024; t += 512) {
            int j = t & (L-1);
            int grp = t >> (2*s);
            int base = grp*(L<<2) + j;
            int i0 = SKW(base), i1 = SKW(base+L), i2 = SKW(base+2*L), i3 = SKW(base+3*L);
            float2 w1 = g_twid[j*stp];
            float2 w2 = g_twid[2*j*stp];
            float2 w3 = g_twid[3*j*stp];
            float ar = sr[i0],  ai = si[i0];
            float x1r = sr[i1], x1i = si[i1];
            float x2r = sr[i2], x2i = si[i2];
            float x3r = sr[i3], x3i = si[i3];
            float br = x1r*w1.x + x1i*w1.y, bi = -x1r*w1.y + x1i*w1.x;
            float cr = x2r*w2.x + x2i*w2.y, ci = -x2r*w2.y + x2i*w2.x;
            float dr = x3r*w3.x + x3i*w3.y, di = -x3r*w3.y + x3i*w3.x;
            float t0r = ar+cr, t0i = ai+ci;
            float t1r = ar-cr, t1i = ai-ci;
            float t2r = br+dr, t2i = bi+di;
            float t3r = br-dr, t3i = bi-di;
            sr[i0] = t0r+t2r;  si[i0] = t0i+t2i;
            sr[i2] = t0r-t2r;  si[i2] = t0i-t2i;
            sr[i1] = t1r - t3i; si[i1] = t1i + t3r;
            sr[i3] = t1r + t3i; si[i3] = t1i - t3r;
        }
    }
    __syncthreads();
    for (int nn = tid; nn < 4096; nn += 512) {
        float re = sr[SKW(nn)], im = si[SKW(nn)];
        float v = sqrtf(re*re + im*im) * (1.f/4096.f)
                + x[((size_t)b*HW_ + nn)*C_ + cg];
        g_out2[((size_t)(b*512) + cg)*HW_ + nn] = v;
    }
}

// ---------------- gating MLP stage 1 ----------------
__global__ void g1_kernel(const float* __restrict__ w1w, const float* __restrict__ w1b,
                          const float* __restrict__ bg, const float* __restrict__ bb,
                          const float* __restrict__ bm, const float* __restrict__ bv) {
    __shared__ float sw[HID_*DD_];
    __shared__ float sa[HID_], st[HID_];
    int b = blockIdx.y;
    int tid = threadIdx.x;
    int n = blockIdx.x*256 + tid;
    for (int e = tid; e < HID_*DD_; e += 256) sw[e] = w1w[e];
    if (tid < HID_) {
        float s = bg[tid] * rsqrtf(bv[tid] + 1e-5f);
        sa[tid] = s;
        st[tid] = w1b[tid]*s + bb[tid] - bm[tid]*s;
    }
    __syncthreads();
    float acc[HID_];
#pragma unroll
    for (int o = 0; o < HID_; o++) acc[o] = 0.f;
    const float* fr = g_fre + (size_t)b*DD_*HW_ + n;
    for (int c = 0; c < DD_; c++) {
        float v = fr[(size_t)c*HW_];
#pragma unroll
        for (int o = 0; o < HID_; o++) acc[o] += v * sw[o*DD_ + c];
    }
#pragma unroll
    for (int o = 0; o < HID_; o++)
        g_g1[((size_t)(b*HID_ + o))*HW_ + n] = fmaxf(acc[o]*sa[o] + st[o], 0.f);
}

// ---------------- fused gate + ifft2 + abs + residual ----------------
__global__ void ifft2_gate_kernel(const float* __restrict__ x,
                                  const float* __restrict__ w2w,
                                  const float* __restrict__ w2b) {
    __shared__ float sr[64*65], si[64*65];
    __shared__ float w2s[HID_];
    int bc = blockIdx.x;
    int b = bc >> 8, c = bc & 255;
    int tid = threadIdx.x;
    if (tid < HID_) w2s[tid] = w2w[c*HID_ + tid];
    __syncthreads();
    float bias = w2b[c];
    float acc[8];
#pragma unroll
    for (int j = 0; j < 8; j++) acc[j] = bias;
    const float* g1p = g_g1 + (size_t)b*HID_*HW_;
#pragma unroll
    for (int o = 0; o < HID_; o++) {
        float w = w2s[o];
        const float* row = g1p + (size_t)o*HW_;
#pragma unroll
        for (int j = 0; j < 8; j++) acc[j] += w * row[tid + j*512];
    }
    const float* fre = g_fre + (size_t)bc*HW_;
    const float* fim = g_fim + (size_t)bc*HW_;
#pragma unroll
    for (int j = 0; j < 8; j++) {
        int e = tid + j*512;
        float gt = 1.f / (1.f + expf(-acc[j]));
        int r = e >> 6, w = e & 63;
        int dw = dig4_6(w);
        sr[r*65 + dw] = gt * fre[e];
        si[r*65 + dw] = gt * fim[e];
    }
    fft64_2d_r4(sr, si, tid, 512, -1.f);
    for (int e = tid; e < 4096; e += 512) {
        float re = sr[(e>>6)*65 + (e&63)], im = si[(e>>6)*65 + (e&63)];
        float v = sqrtf(re*re + im*im) * (1.f/4096.f)
                + x[((size_t)b*HW_ + e)*C_ + (256 + c)];
        g_out2[((size_t)(b*512 + 256 + c))*HW_ + e] = v;
    }
}

// ---------------- final projection via tf32 mma, 4 warps of 64x64 ----------------
// grid (4 o-tiles, 32 n-tiles, 8 b), 128 threads
__global__ void proj_mma_kernel(const float* __restrict__ pw, const float* __restrict__ pb,
                                float* __restrict__ out) {
    __shared__ uint32_t xs[128][36];
    __shared__ uint32_t ws[128][36];
    int b = blockIdx.z, nt = blockIdx.y, ot = blockIdx.x;
    int tid = threadIdx.x, lane = tid & 31, warp = tid >> 5;   // 4 warps
    int wm = warp & 1, wn = warp >> 1;                         // 2 x 2 of 64x64
    int g = lane >> 2, t = lane & 3;
    float acc[4][8][4];
#pragma unroll
    for (int i = 0; i < 4; i++)
#pragma unroll
        for (int j = 0; j < 8; j++)
#pragma unroll
            for (int q = 0; q < 4; q++) acc[i][j][q] = 0.f;

    int n0g = nt*128, o0g = ot*128;
    for (int kc = 0; kc < 512; kc += 32) {
        __syncthreads();
#pragma unroll
        for (int r = 0; r < 8; r++) {
            int e = tid + r*128;
            int k = e >> 5, n4 = e & 31;
            float4 v = *(const float4*)&g_out2[((size_t)(b*512 + kc + k))*HW_ + n0g + n4*4];
            xs[n4*4+0][k] = f2tf(v.x);
            xs[n4*4+1][k] = f2tf(v.y);
            xs[n4*4+2][k] = f2tf(v.z);
            xs[n4*4+3][k] = f2tf(v.w);
        }
#pragma unroll
        for (int r = 0; r < 8; r++) {
            int e = tid + r*128;
            int o = e >> 3, ch = e & 7;
            float4 v = *(const float4*)&pw[(size_t)(o0g + o)*512 + kc + ch*4];
            uint4 u = make_uint4(f2tf(v.x), f2tf(v.y), f2tf(v.z), f2tf(v.w));
            *(uint4*)&ws[o][ch*4] = u;
        }
        __syncthreads();
#pragma unroll
        for (int ks = 0; ks < 32; ks += 8) {
            int kr = ks + t;
            uint32_t a[4][4];
#pragma unroll
            for (int mi = 0; mi < 4; mi++) {
                int m0 = wm*64 + mi*16 + g;
                a[mi][0] = xs[m0][kr];
                a[mi][1] = xs[m0+8][kr];
                a[mi][2] = xs[m0][kr+4];
                a[mi][3] = xs[m0+8][kr+4];
            }
#pragma unroll
            for (int ni = 0; ni < 8; ni++) {
                int n0 = wn*64 + ni*8 + g;
                uint32_t b0 = ws[n0][kr];
                uint32_t b1 = ws[n0][kr+4];
                mma8(acc[0][ni], a[0], b0, b1);
                mma8(acc[1][ni], a[1], b0, b1);
                mma8(acc[2][ni], a[2], b0, b1);
                mma8(acc[3][ni], a[3], b0, b1);
            }
        }
    }
#pragma unroll
    for (int mi = 0; mi < 4; mi++) {
#pragma unroll
        for (int half = 0; half < 2; half++) {
            int n = n0g + wm*64 + mi*16 + g + half*8;
#pragma unroll
            for (int ni = 0; ni < 8; ni++) {
                int o = o0g + wn*64 + ni*8 + 2*t;
                float2 bias = *(const float2*)&pb[o];
                float v0 = acc[mi][ni][half*2+0] + bias.x;
                float v1 = acc[mi][ni][half*2+1] + bias.y;
                *(float2*)&out[((size_t)b*HW_ + n)*C_ + o] = make_float2(v0, v1);
            }
        }
    }
}

// ---------------- launch ----------------
extern "C" void kernel_launch(void* const* d_in, const int* in_sizes, int n_in,
                              void* d_out, int out_size) {
    const float* x       = (const float*)d_in[0];
    const float* conv2_w = (const float*)d_in[1];
    const float* conv2_b = (const float*)d_in[2];
    const float* bn2_g   = (const float*)d_in[3];
    const float* bn2_b   = (const float*)d_in[4];
    const float* bn2_m   = (const float*)d_in[5];
    const float* bn2_v   = (const float*)d_in[6];
    const float* temp    = (const float*)d_in[7];
    const float* w1_w    = (const float*)d_in[8];
    const float* w1_b    = (const float*)d_in[9];
    const float* bnw_g   = (const float*)d_in[10];
    const float* bnw_b   = (const float*)d_in[11];
    const float* bnw_m   = (const float*)d_in[12];
    const float* bnw_v   = (const float*)d_in[13];
    const float* w2_w    = (const float*)d_in[14];
    const float* w2_b    = (const float*)d_in[15];
    const float* proj_w  = (const float*)d_in[16];
    const float* proj_b  = (const float*)d_in[17];
    float* out = (float*)d_out;

    prep_kernel<<<1024, 256>>>(conv2_w);
    conv_mma_kernel<<<dim3(2, 32, 8), 128>>>(x, conv2_b, bn2_g, bn2_b, bn2_m, bn2_v);
    fft2_fwd_kernel<<<1024, 512>>>();
    attn_gemm64_kernel<<<dim3(64, KSPLIT), 256>>>();
    attn_fin_kernel<<<64, 256>>>(temp);
    attn_apply_kernel<<<dim3(32, 64), 256>>>();
    ifft_row_kernel<<<2048, 512>>>(x);
    g1_kernel<<<dim3(16, 8), 256>>>(w1_w, w1_b, bnw_g, bnw_b, bnw_m, bnw_v);
    ifft2_gate_kernel<<<2048, 512>>>(x, w2_w, w2_b);
    proj_mma_kernel<<<dim3(4, 32, 8), 128>>>(proj_w, proj_b, out);
}

// round 13
// speedup vs baseline: 1.2420x; 1.0508x over previous
#include <cuda_runtime.h>
#include <math.h>
#include <stdint.h>

#define B_  8
#define C_  512
#define DD_ 256
#define HW_ 4096
#define HEADS_ 8
#define CPH_ 32
#define HID_ 16
#define KSPLIT 8

// ---------------- scratch ----------------
__device__ __align__(16) uint32_t g_wt[9*256*512];   // conv weights tf32 [tap][co][cin]
__device__ float2 g_twid[4096];
__device__ float  g_y   [(size_t)B_*DD_*HW_];
__device__ float  g_fre [(size_t)B_*DD_*HW_];
__device__ float  g_fim [(size_t)B_*DD_*HW_];
__device__ float  g_g1  [(size_t)B_*HID_*HW_];
__device__ float  g_attnS[KSPLIT*64*64*64];
__device__ float2 g_attn2[64*1024];
__device__ float  g_or  [(size_t)B_*DD_*HW_];
__device__ float  g_oi  [(size_t)B_*DD_*HW_];
__device__ float  g_out2[(size_t)B_*C_*HW_];

// ---------------- tf32 helpers ----------------
__device__ __forceinline__ uint32_t f2tf(float f) {
    uint32_t u;
    asm("cvt.rna.tf32.f32 %0, %1;" : "=r"(u) : "f"(f));
    return u;
}
__device__ __forceinline__ void mma8(float c[4], const uint32_t a[4], uint32_t b0, uint32_t b1) {
    asm volatile("mma.sync.aligned.m16n8k8.row.col.f32.tf32.tf32.f32 "
        "{%0,%1,%2,%3}, {%4,%5,%6,%7}, {%8,%9}, {%0,%1,%2,%3};"
        : "+f"(c[0]), "+f"(c[1]), "+f"(c[2]), "+f"(c[3])
        : "r"(a[0]), "r"(a[1]), "r"(a[2]), "r"(a[3]), "r"(b0), "r"(b1));
}
// octal digit reversals
__device__ __forceinline__ int dig8_6(int x)  { return ((x & 7) << 3) | (x >> 3); }
__device__ __forceinline__ int dig8_12(int x) {
    return ((x & 7) << 9) | (((x >> 3) & 7) << 6) | (((x >> 6) & 7) << 3) | (x >> 9);
}

// ---------------- radix-8 DIF butterfly (natural in, X[m] out) ----------------
__device__ __forceinline__ void bfly8(float xr[8], float xi[8], float sign) {
    const float RH = 0.70710678118654752440f;
    float ur[4], ui[4], vr[4], vi[4];
#pragma unroll
    for (int m = 0; m < 4; m++) {
        ur[m] = xr[m] + xr[m+4]; ui[m] = xi[m] + xi[m+4];
        vr[m] = xr[m] - xr[m+4]; vi[m] = xi[m] - xi[m+4];
    }
    { float a = vr[1], b = vi[1]; vr[1] = RH*(a + sign*b); vi[1] = RH*(b - sign*a); }
    { float a = vr[2], b = vi[2]; vr[2] = sign*b;          vi[2] = -sign*a; }
    { float a = vr[3], b = vi[3]; vr[3] = RH*(sign*b - a); vi[3] = RH*(-b - sign*a); }
    // even outputs: DFT4(u) -> X0,X2,X4,X6
    float q0r = ur[0]+ur[2], q0i = ui[0]+ui[2];
    float q1r = ur[1]+ur[3], q1i = ui[1]+ui[3];
    float r0r = ur[0]-ur[2], r0i = ui[0]-ui[2];
    float d1r = ur[1]-ur[3], d1i = ui[1]-ui[3];
    float r1r = sign*d1i,    r1i = -sign*d1r;
    xr[0] = q0r+q1r; xi[0] = q0i+q1i;
    xr[2] = r0r+r1r; xi[2] = r0i+r1i;
    xr[4] = q0r-q1r; xi[4] = q0i-q1i;
    xr[6] = r0r-r1r; xi[6] = r0i-r1i;
    // odd outputs: DFT4(v) -> X1,X3,X5,X7
    q0r = vr[0]+vr[2]; q0i = vi[0]+vi[2];
    q1r = vr[1]+vr[3]; q1i = vi[1]+vi[3];
    r0r = vr[0]-vr[2]; r0i = vi[0]-vi[2];
    d1r = vr[1]-vr[3]; d1i = vi[1]-vi[3];
    r1r = sign*d1i;    r1i = -sign*d1r;
    xr[1] = q0r+q1r; xi[1] = q0i+q1i;
    xr[3] = r0r+r1r; xi[3] = r0i+r1i;
    xr[5] = q0r-q1r; xi[5] = q0i-q1i;
    xr[7] = r0r-r1r; xi[7] = r0i-r1i;
}

// ---------------- prep ----------------
__global__ void prep_kernel(const float* __restrict__ cw) {
    int tid = blockIdx.x*blockDim.x + threadIdx.x;
    int stride = gridDim.x*blockDim.x;
    if (tid < 4096) {
        float s, c;
        sincosf(-6.28318530717958647692f * (float)tid / 4096.f, &s, &c);
        g_twid[tid] = make_float2(c, s);
    }
    for (int e = tid; e < 9*256*512; e += stride) {
        int tap = e / (256*512);
        int rem = e - tap*256*512;
        int co = rem >> 9;
        int cin = rem & 511;
        g_wt[e] = f2tf(cw[(co*512 + cin)*9 + tap]);
    }
}

// ---------------- conv via tf32 mma: 128co x 128pos, 4 warps of 64x64 ------------
__global__ void conv_mma_kernel(const float* __restrict__ x, const float* __restrict__ cb,
                                const float* __restrict__ bg, const float* __restrict__ bb,
                                const float* __restrict__ bm, const float* __restrict__ bv) {
    __shared__ uint32_t xs[128][36];
    __shared__ uint32_t ws[128][36];
    int b = blockIdx.z, pt = blockIdx.y, ct = blockIdx.x;
    int tid = threadIdx.x, lane = tid & 31, warp = tid >> 5;
    int wm = warp & 1, wn = warp >> 1;
    int g = lane >> 2, t = lane & 3;
    float acc[4][8][4];
#pragma unroll
    for (int i = 0; i < 4; i++)
#pragma unroll
        for (int j = 0; j < 8; j++)
#pragma unroll
            for (int q = 0; q < 4; q++) acc[i][j][q] = 0.f;

    int pos0 = pt*128;
    for (int tap = 0; tap < 9; tap++) {
        int dh = 3*((tap/3) - 1), dw = 3*((tap%3) - 1);
        const uint32_t* wtp = g_wt + ((size_t)tap*256 + ct*128)*512;
        for (int kc = 0; kc < 512; kc += 32) {
            __syncthreads();
#pragma unroll
            for (int r = 0; r < 8; r++) {
                int e = tid + r*128;
                int pos = e >> 3, ch = e & 7;
                int gp = pos0 + pos;
                int ih = (gp >> 6) + dh, iw = (gp & 63) + dw;
                uint4 u = make_uint4(0u, 0u, 0u, 0u);
                if ((unsigned)ih < 64u && (unsigned)iw < 64u)
                    u = *(const uint4*)&x[((size_t)(b*HW_) + ih*64 + iw)*C_ + kc + ch*4];
                *(uint4*)&xs[pos][ch*4] = u;
            }
#pragma unroll
            for (int r = 0; r < 8; r++) {
                int e = tid + r*128;
                int co = e >> 3, ch = e & 7;
                *(uint4*)&ws[co][ch*4] = *(const uint4*)&wtp[(size_t)co*512 + kc + ch*4];
            }
            __syncthreads();
#pragma unroll
            for (int ks = 0; ks < 32; ks += 8) {
                int kr = ks + t;
                uint32_t a[4][4];
#pragma unroll
                for (int mi = 0; mi < 4; mi++) {
                    int m0 = wm*64 + mi*16 + g;
                    a[mi][0] = ws[m0][kr];
                    a[mi][1] = ws[m0+8][kr];
                    a[mi][2] = ws[m0][kr+4];
                    a[mi][3] = ws[m0+8][kr+4];
                }
#pragma unroll
                for (int ni = 0; ni < 8; ni++) {
                    int n0 = wn*64 + ni*8 + g;
                    uint32_t b0 = xs[n0][kr];
                    uint32_t b1 = xs[n0][kr+4];
                    mma8(acc[0][ni], a[0], b0, b1);
                    mma8(acc[1][ni], a[1], b0, b1);
                    mma8(acc[2][ni], a[2], b0, b1);
                    mma8(acc[3][ni], a[3], b0, b1);
                }
            }
        }
    }
#pragma unroll
    for (int mi = 0; mi < 4; mi++) {
#pragma unroll
        for (int half = 0; half < 2; half++) {
            int o = ct*128 + wm*64 + mi*16 + g + half*8;
            float s = bg[o] * rsqrtf(bv[o] + 1e-5f);
            float t0 = cb[o]*s + bb[o] - bm[o]*s;
            float* dst = g_y + ((size_t)(b*DD_ + o))*HW_;
#pragma unroll
            for (int ni = 0; ni < 8; ni++) {
                int pos = pos0 + wn*64 + ni*8 + 2*t;
                float v0 = fmaxf(acc[mi][ni][half*2+0]*s + t0, 0.f);
                float v1 = fmaxf(acc[mi][ni][half*2+1]*s + t0, 0.f);
                *(float2*)&dst[pos] = make_float2(v0, v1);
            }
        }
    }
}

// ---------------- 64x64 2D FFT, radix-8 DIF (4 smem passes, 512 threads) ---------
// natural input; output Z(r,w) stored at [dig8_6(r)*65 + dig8_6(w)]
__device__ __forceinline__ void fft64_2d_dif8(float* sr, float* si, int tid, float sign) {
    float xr[8], xi[8];
    // row pass, stage 1: L=8, twiddle step 64
    __syncthreads();
    {
        int row = tid & 63, j = tid >> 6;
        int base = row*65 + j;
#pragma unroll
        for (int m = 0; m < 8; m++) { xr[m] = sr[base + 8*m]; xi[m] = si[base + 8*m]; }
        bfly8(xr, xi, sign);
#pragma unroll
        for (int m = 1; m < 8; m++) {
            float2 w = g_twid[j*m*64];
            float wr = w.x, wi = sign*w.y;
            float a = xr[m], bb2 = xi[m];
            xr[m] = a*wr - bb2*wi; xi[m] = a*wi + bb2*wr;
        }
#pragma unroll
        for (int m = 0; m < 8; m++) { sr[base + 8*m] = xr[m]; si[base + 8*m] = xi[m]; }
    }
    __syncthreads();
    // row pass, stage 2: L=1
    {
        int row = tid & 63, g = tid >> 6;
        int base = row*65 + g*8;
#pragma unroll
        for (int m = 0; m < 8; m++) { xr[m] = sr[base + m]; xi[m] = si[base + m]; }
        bfly8(xr, xi, sign);
#pragma unroll
        for (int m = 0; m < 8; m++) { sr[base + m] = xr[m]; si[base + m] = xi[m]; }
    }
    __syncthreads();
    // col pass, stage 1: L=8 (stride 8*65)
    {
        int col = tid & 63, j = tid >> 6;
        int base = j*65 + col;
#pragma unroll
        for (int m = 0; m < 8; m++) { xr[m] = sr[base + 520*m]; xi[m] = si[base + 520*m]; }
        bfly8(xr, xi, sign);
#pragma unroll
        for (int m = 1; m < 8; m++) {
            float2 w = g_twid[j*m*64];
            float wr = w.x, wi = sign*w.y;
            float a = xr[m], bb2 = xi[m];
            xr[m] = a*wr - bb2*wi; xi[m] = a*wi + bb2*wr;
        }
#pragma unroll
        for (int m = 0; m < 8; m++) { sr[base + 520*m] = xr[m]; si[base + 520*m] = xi[m]; }
    }
    __syncthreads();
    // col pass, stage 2: L=1 (stride 65)
    {
        int col = tid & 63, g = tid >> 6;
        int base = (g*8)*65 + col;
#pragma unroll
        for (int m = 0; m < 8; m++) { xr[m] = sr[base + 65*m]; xi[m] = si[base + 65*m]; }
        bfly8(xr, xi, sign);
#pragma unroll
        for (int m = 0; m < 8; m++) { sr[base + 65*m] = xr[m]; si[base + 65*m] = xi[m]; }
    }
    __syncthreads();
}

// forward fft2 of real conv output, TWO channels per block via packing
__global__ void fft2_fwd_kernel() {
    __shared__ float sr[64*65], si[64*65];
    int bp = blockIdx.x;
    int b = bp >> 7, cp = bp & 127;
    int c0 = cp*2;
    int tid = threadIdx.x;
    const float* s0 = g_y + ((size_t)(b*DD_ + c0))*HW_;
    const float* s1 = s0 + HW_;
    for (int e = tid; e < 4096; e += 512) {
        int r = e >> 6, w = e & 63;
        sr[r*65 + w] = s0[e];
        si[r*65 + w] = s1[e];
    }
    fft64_2d_dif8(sr, si, tid, 1.f);
    float* f0r = g_fre + ((size_t)(b*DD_ + c0))*HW_;
    float* f0i = g_fim + ((size_t)(b*DD_ + c0))*HW_;
    float* f1r = f0r + HW_;
    float* f1i = f0i + HW_;
    for (int e = tid; e < 4096; e += 512) {
        int r = e >> 6, w = e & 63;
        int rn = (64 - r) & 63, wn = (64 - w) & 63;
        float Zr  = sr[dig8_6(r)*65 + dig8_6(w)],   Zi  = si[dig8_6(r)*65 + dig8_6(w)];
        float Z2r = sr[dig8_6(rn)*65 + dig8_6(wn)], Z2i = si[dig8_6(rn)*65 + dig8_6(wn)];
        f0r[e] = 0.5f*(Zr + Z2r);
        f0i[e] = 0.5f*(Zi - Z2i);
        f1r[e] = 0.5f*(Zi + Z2i);
        f1i[e] = 0.5f*(Z2r - Zr);
    }
}

// ---------------- attention scores ----------------
__global__ void attn_gemm64_kernel() {
    __shared__ uint32_t gs[64][36];
    int bh = blockIdx.x, kq = blockIdx.y;
    int tid = threadIdx.x, lane = tid & 31, warp = tid >> 5;
    int wm = warp & 3, wn = warp >> 2;
    int g = lane >> 2, t = lane & 3;
    float acc[4][4];
#pragma unroll
    for (int i = 0; i < 4; i++)
#pragma unroll
        for (int q = 0; q < 4; q++) acc[i][q] = 0.f;
    const float* fr = g_fre + (size_t)bh*CPH_*HW_;
    const float* fi = g_fim + (size_t)bh*CPH_*HW_;
    int kbeg = kq*(HW_/KSPLIT), kend = kbeg + HW_/KSPLIT;
    for (int k0 = kbeg; k0 < kend; k0 += 32) {
        __syncthreads();
#pragma unroll
        for (int r = 0; r < 2; r++) {
            int e = tid + r*256;
            int row = e >> 3, kqq = e & 7;
            const float* src = (row < 32) ? (fr + (size_t)row*HW_) : (fi + (size_t)(row-32)*HW_);
            float4 v = *(const float4*)&src[k0 + kqq*4];
            uint4 u = make_uint4(f2tf(v.x), f2tf(v.y), f2tf(v.z), f2tf(v.w));
            *(uint4*)&gs[row][kqq*4] = u;
        }
        __syncthreads();
#pragma unroll
        for (int ks = 0; ks < 32; ks += 8) {
            int kr = ks + t;
            uint32_t a[4];
            a[0] = gs[wm*16+g][kr];
            a[1] = gs[wm*16+g+8][kr];
            a[2] = gs[wm*16+g][kr+4];
            a[3] = gs[wm*16+g+8][kr+4];
#pragma unroll
            for (int ni = 0; ni < 4; ni++) {
                int n0 = wn*32 + ni*8 + g;
                mma8(acc[ni], a, gs[n0][kr], gs[n0][kr+4]);
            }
        }
    }
    float* S = g_attnS + ((size_t)(kq*64 + bh))*4096;
#pragma unroll
    for (int ni = 0; ni < 4; ni++) {
        int d = wn*32 + ni*8 + 2*t;
        int c0 = wm*16 + g;
        *(float2*)&S[(size_t)c0*64 + d]     = make_float2(acc[ni][0], acc[ni][1]);
        *(float2*)&S[(size_t)(c0+8)*64 + d] = make_float2(acc[ni][2], acc[ni][3]);
    }
}

// ---------------- attn finalize ----------------
__global__ void attn_fin_kernel(const float* __restrict__ temp) {
    int bh = blockIdx.x;
    int head = bh & 7;
    int tid = threadIdx.x;
    __shared__ float Ss[4096];
    __shared__ float ar_[32*33], ai_[32*33];
    __shared__ float inv[32];
    for (int p = tid; p < 4096; p += 256) {
        float s = 0.f;
#pragma unroll
        for (int q = 0; q < KSPLIT; q++)
            s += g_attnS[((size_t)(q*64 + bh))*4096 + p];
        Ss[p] = s;
    }
    __syncthreads();
    if (tid < 32)
        inv[tid] = rsqrtf(fmaxf(Ss[tid*64 + tid] + Ss[(32+tid)*64 + 32+tid], 1e-24f));
    __syncthreads();
    float tmp = temp[head];
    for (int p = tid; p < 1024; p += 256) {
        int cc = p >> 5, dd = p & 31;
        float sre = Ss[cc*64 + dd] - Ss[(32+cc)*64 + (32+dd)];
        float sim = Ss[cc*64 + (32+dd)] + Ss[(32+cc)*64 + dd];
        float sc = inv[cc] * inv[dd] * tmp;
        ar_[cc*33+dd] = sre*sc;
        ai_[cc*33+dd] = sim*sc;
    }
    __syncthreads();
    int w = tid >> 5, lane = tid & 31;
    for (int r = w; r < 32; r += 8) {
        float vr = ar_[r*33+lane];
        float m = vr;
        for (int o = 16; o; o >>= 1) m = fmaxf(m, __shfl_xor_sync(0xffffffffu, m, o));
        float e = expf(vr - m); float s = e;
        for (int o = 16; o; o >>= 1) s += __shfl_xor_sync(0xffffffffu, s, o);
        ar_[r*33+lane] = e / s;
        float vi = ai_[r*33+lane];
        m = vi;
        for (int o = 16; o; o >>= 1) m = fmaxf(m, __shfl_xor_sync(0xffffffffu, m, o));
        e = expf(vi - m); s = e;
        for (int o = 16; o; o >>= 1) s += __shfl_xor_sync(0xffffffffu, s, o);
        ai_[r*33+lane] = e / s;
    }
    __syncthreads();
    for (int p = tid; p < 1024; p += 256) {
        int k = p >> 5, dd = p & 31;
        float accr = 0.f, acci = 0.f;
#pragma unroll
        for (int cc = 0; cc < 32; cc++) {
            float2 w2 = g_twid[((k*cc) & 31) * 128];
            float wr = w2.x, wi = -w2.y;
            float xr = ar_[cc*33+dd], xi = ai_[cc*33+dd];
            accr += wr*xr - wi*xi;
            acci += wr*xi + wi*xr;
        }
        g_attn2[(size_t)bh*1024 + p] = make_float2(accr*(1.f/32.f), acci*(1.f/32.f));
    }
}

// ---------------- attn apply ----------------
__global__ void attn_apply_kernel() {
    __shared__ float sfr[32][132], sfi[32][132];
    __shared__ float2 a2s[32][32];
    int nc = blockIdx.x, bh = blockIdx.y;
    int tid = threadIdx.x;
    for (int p = tid; p < 1024; p += 256)
        a2s[p>>5][p&31] = g_attn2[(size_t)bh*1024 + p];
    const float* fr = g_fre + (size_t)bh*CPH_*HW_ + nc*128;
    const float* fi = g_fim + (size_t)bh*CPH_*HW_ + nc*128;
    for (int e = tid; e < 1024; e += 256) {
        int d = e >> 5, j = e & 31;
        *(float4*)&sfr[d][j*4] = *(const float4*)&fr[(size_t)d*HW_ + j*4];
        *(float4*)&sfi[d][j*4] = *(const float4*)&fi[(size_t)d*HW_ + j*4];
    }
    __syncthreads();
    int tx = tid & 15, ty = tid >> 4;
    int k0 = ty*2, n0 = tx*8;
    float ar0[8], ai0[8], ar1[8], ai1[8];
#pragma unroll
    for (int j = 0; j < 8; j++) { ar0[j]=0.f; ai0[j]=0.f; ar1[j]=0.f; ai1[j]=0.f; }
#pragma unroll
    for (int d = 0; d < 32; d++) {
        float2 a0 = a2s[k0][d], a1 = a2s[k0+1][d];
        float4 f0 = *(float4*)&sfr[d][n0], f1 = *(float4*)&sfr[d][n0+4];
        float4 h0 = *(float4*)&sfi[d][n0], h1 = *(float4*)&sfi[d][n0+4];
        float frv[8] = {f0.x,f0.y,f0.z,f0.w,f1.x,f1.y,f1.z,f1.w};
        float fiv[8] = {h0.x,h0.y,h0.z,h0.w,h1.x,h1.y,h1.z,h1.w};
#pragma unroll
        for (int j = 0; j < 8; j++) {
            ar0[j] += a0.x*frv[j] - a0.y*fiv[j];
            ai0[j] += a0.x*fiv[j] + a0.y*frv[j];
            ar1[j] += a1.x*frv[j] - a1.y*fiv[j];
            ai1[j] += a1.x*fiv[j] + a1.y*frv[j];
        }
    }
    size_t base0 = ((size_t)(bh*32 + k0))*HW_ + nc*128 + n0;
    size_t base1 = base0 + HW_;
    *(float4*)&g_or[base0]   = make_float4(ar0[0],ar0[1],ar0[2],ar0[3]);
    *(float4*)&g_or[base0+4] = make_float4(ar0[4],ar0[5],ar0[6],ar0[7]);
    *(float4*)&g_oi[base0]   = make_float4(ai0[0],ai0[1],ai0[2],ai0[3]);
    *(float4*)&g_oi[base0+4] = make_float4(ai0[4],ai0[5],ai0[6],ai0[7]);
    *(float4*)&g_or[base1]   = make_float4(ar1[0],ar1[1],ar1[2],ar1[3]);
    *(float4*)&g_or[base1+4] = make_float4(ar1[4],ar1[5],ar1[6],ar1[7]);
    *(float4*)&g_oi[base1]   = make_float4(ai1[0],ai1[1],ai1[2],ai1[3]);
    *(float4*)&g_oi[base1+4] = make_float4(ai1[4],ai1[5],ai1[6],ai1[7]);
}

// ---------------- row ifft4096 radix-8 DIF + abs + residual ----------------
#define SKW(i) ((i) + ((i) >> 7))
__global__ void ifft_row_kernel(const float* __restrict__ x) {
    __shared__ float sr[4128], si[4128];
    int gid = blockIdx.x;
    int b = gid >> 8, cg = gid & 255;
    int tid = threadIdx.x;
    const float* pr = g_or + (size_t)gid*HW_;
    const float* pi = g_oi + (size_t)gid*HW_;
    for (int nn = tid; nn < 4096; nn += 512) {
        int d = SKW(nn);
        sr[d] = pr[nn];
        si[d] = pi[nn];
    }
    float xr[8], xi[8];
    // 4 DIF stages, inverse (conjugated twiddles)
#define IFFT_STAGE(L, LG, TS)                                                       \
    {                                                                               \
        __syncthreads();                                                            \
        int j = tid & ((L) - 1);                                                    \
        int g = tid >> (LG);                                                        \
        int base = g*((L) << 3) + j;                                                \
        _Pragma("unroll")                                                           \
        for (int m = 0; m < 8; m++) {                                               \
            int idx = SKW(base + m*(L));                                            \
            xr[m] = sr[idx]; xi[m] = si[idx];                                       \
        }                                                                           \
        bfly8(xr, xi, -1.f);                                                        \
        if ((L) > 1) {                                                              \
            _Pragma("unroll")                                                       \
            for (int m = 1; m < 8; m++) {                                           \
                float2 w = g_twid[j*m*(TS)];                                        \
                float wr = w.x, wi = -w.y;                                          \
                float a = xr[m], bb2 = xi[m];                                       \
                xr[m] = a*wr - bb2*wi; xi[m] = a*wi + bb2*wr;                       \
            }                                                                       \
        }                                                                           \
        _Pragma("unroll")                                                           \
        for (int m = 0; m < 8; m++) {                                               \
            int idx = SKW(base + m*(L));                                            \
            sr[idx] = xr[m]; si[idx] = xi[m];                                       \
        }                                                                           \
    }
    IFFT_STAGE(512, 9, 1)
    IFFT_STAGE(64, 6, 8)
    IFFT_STAGE(8, 3, 64)
    IFFT_STAGE(1, 0, 0)
#undef IFFT_STAGE
    __syncthreads();
    for (int nn = tid; nn < 4096; nn += 512) {
        int d = SKW(dig8_12(nn));
        float re = sr[d], im = si[d];
        float v = sqrtf(re*re + im*im) * (1.f/4096.f)
                + x[((size_t)b*HW_ + nn)*C_ + cg];
        g_out2[((size_t)(b*512) + cg)*HW_ + nn] = v;
    }
}

// ---------------- gating MLP stage 1 ----------------
__global__ void g1_kernel(const float* __restrict__ w1w, const float* __restrict__ w1b,
                          const float* __restrict__ bg, const float* __restrict__ bb,
                          const float* __restrict__ bm, const float* __restrict__ bv) {
    __shared__ float sw[HID_*DD_];
    __shared__ float sa[HID_], st[HID_];
    int b = blockIdx.y;
    int tid = threadIdx.x;
    int n = blockIdx.x*256 + tid;
    for (int e = tid; e < HID_*DD_; e += 256) sw[e] = w1w[e];
    if (tid < HID_) {
        float s = bg[tid] * rsqrtf(bv[tid] + 1e-5f);
        sa[tid] = s;
        st[tid] = w1b[tid]*s + bb[tid] - bm[tid]*s;
    }
    __syncthreads();
    float acc[HID_];
#pragma unroll
    for (int o = 0; o < HID_; o++) acc[o] = 0.f;
    const float* fr = g_fre + (size_t)b*DD_*HW_ + n;
    for (int c = 0; c < DD_; c++) {
        float v = fr[(size_t)c*HW_];
#pragma unroll
        for (int o = 0; o < HID_; o++) acc[o] += v * sw[o*DD_ + c];
    }
#pragma unroll
    for (int o = 0; o < HID_; o++)
        g_g1[((size_t)(b*HID_ + o))*HW_ + n] = fmaxf(acc[o]*sa[o] + st[o], 0.f);
}

// ---------------- fused gate + ifft2 + abs + residual ----------------
__global__ void ifft2_gate_kernel(const float* __restrict__ x,
                                  const float* __restrict__ w2w,
                                  const float* __restrict__ w2b) {
    __shared__ float sr[64*65], si[64*65];
    __shared__ float w2s[HID_];
    int bc = blockIdx.x;
    int b = bc >> 8, c = bc & 255;
    int tid = threadIdx.x;
    if (tid < HID_) w2s[tid] = w2w[c*HID_ + tid];
    __syncthreads();
    float bias = w2b[c];
    float acc[8];
#pragma unroll
    for (int j = 0; j < 8; j++) acc[j] = bias;
    const float* g1p = g_g1 + (size_t)b*HID_*HW_;
#pragma unroll
    for (int o = 0; o < HID_; o++) {
        float w = w2s[o];
        const float* row = g1p + (size_t)o*HW_;
#pragma unroll
        for (int j = 0; j < 8; j++) acc[j] += w * row[tid + j*512];
    }
    const float* fre = g_fre + (size_t)bc*HW_;
    const float* fim = g_fim + (size_t)bc*HW_;
#pragma unroll
    for (int j = 0; j < 8; j++) {
        int e = tid + j*512;
        float gt = 1.f / (1.f + expf(-acc[j]));
        int r = e >> 6, w = e & 63;
        sr[r*65 + w] = gt * fre[e];
        si[r*65 + w] = gt * fim[e];
    }
    fft64_2d_dif8(sr, si, tid, -1.f);
    for (int e = tid; e < 4096; e += 512) {
        int r = e >> 6, w = e & 63;
        int d = dig8_6(r)*65 + dig8_6(w);
        float re = sr[d], im = si[d];
        float v = sqrtf(re*re + im*im) * (1.f/4096.f)
                + x[((size_t)b*HW_ + e)*C_ + (256 + c)];
        g_out2[((size_t)(b*512 + 256 + c))*HW_ + e] = v;
    }
}

// ---------------- final projection via tf32 mma, 4 warps of 64x64 ----------------
__global__ void proj_mma_kernel(const float* __restrict__ pw, const float* __restrict__ pb,
                                float* __restrict__ out) {
    __shared__ uint32_t xs[128][36];
    __shared__ uint32_t ws[128][36];
    int b = blockIdx.z, nt = blockIdx.y, ot = blockIdx.x;
    int tid = threadIdx.x, lane = tid & 31, warp = tid >> 5;
    int wm = warp & 1, wn = warp >> 1;
    int g = lane >> 2, t = lane & 3;
    float acc[4][8][4];
#pragma unroll
    for (int i = 0; i < 4; i++)
#pragma unroll
        for (int j = 0; j < 8; j++)
#pragma unroll
            for (int q = 0; q < 4; q++) acc[i][j][q] = 0.f;

    int n0g = nt*128, o0g = ot*128;
    for (int kc = 0; kc < 512; kc += 32) {
        __syncthreads();
#pragma unroll
        for (int r = 0; r < 8; r++) {
            int e = tid + r*128;
            int k = e >> 5, n4 = e & 31;
            float4 v = *(const float4*)&g_out2[((size_t)(b*512 + kc + k))*HW_ + n0g + n4*4];
            xs[n4*4+0][k] = f2tf(v.x);
            xs[n4*4+1][k] = f2tf(v.y);
            xs[n4*4+2][k] = f2tf(v.z);
            xs[n4*4+3][k] = f2tf(v.w);
        }
#pragma unroll
        for (int r = 0; r < 8; r++) {
            int e = tid + r*128;
            int o = e >> 3, ch = e & 7;
            float4 v = *(const float4*)&pw[(size_t)(o0g + o)*512 + kc + ch*4];
            uint4 u = make_uint4(f2tf(v.x), f2tf(v.y), f2tf(v.z), f2tf(v.w));
            *(uint4*)&ws[o][ch*4] = u;
        }
        __syncthreads();
#pragma unroll
        for (int ks = 0; ks < 32; ks += 8) {
            int kr = ks + t;
            uint32_t a[4][4];
#pragma unroll
            for (int mi = 0; mi < 4; mi++) {
                int m0 = wm*64 + mi*16 + g;
                a[mi][0] = xs[m0][kr];
                a[mi][1] = xs[m0+8][kr];
                a[mi][2] = xs[m0][kr+4];
                a[mi][3] = xs[m0+8][kr+4];
            }
#pragma unroll
            for (int ni = 0; ni < 8; ni++) {
                int n0 = wn*64 + ni*8 + g;
                uint32_t b0 = ws[n0][kr];
                uint32_t b1 = ws[n0][kr+4];
                mma8(acc[0][ni], a[0], b0, b1);
                mma8(acc[1][ni], a[1], b0, b1);
                mma8(acc[2][ni], a[2], b0, b1);
                mma8(acc[3][ni], a[3], b0, b1);
            }
        }
    }
#pragma unroll
    for (int mi = 0; mi < 4; mi++) {
#pragma unroll
        for (int half = 0; half < 2; half++) {
            int n = n0g + wm*64 + mi*16 + g + half*8;
#pragma unroll
            for (int ni = 0; ni < 8; ni++) {
                int o = o0g + wn*64 + ni*8 + 2*t;
                float2 bias = *(const float2*)&pb[o];
                float v0 = acc[mi][ni][half*2+0] + bias.x;
                float v1 = acc[mi][ni][half*2+1] + bias.y;
                *(float2*)&out[((size_t)b*HW_ + n)*C_ + o] = make_float2(v0, v1);
            }
        }
    }
}

// ---------------- launch ----------------
extern "C" void kernel_launch(void* const* d_in, const int* in_sizes, int n_in,
                              void* d_out, int out_size) {
    const float* x       = (const float*)d_in[0];
    const float* conv2_w = (const float*)d_in[1];
    const float* conv2_b = (const float*)d_in[2];
    const float* bn2_g   = (const float*)d_in[3];
    const float* bn2_b   = (const float*)d_in[4];
    const float* bn2_m   = (const float*)d_in[5];
    const float* bn2_v   = (const float*)d_in[6];
    const float* temp    = (const float*)d_in[7];
    const float* w1_w    = (const float*)d_in[8];
    const float* w1_b    = (const float*)d_in[9];
    const float* bnw_g   = (const float*)d_in[10];
    const float* bnw_b   = (const float*)d_in[11];
    const float* bnw_m   = (const float*)d_in[12];
    const float* bnw_v   = (const float*)d_in[13];
    const float* w2_w    = (const float*)d_in[14];
    const float* w2_b    = (const float*)d_in[15];
    const float* proj_w  = (const float*)d_in[16];
    const float* proj_b  = (const float*)d_in[17];
    float* out = (float*)d_out;

    prep_kernel<<<1024, 256>>>(conv2_w);
    conv_mma_kernel<<<dim3(2, 32, 8), 128>>>(x, conv2_b, bn2_g, bn2_b, bn2_m, bn2_v);
    fft2_fwd_kernel<<<1024, 512>>>();
    attn_gemm64_kernel<<<dim3(64, KSPLIT), 256>>>();
    attn_fin_kernel<<<64, 256>>>(temp);
    attn_apply_kernel<<<dim3(32, 64), 256>>>();
    ifft_row_kernel<<<2048, 512>>>(x);
    g1_kernel<<<dim3(16, 8), 256>>>(w1_w, w1_b, bnw_g, bnw_b, bnw_m, bnw_v);
    ifft2_gate_kernel<<<2048, 512>>>(x, w2_w, w2_b);
    proj_mma_kernel<<<dim3(4, 32, 8), 128>>>(proj_w, proj_b, out);
}

// round 14
// speedup vs baseline: 1.4348x; 1.1552x over previous
#include <cuda_runtime.h>
#include <cuda_fp16.h>
#include <math.h>
#include <stdint.h>

#define B_  8
#define C_  512
#define DD_ 256
#define HW_ 4096
#define HEADS_ 8
#define CPH_ 32
#define HID_ 16
#define KSPLIT 8

// ---------------- scratch ----------------
__device__ __align__(16) uint32_t g_wt16[9*256*256];  // conv weights half2 [tap][co][cin/2]
__device__ float2 g_twid[4096];
__device__ float  g_y   [(size_t)B_*DD_*HW_];
__device__ float  g_fre [(size_t)B_*DD_*HW_];
__device__ float  g_fim [(size_t)B_*DD_*HW_];
__device__ float  g_g1  [(size_t)B_*HID_*HW_];
__device__ float  g_attnS[KSPLIT*64*64*64];
__device__ float2 g_attn2[64*1024];
__device__ float  g_or  [(size_t)B_*DD_*HW_];
__device__ float  g_oi  [(size_t)B_*DD_*HW_];
__device__ float  g_out2[(size_t)B_*C_*HW_];

// ---------------- mma helpers ----------------
__device__ __forceinline__ uint32_t f2tf(float f) {
    uint32_t u;
    asm("cvt.rna.tf32.f32 %0, %1;" : "=r"(u) : "f"(f));
    return u;
}
__device__ __forceinline__ void mma8(float c[4], const uint32_t a[4], uint32_t b0, uint32_t b1) {
    asm volatile("mma.sync.aligned.m16n8k8.row.col.f32.tf32.tf32.f32 "
        "{%0,%1,%2,%3}, {%4,%5,%6,%7}, {%8,%9}, {%0,%1,%2,%3};"
        : "+f"(c[0]), "+f"(c[1]), "+f"(c[2]), "+f"(c[3])
        : "r"(a[0]), "r"(a[1]), "r"(a[2]), "r"(a[3]), "r"(b0), "r"(b1));
}
__device__ __forceinline__ void mma16h(float c[4], const uint32_t a[4], uint32_t b0, uint32_t b1) {
    asm volatile("mma.sync.aligned.m16n8k16.row.col.f32.f16.f16.f32 "
        "{%0,%1,%2,%3}, {%4,%5,%6,%7}, {%8,%9}, {%0,%1,%2,%3};"
        : "+f"(c[0]), "+f"(c[1]), "+f"(c[2]), "+f"(c[3])
        : "r"(a[0]), "r"(a[1]), "r"(a[2]), "r"(a[3]), "r"(b0), "r"(b1));
}
__device__ __forceinline__ uint32_t h2bits(__half2 h) {
    return *(uint32_t*)&h;
}
// octal digit reversals
__device__ __forceinline__ int dig8_6(int x)  { return ((x & 7) << 3) | (x >> 3); }
__device__ __forceinline__ int dig8_12(int x) {
    return ((x & 7) << 9) | (((x >> 3) & 7) << 6) | (((x >> 6) & 7) << 3) | (x >> 9);
}

// ---------------- radix-8 DIF butterfly ----------------
__device__ __forceinline__ void bfly8(float xr[8], float xi[8], float sign) {
    const float RH = 0.70710678118654752440f;
    float ur[4], ui[4], vr[4], vi[4];
#pragma unroll
    for (int m = 0; m < 4; m++) {
        ur[m] = xr[m] + xr[m+4]; ui[m] = xi[m] + xi[m+4];
        vr[m] = xr[m] - xr[m+4]; vi[m] = xi[m] - xi[m+4];
    }
    { float a = vr[1], b = vi[1]; vr[1] = RH*(a + sign*b); vi[1] = RH*(b - sign*a); }
    { float a = vr[2], b = vi[2]; vr[2] = sign*b;          vi[2] = -sign*a; }
    { float a = vr[3], b = vi[3]; vr[3] = RH*(sign*b - a); vi[3] = RH*(-b - sign*a); }
    float q0r = ur[0]+ur[2], q0i = ui[0]+ui[2];
    float q1r = ur[1]+ur[3], q1i = ui[1]+ui[3];
    float r0r = ur[0]-ur[2], r0i = ui[0]-ui[2];
    float d1r = ur[1]-ur[3], d1i = ui[1]-ui[3];
    float r1r = sign*d1i,    r1i = -sign*d1r;
    xr[0] = q0r+q1r; xi[0] = q0i+q1i;
    xr[2] = r0r+r1r; xi[2] = r0i+r1i;
    xr[4] = q0r-q1r; xi[4] = q0i-q1i;
    xr[6] = r0r-r1r; xi[6] = r0i-r1i;
    q0r = vr[0]+vr[2]; q0i = vi[0]+vi[2];
    q1r = vr[1]+vr[3]; q1i = vi[1]+vi[3];
    r0r = vr[0]-vr[2]; r0i = vi[0]-vi[2];
    d1r = vr[1]-vr[3]; d1i = vi[1]-vi[3];
    r1r = sign*d1i;    r1i = -sign*d1r;
    xr[1] = q0r+q1r; xi[1] = q0i+q1i;
    xr[3] = r0r+r1r; xi[3] = r0i+r1i;
    xr[5] = q0r-q1r; xi[5] = q0i-q1i;
    xr[7] = r0r-r1r; xi[7] = r0i-r1i;
}

// ---------------- prep ----------------
__global__ void prep_kernel(const float* __restrict__ cw) {
    int tid = blockIdx.x*blockDim.x + threadIdx.x;
    int stride = gridDim.x*blockDim.x;
    if (tid < 4096) {
        float s, c;
        sincosf(-6.28318530717958647692f * (float)tid / 4096.f, &s, &c);
        g_twid[tid] = make_float2(c, s);
    }
    for (int e = tid; e < 9*256*256; e += stride) {
        int tap = e / (256*256);
        int rem = e - tap*256*256;
        int co = rem >> 8;
        int cin = (rem & 255) * 2;
        float w0 = cw[(co*512 + cin)*9 + tap];
        float w1 = cw[(co*512 + cin + 1)*9 + tap];
        g_wt16[e] = h2bits(__floats2half2_rn(w0, w1));
    }
}

// ---------------- conv via fp16 mma m16n8k16: 128co x 128pos, 4 warps 64x64 ------
__global__ void conv_mma_kernel(const float* __restrict__ x, const float* __restrict__ cb,
                                const float* __restrict__ bg, const float* __restrict__ bb,
                                const float* __restrict__ bm, const float* __restrict__ bv) {
    __shared__ uint32_t xs[128][20];   // 16 half2 words + 4 pad
    __shared__ uint32_t ws[128][20];
    int b = blockIdx.z, pt = blockIdx.y, ct = blockIdx.x;
    int tid = threadIdx.x, lane = tid & 31, warp = tid >> 5;
    int wm = warp & 1, wn = warp >> 1;
    int g = lane >> 2, t = lane & 3;
    float acc[4][8][4];
#pragma unroll
    for (int i = 0; i < 4; i++)
#pragma unroll
        for (int j = 0; j < 8; j++)
#pragma unroll
            for (int q = 0; q < 4; q++) acc[i][j][q] = 0.f;

    int pos0 = pt*128;
    for (int tap = 0; tap < 9; tap++) {
        int dh = 3*((tap/3) - 1), dw = 3*((tap%3) - 1);
        const uint32_t* wtp = g_wt16 + ((size_t)tap*256 + ct*128)*256;
        for (int kc = 0; kc < 512; kc += 32) {
            __syncthreads();
            // x fill: 1024 elems of float4 -> 2 half2 words
#pragma unroll
            for (int r = 0; r < 8; r++) {
                int e = tid + r*128;
                int pos = e >> 3, ch = e & 7;
                int gp = pos0 + pos;
                int ih = (gp >> 6) + dh, iw = (gp & 63) + dw;
                uint2 u = make_uint2(0u, 0u);
                if ((unsigned)ih < 64u && (unsigned)iw < 64u) {
                    float4 v = *(const float4*)&x[((size_t)(b*HW_) + ih*64 + iw)*C_ + kc + ch*4];
                    u.x = h2bits(__floats2half2_rn(v.x, v.y));
                    u.y = h2bits(__floats2half2_rn(v.z, v.w));
                }
                *(uint2*)&xs[pos][ch*2] = u;
            }
            // w fill: 512 elems of uint4 (pre-packed half2)
#pragma unroll
            for (int r = 0; r < 4; r++) {
                int e = tid + r*128;
                int co = e >> 2, ch = e & 3;
                *(uint4*)&ws[co][ch*4] =
                    *(const uint4*)&wtp[(size_t)co*256 + (kc >> 1) + ch*4];
            }
            __syncthreads();
#pragma unroll
            for (int ks = 0; ks < 2; ks++) {
                int kb = ks*8 + t;
                uint32_t a[4][4];
#pragma unroll
                for (int mi = 0; mi < 4; mi++) {
                    int m0 = wm*64 + mi*16 + g;
                    a[mi][0] = ws[m0][kb];
                    a[mi][1] = ws[m0+8][kb];
                    a[mi][2] = ws[m0][kb+4];
                    a[mi][3] = ws[m0+8][kb+4];
                }
#pragma unroll
                for (int ni = 0; ni < 8; ni++) {
                    int n0 = wn*64 + ni*8 + g;
                    uint32_t b0 = xs[n0][kb];
                    uint32_t b1 = xs[n0][kb+4];
                    mma16h(acc[0][ni], a[0], b0, b1);
                    mma16h(acc[1][ni], a[1], b0, b1);
                    mma16h(acc[2][ni], a[2], b0, b1);
                    mma16h(acc[3][ni], a[3], b0, b1);
                }
            }
        }
    }
#pragma unroll
    for (int mi = 0; mi < 4; mi++) {
#pragma unroll
        for (int half = 0; half < 2; half++) {
            int o = ct*128 + wm*64 + mi*16 + g + half*8;
            float s = bg[o] * rsqrtf(bv[o] + 1e-5f);
            float t0 = cb[o]*s + bb[o] - bm[o]*s;
            float* dst = g_y + ((size_t)(b*DD_ + o))*HW_;
#pragma unroll
            for (int ni = 0; ni < 8; ni++) {
                int pos = pos0 + wn*64 + ni*8 + 2*t;
                float v0 = fmaxf(acc[mi][ni][half*2+0]*s + t0, 0.f);
                float v1 = fmaxf(acc[mi][ni][half*2+1]*s + t0, 0.f);
                *(float2*)&dst[pos] = make_float2(v0, v1);
            }
        }
    }
}

// ---------------- 64x64 2D FFT, radix-8 DIF (4 smem passes, 512 threads) ---------
__device__ __forceinline__ void fft64_2d_dif8(float* sr, float* si, int tid, float sign) {
    float xr[8], xi[8];
    __syncthreads();
    {
        int row = tid & 63, j = tid >> 6;
        int base = row*65 + j;
#pragma unroll
        for (int m = 0; m < 8; m++) { xr[m] = sr[base + 8*m]; xi[m] = si[base + 8*m]; }
        bfly8(xr, xi, sign);
#pragma unroll
        for (int m = 1; m < 8; m++) {
            float2 w = g_twid[j*m*64];
            float wr = w.x, wi = sign*w.y;
            float a = xr[m], bb2 = xi[m];
            xr[m] = a*wr - bb2*wi; xi[m] = a*wi + bb2*wr;
        }
#pragma unroll
        for (int m = 0; m < 8; m++) { sr[base + 8*m] = xr[m]; si[base + 8*m] = xi[m]; }
    }
    __syncthreads();
    {
        int row = tid & 63, g = tid >> 6;
        int base = row*65 + g*8;
#pragma unroll
        for (int m = 0; m < 8; m++) { xr[m] = sr[base + m]; xi[m] = si[base + m]; }
        bfly8(xr, xi, sign);
#pragma unroll
        for (int m = 0; m < 8; m++) { sr[base + m] = xr[m]; si[base + m] = xi[m]; }
    }
    __syncthreads();
    {
        int col = tid & 63, j = tid >> 6;
        int base = j*65 + col;
#pragma unroll
        for (int m = 0; m < 8; m++) { xr[m] = sr[base + 520*m]; xi[m] = si[base + 520*m]; }
        bfly8(xr, xi, sign);
#pragma unroll
        for (int m = 1; m < 8; m++) {
            float2 w = g_twid[j*m*64];
            float wr = w.x, wi = sign*w.y;
            float a = xr[m], bb2 = xi[m];
            xr[m] = a*wr - bb2*wi; xi[m] = a*wi + bb2*wr;
        }
#pragma unroll
        for (int m = 0; m < 8; m++) { sr[base + 520*m] = xr[m]; si[base + 520*m] = xi[m]; }
    }
    __syncthreads();
    {
        int col = tid & 63, g = tid >> 6;
        int base = (g*8)*65 + col;
#pragma unroll
        for (int m = 0; m < 8; m++) { xr[m] = sr[base + 65*m]; xi[m] = si[base + 65*m]; }
        bfly8(xr, xi, sign);
#pragma unroll
        for (int m = 0; m < 8; m++) { sr[base + 65*m] = xr[m]; si[base + 65*m] = xi[m]; }
    }
    __syncthreads();
}

// forward fft2 of real conv output, TWO channels per block via packing
__global__ void fft2_fwd_kernel() {
    __shared__ float sr[64*65], si[64*65];
    int bp = blockIdx.x;
    int b = bp >> 7, cp = bp & 127;
    int c0 = cp*2;
    int tid = threadIdx.x;
    const float* s0 = g_y + ((size_t)(b*DD_ + c0))*HW_;
    const float* s1 = s0 + HW_;
    for (int e = tid; e < 4096; e += 512) {
        int r = e >> 6, w = e & 63;
        sr[r*65 + w] = s0[e];
        si[r*65 + w] = s1[e];
    }
    fft64_2d_dif8(sr, si, tid, 1.f);
    float* f0r = g_fre + ((size_t)(b*DD_ + c0))*HW_;
    float* f0i = g_fim + ((size_t)(b*DD_ + c0))*HW_;
    float* f1r = f0r + HW_;
    float* f1i = f0i + HW_;
    for (int e = tid; e < 4096; e += 512) {
        int r = e >> 6, w = e & 63;
        int rn = (64 - r) & 63, wn = (64 - w) & 63;
        float Zr  = sr[dig8_6(r)*65 + dig8_6(w)],   Zi  = si[dig8_6(r)*65 + dig8_6(w)];
        float Z2r = sr[dig8_6(rn)*65 + dig8_6(wn)], Z2i = si[dig8_6(rn)*65 + dig8_6(wn)];
        f0r[e] = 0.5f*(Zr + Z2r);
        f0i[e] = 0.5f*(Zi - Z2i);
        f1r[e] = 0.5f*(Zi + Z2i);
        f1i[e] = 0.5f*(Z2r - Zr);
    }
}

// ---------------- attention scores ----------------
__global__ void attn_gemm64_kernel() {
    __shared__ uint32_t gs[64][36];
    int bh = blockIdx.x, kq = blockIdx.y;
    int tid = threadIdx.x, lane = tid & 31, warp = tid >> 5;
    int wm = warp & 3, wn = warp >> 2;
    int g = lane >> 2, t = lane & 3;
    float acc[4][4];
#pragma unroll
    for (int i = 0; i < 4; i++)
#pragma unroll
        for (int q = 0; q < 4; q++) acc[i][q] = 0.f;
    const float* fr = g_fre + (size_t)bh*CPH_*HW_;
    const float* fi = g_fim + (size_t)bh*CPH_*HW_;
    int kbeg = kq*(HW_/KSPLIT), kend = kbeg + HW_/KSPLIT;
    for (int k0 = kbeg; k0 < kend; k0 += 32) {
        __syncthreads();
#pragma unroll
        for (int r = 0; r < 2; r++) {
            int e = tid + r*256;
            int row = e >> 3, kqq = e & 7;
            const float* src = (row < 32) ? (fr + (size_t)row*HW_) : (fi + (size_t)(row-32)*HW_);
            float4 v = *(const float4*)&src[k0 + kqq*4];
            uint4 u = make_uint4(f2tf(v.x), f2tf(v.y), f2tf(v.z), f2tf(v.w));
            *(uint4*)&gs[row][kqq*4] = u;
        }
        __syncthreads();
#pragma unroll
        for (int ks = 0; ks < 32; ks += 8) {
            int kr = ks + t;
            uint32_t a[4];
            a[0] = gs[wm*16+g][kr];
            a[1] = gs[wm*16+g+8][kr];
            a[2] = gs[wm*16+g][kr+4];
            a[3] = gs[wm*16+g+8][kr+4];
#pragma unroll
            for (int ni = 0; ni < 4; ni++) {
                int n0 = wn*32 + ni*8 + g;
                mma8(acc[ni], a, gs[n0][kr], gs[n0][kr+4]);
            }
        }
    }
    float* S = g_attnS + ((size_t)(kq*64 + bh))*4096;
#pragma unroll
    for (int ni = 0; ni < 4; ni++) {
        int d = wn*32 + ni*8 + 2*t;
        int c0 = wm*16 + g;
        *(float2*)&S[(size_t)c0*64 + d]     = make_float2(acc[ni][0], acc[ni][1]);
        *(float2*)&S[(size_t)(c0+8)*64 + d] = make_float2(acc[ni][2], acc[ni][3]);
    }
}

// ---------------- attn finalize ----------------
__global__ void attn_fin_kernel(const float* __restrict__ temp) {
    int bh = blockIdx.x;
    int head = bh & 7;
    int tid = threadIdx.x;
    __shared__ float Ss[4096];
    __shared__ float ar_[32*33], ai_[32*33];
    __shared__ float inv[32];
    for (int p = tid; p < 4096; p += 256) {
        float s = 0.f;
#pragma unroll
        for (int q = 0; q < KSPLIT; q++)
            s += g_attnS[((size_t)(q*64 + bh))*4096 + p];
        Ss[p] = s;
    }
    __syncthreads();
    if (tid < 32)
        inv[tid] = rsqrtf(fmaxf(Ss[tid*64 + tid] + Ss[(32+tid)*64 + 32+tid], 1e-24f));
    __syncthreads();
    float tmp = temp[head];
    for (int p = tid; p < 1024; p += 256) {
        int cc = p >> 5, dd = p & 31;
        float sre = Ss[cc*64 + dd] - Ss[(32+cc)*64 + (32+dd)];
        float sim = Ss[cc*64 + (32+dd)] + Ss[(32+cc)*64 + dd];
        float sc = inv[cc] * inv[dd] * tmp;
        ar_[cc*33+dd] = sre*sc;
        ai_[cc*33+dd] = sim*sc;
    }
    __syncthreads();
    int w = tid >> 5, lane = tid & 31;
    for (int r = w; r < 32; r += 8) {
        float vr = ar_[r*33+lane];
        float m = vr;
        for (int o = 16; o; o >>= 1) m = fmaxf(m, __shfl_xor_sync(0xffffffffu, m, o));
        float e = expf(vr - m); float s = e;
        for (int o = 16; o; o >>= 1) s += __shfl_xor_sync(0xffffffffu, s, o);
        ar_[r*33+lane] = e / s;
        float vi = ai_[r*33+lane];
        m = vi;
        for (int o = 16; o; o >>= 1) m = fmaxf(m, __shfl_xor_sync(0xffffffffu, m, o));
        e = expf(vi - m); s = e;
        for (int o = 16; o; o >>= 1) s += __shfl_xor_sync(0xffffffffu, s, o);
        ai_[r*33+lane] = e / s;
    }
    __syncthreads();
    for (int p = tid; p < 1024; p += 256) {
        int k = p >> 5, dd = p & 31;
        float accr = 0.f, acci = 0.f;
#pragma unroll
        for (int cc = 0; cc < 32; cc++) {
            float2 w2 = g_twid[((k*cc) & 31) * 128];
            float wr = w2.x, wi = -w2.y;
            float xr = ar_[cc*33+dd], xi = ai_[cc*33+dd];
            accr += wr*xr - wi*xi;
            acci += wr*xi + wi*xr;
        }
        g_attn2[(size_t)bh*1024 + p] = make_float2(accr*(1.f/32.f), acci*(1.f/32.f));
    }
}

// ---------------- attn apply ----------------
__global__ void attn_apply_kernel() {
    __shared__ float sfr[32][132], sfi[32][132];
    __shared__ float2 a2s[32][32];
    int nc = blockIdx.x, bh = blockIdx.y;
    int tid = threadIdx.x;
    for (int p = tid; p < 1024; p += 256)
        a2s[p>>5][p&31] = g_attn2[(size_t)bh*1024 + p];
    const float* fr = g_fre + (size_t)bh*CPH_*HW_ + nc*128;
    const float* fi = g_fim + (size_t)bh*CPH_*HW_ + nc*128;
    for (int e = tid; e < 1024; e += 256) {
        int d = e >> 5, j = e & 31;
        *(float4*)&sfr[d][j*4] = *(const float4*)&fr[(size_t)d*HW_ + j*4];
        *(float4*)&sfi[d][j*4] = *(const float4*)&fi[(size_t)d*HW_ + j*4];
    }
    __syncthreads();
    int tx = tid & 15, ty = tid >> 4;
    int k0 = ty*2, n0 = tx*8;
    float ar0[8], ai0[8], ar1[8], ai1[8];
#pragma unroll
    for (int j = 0; j < 8; j++) { ar0[j]=0.f; ai0[j]=0.f; ar1[j]=0.f; ai1[j]=0.f; }
#pragma unroll
    for (int d = 0; d < 32; d++) {
        float2 a0 = a2s[k0][d], a1 = a2s[k0+1][d];
        float4 f0 = *(float4*)&sfr[d][n0], f1 = *(float4*)&sfr[d][n0+4];
        float4 h0 = *(float4*)&sfi[d][n0], h1 = *(float4*)&sfi[d][n0+4];
        float frv[8] = {f0.x,f0.y,f0.z,f0.w,f1.x,f1.y,f1.z,f1.w};
        float fiv[8] = {h0.x,h0.y,h0.z,h0.w,h1.x,h1.y,h1.z,h1.w};
#pragma unroll
        for (int j = 0; j < 8; j++) {
            ar0[j] += a0.x*frv[j] - a0.y*fiv[j];
            ai0[j] += a0.x*fiv[j] + a0.y*frv[j];
            ar1[j] += a1.x*frv[j] - a1.y*fiv[j];
            ai1[j] += a1.x*fiv[j] + a1.y*frv[j];
        }
    }
    size_t base0 = ((size_t)(bh*32 + k0))*HW_ + nc*128 + n0;
    size_t base1 = base0 + HW_;
    *(float4*)&g_or[base0]   = make_float4(ar0[0],ar0[1],ar0[2],ar0[3]);
    *(float4*)&g_or[base0+4] = make_float4(ar0[4],ar0[5],ar0[6],ar0[7]);
    *(float4*)&g_oi[base0]   = make_float4(ai0[0],ai0[1],ai0[2],ai0[3]);
    *(float4*)&g_oi[base0+4] = make_float4(ai0[4],ai0[5],ai0[6],ai0[7]);
    *(float4*)&g_or[base1]   = make_float4(ar1[0],ar1[1],ar1[2],ar1[3]);
    *(float4*)&g_or[base1+4] = make_float4(ar1[4],ar1[5],ar1[6],ar1[7]);
    *(float4*)&g_oi[base1]   = make_float4(ai1[0],ai1[1],ai1[2],ai1[3]);
    *(float4*)&g_oi[base1+4] = make_float4(ai1[4],ai1[5],ai1[6],ai1[7]);
}

// ---------------- row ifft4096 radix-8 DIF + abs + residual ----------------
#define SKW(i) ((i) + ((i) >> 7))
__global__ void ifft_row_kernel(const float* __restrict__ x) {
    __shared__ float sr[4128], si[4128];
    int gid = blockIdx.x;
    int b = gid >> 8, cg = gid & 255;
    int tid = threadIdx.x;
    const float* pr = g_or + (size_t)gid*HW_;
    const float* pi = g_oi + (size_t)gid*HW_;
    for (int nn = tid; nn < 4096; nn += 512) {
        int d = SKW(nn);
        sr[d] = pr[nn];
        si[d] = pi[nn];
    }
    float xr[8], xi[8];
#define IFFT_STAGE(L, LG, TS)                                                       \
    {                                                                               \
        __syncthreads();                                                            \
        int j = tid & ((L) - 1);                                                    \
        int g = tid >> (LG);                                                        \
        int base = g*((L) << 3) + j;                                                \
        _Pragma("unroll")                                                           \
        for (int m = 0; m < 8; m++) {                                               \
            int idx = SKW(base + m*(L));                                            \
            xr[m] = sr[idx]; xi[m] = si[idx];                                       \
        }                                                                           \
        bfly8(xr, xi, -1.f);                                                        \
        if ((L) > 1) {                                                              \
            _Pragma("unroll")                                                       \
            for (int m = 1; m < 8; m++) {                                           \
                float2 w = g_twid[j*m*(TS)];                                        \
                float wr = w.x, wi = -w.y;                                          \
                float a = xr[m], bb2 = xi[m];                                       \
                xr[m] = a*wr - bb2*wi; xi[m] = a*wi + bb2*wr;                       \
            }                                                                       \
        }                                                                           \
        _Pragma("unroll")                                                           \
        for (int m = 0; m < 8; m++) {                                               \
            int idx = SKW(base + m*(L));                                            \
            sr[idx] = xr[m]; si[idx] = xi[m];                                       \
        }                                                                           \
    }
    IFFT_STAGE(512, 9, 1)
    IFFT_STAGE(64, 6, 8)
    IFFT_STAGE(8, 3, 64)
    IFFT_STAGE(1, 0, 0)
#undef IFFT_STAGE
    __syncthreads();
    for (int nn = tid; nn < 4096; nn += 512) {
        int d = SKW(dig8_12(nn));
        float re = sr[d], im = si[d];
        float v = sqrtf(re*re + im*im) * (1.f/4096.f)
                + x[((size_t)b*HW_ + nn)*C_ + cg];
        g_out2[((size_t)(b*512) + cg)*HW_ + nn] = v;
    }
}

// ---------------- gating MLP stage 1 ----------------
__global__ void g1_kernel(const float* __restrict__ w1w, const float* __restrict__ w1b,
                          const float* __restrict__ bg, const float* __restrict__ bb,
                          const float* __restrict__ bm, const float* __restrict__ bv) {
    __shared__ float sw[HID_*DD_];
    __shared__ float sa[HID_], st[HID_];
    int b = blockIdx.y;
    int tid = threadIdx.x;
    int n = blockIdx.x*256 + tid;
    for (int e = tid; e < HID_*DD_; e += 256) sw[e] = w1w[e];
    if (tid < HID_) {
        float s = bg[tid] * rsqrtf(bv[tid] + 1e-5f);
        sa[tid] = s;
        st[tid] = w1b[tid]*s + bb[tid] - bm[tid]*s;
    }
    __syncthreads();
    float acc[HID_];
#pragma unroll
    for (int o = 0; o < HID_; o++) acc[o] = 0.f;
    const float* fr = g_fre + (size_t)b*DD_*HW_ + n;
    for (int c = 0; c < DD_; c++) {
        float v = fr[(size_t)c*HW_];
#pragma unroll
        for (int o = 0; o < HID_; o++) acc[o] += v * sw[o*DD_ + c];
    }
#pragma unroll
    for (int o = 0; o < HID_; o++)
        g_g1[((size_t)(b*HID_ + o))*HW_ + n] = fmaxf(acc[o]*sa[o] + st[o], 0.f);
}

// ---------------- fused gate + ifft2 + abs + residual ----------------
__global__ void ifft2_gate_kernel(const float* __restrict__ x,
                                  const float* __restrict__ w2w,
                                  const float* __restrict__ w2b) {
    __shared__ float sr[64*65], si[64*65];
    __shared__ float w2s[HID_];
    int bc = blockIdx.x;
    int b = bc >> 8, c = bc & 255;
    int tid = threadIdx.x;
    if (tid < HID_) w2s[tid] = w2w[c*HID_ + tid];
    __syncthreads();
    float bias = w2b[c];
    float acc[8];
#pragma unroll
    for (int j = 0; j < 8; j++) acc[j] = bias;
    const float* g1p = g_g1 + (size_t)b*HID_*HW_;
#pragma unroll
    for (int o = 0; o < HID_; o++) {
        float w = w2s[o];
        const float* row = g1p + (size_t)o*HW_;
#pragma unroll
        for (int j = 0; j < 8; j++) acc[j] += w * row[tid + j*512];
    }
    const float* fre = g_fre + (size_t)bc*HW_;
    const float* fim = g_fim + (size_t)bc*HW_;
#pragma unroll
    for (int j = 0; j < 8; j++) {
        int e = tid + j*512;
        float gt = 1.f / (1.f + expf(-acc[j]));
        int r = e >> 6, w = e & 63;
        sr[r*65 + w] = gt * fre[e];
        si[r*65 + w] = gt * fim[e];
    }
    fft64_2d_dif8(sr, si, tid, -1.f);
    for (int e = tid; e < 4096; e += 512) {
        int r = e >> 6, w = e & 63;
        int d = dig8_6(r)*65 + dig8_6(w);
        float re = sr[d], im = si[d];
        float v = sqrtf(re*re + im*im) * (1.f/4096.f)
                + x[((size_t)b*HW_ + e)*C_ + (256 + c)];
        g_out2[((size_t)(b*512 + 256 + c))*HW_ + e] = v;
    }
}

// ---------------- final projection via tf32 mma, 4 warps of 64x64 ----------------
__global__ void proj_mma_kernel(const float* __restrict__ pw, const float* __restrict__ pb,
                                float* __restrict__ out) {
    __shared__ uint32_t xs[128][36];
    __shared__ uint32_t ws[128][36];
    int b = blockIdx.z, nt = blockIdx.y, ot = blockIdx.x;
    int tid = threadIdx.x, lane = tid & 31, warp = tid >> 5;
    int wm = warp & 1, wn = warp >> 1;
    int g = lane >> 2, t = lane & 3;
    float acc[4][8][4];
#pragma unroll
    for (int i = 0; i < 4; i++)
#pragma unroll
        for (int j = 0; j < 8; j++)
#pragma unroll
            for (int q = 0; q < 4; q++) acc[i][j][q] = 0.f;

    int n0g = nt*128, o0g = ot*128;
    for (int kc = 0; kc < 512; kc += 32) {
        __syncthreads();
#pragma unroll
        for (int r = 0; r < 8; r++) {
            int e = tid + r*128;
            int k = e >> 5, n4 = e & 31;
            float4 v = *(const float4*)&g_out2[((size_t)(b*512 + kc + k))*HW_ + n0g + n4*4];
            xs[n4*4+0][k] = f2tf(v.x);
            xs[n4*4+1][k] = f2tf(v.y);
            xs[n4*4+2][k] = f2tf(v.z);
            xs[n4*4+3][k] = f2tf(v.w);
        }
#pragma unroll
        for (int r = 0; r < 8; r++) {
            int e = tid + r*128;
            int o = e >> 3, ch = e & 7;
            float4 v = *(const float4*)&pw[(size_t)(o0g + o)*512 + kc + ch*4];
            uint4 u = make_uint4(f2tf(v.x), f2tf(v.y), f2tf(v.z), f2tf(v.w));
            *(uint4*)&ws[o][ch*4] = u;
        }
        __syncthreads();
#pragma unroll
        for (int ks = 0; ks < 32; ks += 8) {
            int kr = ks + t;
            uint32_t a[4][4];
#pragma unroll
            for (int mi = 0; mi < 4; mi++) {
                int m0 = wm*64 + mi*16 + g;
                a[mi][0] = xs[m0][kr];
                a[mi][1] = xs[m0+8][kr];
                a[mi][2] = xs[m0][kr+4];
                a[mi][3] = xs[m0+8][kr+4];
            }
#pragma unroll
            for (int ni = 0; ni < 8; ni++) {
                int n0 = wn*64 + ni*8 + g;
                uint32_t b0 = ws[n0][kr];
                uint32_t b1 = ws[n0][kr+4];
                mma8(acc[0][ni], a[0], b0, b1);
                mma8(acc[1][ni], a[1], b0, b1);
                mma8(acc[2][ni], a[2], b0, b1);
                mma8(acc[3][ni], a[3], b0, b1);
            }
        }
    }
#pragma unroll
    for (int mi = 0; mi < 4; mi++) {
#pragma unroll
        for (int half = 0; half < 2; half++) {
            int n = n0g + wm*64 + mi*16 + g + half*8;
#pragma unroll
            for (int ni = 0; ni < 8; ni++) {
                int o = o0g + wn*64 + ni*8 + 2*t;
                float2 bias = *(const float2*)&pb[o];
                float v0 = acc[mi][ni][half*2+0] + bias.x;
                float v1 = acc[mi][ni][half*2+1] + bias.y;
                *(float2*)&out[((size_t)b*HW_ + n)*C_ + o] = make_float2(v0, v1);
            }
        }
    }
}

// ---------------- launch ----------------
extern "C" void kernel_launch(void* const* d_in, const int* in_sizes, int n_in,
                              void* d_out, int out_size) {
    const float* x       = (const float*)d_in[0];
    const float* conv2_w = (const float*)d_in[1];
    const float* conv2_b = (const float*)d_in[2];
    const float* bn2_g   = (const float*)d_in[3];
    const float* bn2_b   = (const float*)d_in[4];
    const float* bn2_m   = (const float*)d_in[5];
    const float* bn2_v   = (const float*)d_in[6];
    const float* temp    = (const float*)d_in[7];
    const float* w1_w    = (const float*)d_in[8];
    const float* w1_b    = (const float*)d_in[9];
    const float* bnw_g   = (const float*)d_in[10];
    const float* bnw_b   = (const float*)d_in[11];
    const float* bnw_m   = (const float*)d_in[12];
    const float* bnw_v   = (const float*)d_in[13];
    const float* w2_w    = (const float*)d_in[14];
    const float* w2_b    = (const float*)d_in[15];
    const float* proj_w  = (const float*)d_in[16];
    const float* proj_b  = (const float*)d_in[17];
    float* out = (float*)d_out;

    prep_kernel<<<1024, 256>>>(conv2_w);
    conv_mma_kernel<<<dim3(2, 32, 8), 128>>>(x, conv2_b, bn2_g, bn2_b, bn2_m, bn2_v);
    fft2_fwd_kernel<<<1024, 512>>>();
    attn_gemm64_kernel<<<dim3(64, KSPLIT), 256>>>();
    attn_fin_kernel<<<64, 256>>>(temp);
    attn_apply_kernel<<<dim3(32, 64), 256>>>();
    ifft_row_kernel<<<2048, 512>>>(x);
    g1_kernel<<<dim3(16, 8), 256>>>(w1_w, w1_b, bnw_g, bnw_b, bnw_m, bnw_v);
    ifft2_gate_kernel<<<2048, 512>>>(x, w2_w, w2_b);
    proj_mma_kernel<<<dim3(4, 32, 8), 128>>>(proj_w, proj_b, out);
}

// round 15
// speedup vs baseline: 1.5593x; 1.0868x over previous
#include <cuda_runtime.h>
#include <cuda_fp16.h>
#include <math.h>
#include <stdint.h>

#define B_  8
#define C_  512
#define DD_ 256
#define HW_ 4096
#define HEADS_ 8
#define CPH_ 32
#define HID_ 16
#define KSPLIT 8

// ---------------- scratch ----------------
__device__ __align__(16) uint32_t g_wt16[9*256*256];  // conv weights half2 [tap][co][cin/2]
__device__ __align__(16) uint32_t g_pw16[512*256];    // proj weights half2 [o][c/2]
__device__ float2 g_twid[4096];
__device__ float  g_y   [(size_t)B_*DD_*HW_];
__device__ float  g_fre [(size_t)B_*DD_*HW_];
__device__ float  g_fim [(size_t)B_*DD_*HW_];
__device__ float  g_g1  [(size_t)B_*HID_*HW_];
__device__ float  g_attnS[KSPLIT*64*64*64];
__device__ float2 g_attn2[64*1024];
__device__ float  g_or  [(size_t)B_*DD_*HW_];
__device__ float  g_oi  [(size_t)B_*DD_*HW_];
__device__ float  g_out2[(size_t)B_*C_*HW_];

// ---------------- mma helpers ----------------
__device__ __forceinline__ void mma16h(float c[4], const uint32_t a[4], uint32_t b0, uint32_t b1) {
    asm volatile("mma.sync.aligned.m16n8k16.row.col.f32.f16.f16.f32 "
        "{%0,%1,%2,%3}, {%4,%5,%6,%7}, {%8,%9}, {%0,%1,%2,%3};"
        : "+f"(c[0]), "+f"(c[1]), "+f"(c[2]), "+f"(c[3])
        : "r"(a[0]), "r"(a[1]), "r"(a[2]), "r"(a[3]), "r"(b0), "r"(b1));
}
__device__ __forceinline__ uint32_t h2bits(__half2 h) {
    return *(uint32_t*)&h;
}
// octal digit reversals
__device__ __forceinline__ int dig8_6(int x)  { return ((x & 7) << 3) | (x >> 3); }
__device__ __forceinline__ int dig8_12(int x) {
    return ((x & 7) << 9) | (((x >> 3) & 7) << 6) | (((x >> 6) & 7) << 3) | (x >> 9);
}

// ---------------- radix-8 DIF butterfly ----------------
__device__ __forceinline__ void bfly8(float xr[8], float xi[8], float sign) {
    const float RH = 0.70710678118654752440f;
    float ur[4], ui[4], vr[4], vi[4];
#pragma unroll
    for (int m = 0; m < 4; m++) {
        ur[m] = xr[m] + xr[m+4]; ui[m] = xi[m] + xi[m+4];
        vr[m] = xr[m] - xr[m+4]; vi[m] = xi[m] - xi[m+4];
    }
    { float a = vr[1], b = vi[1]; vr[1] = RH*(a + sign*b); vi[1] = RH*(b - sign*a); }
    { float a = vr[2], b = vi[2]; vr[2] = sign*b;          vi[2] = -sign*a; }
    { float a = vr[3], b = vi[3]; vr[3] = RH*(sign*b - a); vi[3] = RH*(-b - sign*a); }
    float q0r = ur[0]+ur[2], q0i = ui[0]+ui[2];
    float q1r = ur[1]+ur[3], q1i = ui[1]+ui[3];
    float r0r = ur[0]-ur[2], r0i = ui[0]-ui[2];
    float d1r = ur[1]-ur[3], d1i = ui[1]-ui[3];
    float r1r = sign*d1i,    r1i = -sign*d1r;
    xr[0] = q0r+q1r; xi[0] = q0i+q1i;
    xr[2] = r0r+r1r; xi[2] = r0i+r1i;
    xr[4] = q0r-q1r; xi[4] = q0i-q1i;
    xr[6] = r0r-r1r; xi[6] = r0i-r1i;
    q0r = vr[0]+vr[2]; q0i = vi[0]+vi[2];
    q1r = vr[1]+vr[3]; q1i = vi[1]+vi[3];
    r0r = vr[0]-vr[2]; r0i = vi[0]-vi[2];
    d1r = vr[1]-vr[3]; d1i = vi[1]-vi[3];
    r1r = sign*d1i;    r1i = -sign*d1r;
    xr[1] = q0r+q1r; xi[1] = q0i+q1i;
    xr[3] = r0r+r1r; xi[3] = r0i+r1i;
    xr[5] = q0r-q1r; xi[5] = q0i-q1i;
    xr[7] = r0r-r1r; xi[7] = r0i-r1i;
}

// ---------------- prep ----------------
__global__ void prep_kernel(const float* __restrict__ cw, const float* __restrict__ pw) {
    int tid = blockIdx.x*blockDim.x + threadIdx.x;
    int stride = gridDim.x*blockDim.x;
    if (tid < 4096) {
        float s, c;
        sincosf(-6.28318530717958647692f * (float)tid / 4096.f, &s, &c);
        g_twid[tid] = make_float2(c, s);
    }
    for (int e = tid; e < 9*256*256; e += stride) {
        int tap = e / (256*256);
        int rem = e - tap*256*256;
        int co = rem >> 8;
        int cin = (rem & 255) * 2;
        float w0 = cw[(co*512 + cin)*9 + tap];
        float w1 = cw[(co*512 + cin + 1)*9 + tap];
        g_wt16[e] = h2bits(__floats2half2_rn(w0, w1));
    }
    for (int e = tid; e < 512*256; e += stride) {
        int o = e >> 8, c = (e & 255)*2;
        g_pw16[e] = h2bits(__floats2half2_rn(pw[o*512 + c], pw[o*512 + c + 1]));
    }
}

// ---------------- conv via fp16 mma m16n8k16: 128co x 128pos, 4 warps 64x64 ------
__global__ void conv_mma_kernel(const float* __restrict__ x, const float* __restrict__ cb,
                                const float* __restrict__ bg, const float* __restrict__ bb,
                                const float* __restrict__ bm, const float* __restrict__ bv) {
    __shared__ uint32_t xs[128][20];
    __shared__ uint32_t ws[128][20];
    int b = blockIdx.z, pt = blockIdx.y, ct = blockIdx.x;
    int tid = threadIdx.x, lane = tid & 31, warp = tid >> 5;
    int wm = warp & 1, wn = warp >> 1;
    int g = lane >> 2, t = lane & 3;
    float acc[4][8][4];
#pragma unroll
    for (int i = 0; i < 4; i++)
#pragma unroll
        for (int j = 0; j < 8; j++)
#pragma unroll
            for (int q = 0; q < 4; q++) acc[i][j][q] = 0.f;

    int pos0 = pt*128;
    for (int tap = 0; tap < 9; tap++) {
        int dh = 3*((tap/3) - 1), dw = 3*((tap%3) - 1);
        const uint32_t* wtp = g_wt16 + ((size_t)tap*256 + ct*128)*256;
        for (int kc = 0; kc < 512; kc += 32) {
            __syncthreads();
#pragma unroll
            for (int r = 0; r < 8; r++) {
                int e = tid + r*128;
                int pos = e >> 3, ch = e & 7;
                int gp = pos0 + pos;
                int ih = (gp >> 6) + dh, iw = (gp & 63) + dw;
                uint2 u = make_uint2(0u, 0u);
                if ((unsigned)ih < 64u && (unsigned)iw < 64u) {
                    float4 v = *(const float4*)&x[((size_t)(b*HW_) + ih*64 + iw)*C_ + kc + ch*4];
                    u.x = h2bits(__floats2half2_rn(v.x, v.y));
                    u.y = h2bits(__floats2half2_rn(v.z, v.w));
                }
                *(uint2*)&xs[pos][ch*2] = u;
            }
#pragma unroll
            for (int r = 0; r < 4; r++) {
                int e = tid + r*128;
                int co = e >> 2, ch = e & 3;
                *(uint4*)&ws[co][ch*4] =
                    *(const uint4*)&wtp[(size_t)co*256 + (kc >> 1) + ch*4];
            }
            __syncthreads();
#pragma unroll
            for (int ks = 0; ks < 2; ks++) {
                int kb = ks*8 + t;
                uint32_t a[4][4];
#pragma unroll
                for (int mi = 0; mi < 4; mi++) {
                    int m0 = wm*64 + mi*16 + g;
                    a[mi][0] = ws[m0][kb];
                    a[mi][1] = ws[m0+8][kb];
                    a[mi][2] = ws[m0][kb+4];
                    a[mi][3] = ws[m0+8][kb+4];
                }
#pragma unroll
                for (int ni = 0; ni < 8; ni++) {
                    int n0 = wn*64 + ni*8 + g;
                    uint32_t b0 = xs[n0][kb];
                    uint32_t b1 = xs[n0][kb+4];
                    mma16h(acc[0][ni], a[0], b0, b1);
                    mma16h(acc[1][ni], a[1], b0, b1);
                    mma16h(acc[2][ni], a[2], b0, b1);
                    mma16h(acc[3][ni], a[3], b0, b1);
                }
            }
        }
    }
#pragma unroll
    for (int mi = 0; mi < 4; mi++) {
#pragma unroll
        for (int half = 0; half < 2; half++) {
            int o = ct*128 + wm*64 + mi*16 + g + half*8;
            float s = bg[o] * rsqrtf(bv[o] + 1e-5f);
            float t0 = cb[o]*s + bb[o] - bm[o]*s;
            float* dst = g_y + ((size_t)(b*DD_ + o))*HW_;
#pragma unroll
            for (int ni = 0; ni < 8; ni++) {
                int pos = pos0 + wn*64 + ni*8 + 2*t;
                float v0 = fmaxf(acc[mi][ni][half*2+0]*s + t0, 0.f);
                float v1 = fmaxf(acc[mi][ni][half*2+1]*s + t0, 0.f);
                *(float2*)&dst[pos] = make_float2(v0, v1);
            }
        }
    }
}

// ---------------- 64x64 2D FFT, radix-8 DIF ----------------
__device__ __forceinline__ void fft64_2d_dif8(float* sr, float* si, int tid, float sign) {
    float xr[8], xi[8];
    __syncthreads();
    {
        int row = tid & 63, j = tid >> 6;
        int base = row*65 + j;
#pragma unroll
        for (int m = 0; m < 8; m++) { xr[m] = sr[base + 8*m]; xi[m] = si[base + 8*m]; }
        bfly8(xr, xi, sign);
#pragma unroll
        for (int m = 1; m < 8; m++) {
            float2 w = g_twid[j*m*64];
            float wr = w.x, wi = sign*w.y;
            float a = xr[m], bb2 = xi[m];
            xr[m] = a*wr - bb2*wi; xi[m] = a*wi + bb2*wr;
        }
#pragma unroll
        for (int m = 0; m < 8; m++) { sr[base + 8*m] = xr[m]; si[base + 8*m] = xi[m]; }
    }
    __syncthreads();
    {
        int row = tid & 63, g = tid >> 6;
        int base = row*65 + g*8;
#pragma unroll
        for (int m = 0; m < 8; m++) { xr[m] = sr[base + m]; xi[m] = si[base + m]; }
        bfly8(xr, xi, sign);
#pragma unroll
        for (int m = 0; m < 8; m++) { sr[base + m] = xr[m]; si[base + m] = xi[m]; }
    }
    __syncthreads();
    {
        int col = tid & 63, j = tid >> 6;
        int base = j*65 + col;
#pragma unroll
        for (int m = 0; m < 8; m++) { xr[m] = sr[base + 520*m]; xi[m] = si[base + 520*m]; }
        bfly8(xr, xi, sign);
#pragma unroll
        for (int m = 1; m < 8; m++) {
            float2 w = g_twid[j*m*64];
            float wr = w.x, wi = sign*w.y;
            float a = xr[m], bb2 = xi[m];
            xr[m] = a*wr - bb2*wi; xi[m] = a*wi + bb2*wr;
        }
#pragma unroll
        for (int m = 0; m < 8; m++) { sr[base + 520*m] = xr[m]; si[base + 520*m] = xi[m]; }
    }
    __syncthreads();
    {
        int col = tid & 63, g = tid >> 6;
        int base = (g*8)*65 + col;
#pragma unroll
        for (int m = 0; m < 8; m++) { xr[m] = sr[base + 65*m]; xi[m] = si[base + 65*m]; }
        bfly8(xr, xi, sign);
#pragma unroll
        for (int m = 0; m < 8; m++) { sr[base + 65*m] = xr[m]; si[base + 65*m] = xi[m]; }
    }
    __syncthreads();
}

// forward fft2 of real conv output, TWO channels per block via packing
__global__ void fft2_fwd_kernel() {
    __shared__ float sr[64*65], si[64*65];
    int bp = blockIdx.x;
    int b = bp >> 7, cp = bp & 127;
    int c0 = cp*2;
    int tid = threadIdx.x;
    const float* s0 = g_y + ((size_t)(b*DD_ + c0))*HW_;
    const float* s1 = s0 + HW_;
    for (int e = tid; e < 4096; e += 512) {
        int r = e >> 6, w = e & 63;
        sr[r*65 + w] = s0[e];
        si[r*65 + w] = s1[e];
    }
    fft64_2d_dif8(sr, si, tid, 1.f);
    float* f0r = g_fre + ((size_t)(b*DD_ + c0))*HW_;
    float* f0i = g_fim + ((size_t)(b*DD_ + c0))*HW_;
    float* f1r = f0r + HW_;
    float* f1i = f0i + HW_;
    for (int e = tid; e < 4096; e += 512) {
        int r = e >> 6, w = e & 63;
        int rn = (64 - r) & 63, wn = (64 - w) & 63;
        float Zr  = sr[dig8_6(r)*65 + dig8_6(w)],   Zi  = si[dig8_6(r)*65 + dig8_6(w)];
        float Z2r = sr[dig8_6(rn)*65 + dig8_6(wn)], Z2i = si[dig8_6(rn)*65 + dig8_6(wn)];
        f0r[e] = 0.5f*(Zr + Z2r);
        f0i[e] = 0.5f*(Zi - Z2i);
        f1r[e] = 0.5f*(Zi + Z2i);
        f1i[e] = 0.5f*(Z2r - Zr);
    }
}

// ---------------- attention scores, fp16 mma ----------------
__global__ void attn_gemm64_kernel() {
    __shared__ uint32_t gs[64][20];
    int bh = blockIdx.x, kq = blockIdx.y;
    int tid = threadIdx.x, lane = tid & 31, warp = tid >> 5;
    int wm = warp & 3, wn = warp >> 2;
    int g = lane >> 2, t = lane & 3;
    float acc[4][4];
#pragma unroll
    for (int i = 0; i < 4; i++)
#pragma unroll
        for (int q = 0; q < 4; q++) acc[i][q] = 0.f;
    const float* fr = g_fre + (size_t)bh*CPH_*HW_;
    const float* fi = g_fim + (size_t)bh*CPH_*HW_;
    int kbeg = kq*(HW_/KSPLIT), kend = kbeg + HW_/KSPLIT;
    for (int k0 = kbeg; k0 < kend; k0 += 32) {
        __syncthreads();
#pragma unroll
        for (int r = 0; r < 2; r++) {
            int e = tid + r*256;
            int row = e >> 3, kqq = e & 7;
            const float* src = (row < 32) ? (fr + (size_t)row*HW_) : (fi + (size_t)(row-32)*HW_);
            float4 v = *(const float4*)&src[k0 + kqq*4];
            uint2 u;
            u.x = h2bits(__floats2half2_rn(v.x, v.y));
            u.y = h2bits(__floats2half2_rn(v.z, v.w));
            *(uint2*)&gs[row][kqq*2] = u;
        }
        __syncthreads();
#pragma unroll
        for (int ks = 0; ks < 2; ks++) {
            int kb = ks*8 + t;
            uint32_t a[4];
            a[0] = gs[wm*16+g][kb];
            a[1] = gs[wm*16+g+8][kb];
            a[2] = gs[wm*16+g][kb+4];
            a[3] = gs[wm*16+g+8][kb+4];
#pragma unroll
            for (int ni = 0; ni < 4; ni++) {
                int n0 = wn*32 + ni*8 + g;
                mma16h(acc[ni], a, gs[n0][kb], gs[n0][kb+4]);
            }
        }
    }
    float* S = g_attnS + ((size_t)(kq*64 + bh))*4096;
#pragma unroll
    for (int ni = 0; ni < 4; ni++) {
        int d = wn*32 + ni*8 + 2*t;
        int c0 = wm*16 + g;
        *(float2*)&S[(size_t)c0*64 + d]     = make_float2(acc[ni][0], acc[ni][1]);
        *(float2*)&S[(size_t)(c0+8)*64 + d] = make_float2(acc[ni][2], acc[ni][3]);
    }
}

// ---------------- attn finalize ----------------
__global__ void attn_fin_kernel(const float* __restrict__ temp) {
    int bh = blockIdx.x;
    int head = bh & 7;
    int tid = threadIdx.x;
    __shared__ float Ss[4096];
    __shared__ float ar_[32*33], ai_[32*33];
    __shared__ float inv[32];
    for (int p = tid; p < 4096; p += 256) {
        float s = 0.f;
#pragma unroll
        for (int q = 0; q < KSPLIT; q++)
            s += g_attnS[((size_t)(q*64 + bh))*4096 + p];
        Ss[p] = s;
    }
    __syncthreads();
    if (tid < 32)
        inv[tid] = rsqrtf(fmaxf(Ss[tid*64 + tid] + Ss[(32+tid)*64 + 32+tid], 1e-24f));
    __syncthreads();
    float tmp = temp[head];
    for (int p = tid; p < 1024; p += 256) {
        int cc = p >> 5, dd = p & 31;
        float sre = Ss[cc*64 + dd] - Ss[(32+cc)*64 + (32+dd)];
        float sim = Ss[cc*64 + (32+dd)] + Ss[(32+cc)*64 + dd];
        float sc = inv[cc] * inv[dd] * tmp;
        ar_[cc*33+dd] = sre*sc;
        ai_[cc*33+dd] = sim*sc;
    }
    __syncthreads();
    int w = tid >> 5, lane = tid & 31;
    for (int r = w; r < 32; r += 8) {
        float vr = ar_[r*33+lane];
        float m = vr;
        for (int o = 16; o; o >>= 1) m = fmaxf(m, __shfl_xor_sync(0xffffffffu, m, o));
        float e = expf(vr - m); float s = e;
        for (int o = 16; o; o >>= 1) s += __shfl_xor_sync(0xffffffffu, s, o);
        ar_[r*33+lane] = e / s;
        float vi = ai_[r*33+lane];
        m = vi;
        for (int o = 16; o; o >>= 1) m = fmaxf(m, __shfl_xor_sync(0xffffffffu, m, o));
        e = expf(vi - m); s = e;
        for (int o = 16; o; o >>= 1) s += __shfl_xor_sync(0xffffffffu, s, o);
        ai_[r*33+lane] = e / s;
    }
    __syncthreads();
    for (int p = tid; p < 1024; p += 256) {
        int k = p >> 5, dd = p & 31;
        float accr = 0.f, acci = 0.f;
#pragma unroll
        for (int cc = 0; cc < 32; cc++) {
            float2 w2 = g_twid[((k*cc) & 31) * 128];
            float wr = w2.x, wi = -w2.y;
            float xr = ar_[cc*33+dd], xi = ai_[cc*33+dd];
            accr += wr*xr - wi*xi;
            acci += wr*xi + wi*xr;
        }
        g_attn2[(size_t)bh*1024 + p] = make_float2(accr*(1.f/32.f), acci*(1.f/32.f));
    }
}

// ---------------- attn apply ----------------
__global__ void attn_apply_kernel() {
    __shared__ float sfr[32][132], sfi[32][132];
    __shared__ float2 a2s[32][32];
    int nc = blockIdx.x, bh = blockIdx.y;
    int tid = threadIdx.x;
    for (int p = tid; p < 1024; p += 256)
        a2s[p>>5][p&31] = g_attn2[(size_t)bh*1024 + p];
    const float* fr = g_fre + (size_t)bh*CPH_*HW_ + nc*128;
    const float* fi = g_fim + (size_t)bh*CPH_*HW_ + nc*128;
    for (int e = tid; e < 1024; e += 256) {
        int d = e >> 5, j = e & 31;
        *(float4*)&sfr[d][j*4] = *(const float4*)&fr[(size_t)d*HW_ + j*4];
        *(float4*)&sfi[d][j*4] = *(const float4*)&fi[(size_t)d*HW_ + j*4];
    }
    __syncthreads();
    int tx = tid & 15, ty = tid >> 4;
    int k0 = ty*2, n0 = tx*8;
    float ar0[8], ai0[8], ar1[8], ai1[8];
#pragma unroll
    for (int j = 0; j < 8; j++) { ar0[j]=0.f; ai0[j]=0.f; ar1[j]=0.f; ai1[j]=0.f; }
#pragma unroll
    for (int d = 0; d < 32; d++) {
        float2 a0 = a2s[k0][d], a1 = a2s[k0+1][d];
        float4 f0 = *(float4*)&sfr[d][n0], f1 = *(float4*)&sfr[d][n0+4];
        float4 h0 = *(float4*)&sfi[d][n0], h1 = *(float4*)&sfi[d][n0+4];
        float frv[8] = {f0.x,f0.y,f0.z,f0.w,f1.x,f1.y,f1.z,f1.w};
        float fiv[8] = {h0.x,h0.y,h0.z,h0.w,h1.x,h1.y,h1.z,h1.w};
#pragma unroll
        for (int j = 0; j < 8; j++) {
            ar0[j] += a0.x*frv[j] - a0.y*fiv[j];
            ai0[j] += a0.x*fiv[j] + a0.y*frv[j];
            ar1[j] += a1.x*frv[j] - a1.y*fiv[j];
            ai1[j] += a1.x*fiv[j] + a1.y*frv[j];
        }
    }
    size_t base0 = ((size_t)(bh*32 + k0))*HW_ + nc*128 + n0;
    size_t base1 = base0 + HW_;
    *(float4*)&g_or[base0]   = make_float4(ar0[0],ar0[1],ar0[2],ar0[3]);
    *(float4*)&g_or[base0+4] = make_float4(ar0[4],ar0[5],ar0[6],ar0[7]);
    *(float4*)&g_oi[base0]   = make_float4(ai0[0],ai0[1],ai0[2],ai0[3]);
    *(float4*)&g_oi[base0+4] = make_float4(ai0[4],ai0[5],ai0[6],ai0[7]);
    *(float4*)&g_or[base1]   = make_float4(ar1[0],ar1[1],ar1[2],ar1[3]);
    *(float4*)&g_or[base1+4] = make_float4(ar1[4],ar1[5],ar1[6],ar1[7]);
    *(float4*)&g_oi[base1]   = make_float4(ai1[0],ai1[1],ai1[2],ai1[3]);
    *(float4*)&g_oi[base1+4] = make_float4(ai1[4],ai1[5],ai1[6],ai1[7]);
}

// ---------------- row ifft4096 radix-8 DIF + abs + residual ----------------
#define SKW(i) ((i) + ((i) >> 7))
__global__ void ifft_row_kernel(const float* __restrict__ x) {
    __shared__ float sr[4128], si[4128];
    int gid = blockIdx.x;
    int b = gid >> 8, cg = gid & 255;
    int tid = threadIdx.x;
    const float* pr = g_or + (size_t)gid*HW_;
    const float* pi = g_oi + (size_t)gid*HW_;
    for (int nn = tid; nn < 4096; nn += 512) {
        int d = SKW(nn);
        sr[d] = pr[nn];
        si[d] = pi[nn];
    }
    float xr[8], xi[8];
#define IFFT_STAGE(L, LG, TS)                                                       \
    {                                                                               \
        __syncthreads();                                                            \
        int j = tid & ((L) - 1);                                                    \
        int g = tid >> (LG);                                                        \
        int base = g*((L) << 3) + j;                                                \
        _Pragma("unroll")                                                           \
        for (int m = 0; m < 8; m++) {                                               \
            int idx = SKW(base + m*(L));                                            \
            xr[m] = sr[idx]; xi[m] = si[idx];                                       \
        }                                                                           \
        bfly8(xr, xi, -1.f);                                                        \
        if ((L) > 1) {                                                              \
            _Pragma("unroll")                                                       \
            for (int m = 1; m < 8; m++) {                                           \
                float2 w = g_twid[j*m*(TS)];                                        \
                float wr = w.x, wi = -w.y;                                          \
                float a = xr[m], bb2 = xi[m];                                       \
                xr[m] = a*wr - bb2*wi; xi[m] = a*wi + bb2*wr;                       \
            }                                                                       \
        }                                                                           \
        _Pragma("unroll")                                                           \
        for (int m = 0; m < 8; m++) {                                               \
            int idx = SKW(base + m*(L));                                            \
            sr[idx] = xr[m]; si[idx] = xi[m];                                       \
        }                                                                           \
    }
    IFFT_STAGE(512, 9, 1)
    IFFT_STAGE(64, 6, 8)
    IFFT_STAGE(8, 3, 64)
    IFFT_STAGE(1, 0, 0)
#undef IFFT_STAGE
    __syncthreads();
    for (int nn = tid; nn < 4096; nn += 512) {
        int d = SKW(dig8_12(nn));
        float re = sr[d], im = si[d];
        float v = sqrtf(re*re + im*im) * (1.f/4096.f)
                + x[((size_t)b*HW_ + nn)*C_ + cg];
        g_out2[((size_t)(b*512) + cg)*HW_ + nn] = v;
    }
}

// ---------------- gating MLP stage 1 ----------------
__global__ void g1_kernel(const float* __restrict__ w1w, const float* __restrict__ w1b,
                          const float* __restrict__ bg, const float* __restrict__ bb,
                          const float* __restrict__ bm, const float* __restrict__ bv) {
    __shared__ float sw[HID_*DD_];
    __shared__ float sa[HID_], st[HID_];
    int b = blockIdx.y;
    int tid = threadIdx.x;
    int n = blockIdx.x*256 + tid;
    for (int e = tid; e < HID_*DD_; e += 256) sw[e] = w1w[e];
    if (tid < HID_) {
        float s = bg[tid] * rsqrtf(bv[tid] + 1e-5f);
        sa[tid] = s;
        st[tid] = w1b[tid]*s + bb[tid] - bm[tid]*s;
    }
    __syncthreads();
    float acc[HID_];
#pragma unroll
    for (int o = 0; o < HID_; o++) acc[o] = 0.f;
    const float* fr = g_fre + (size_t)b*DD_*HW_ + n;
    for (int c = 0; c < DD_; c++) {
        float v = fr[(size_t)c*HW_];
#pragma unroll
        for (int o = 0; o < HID_; o++) acc[o] += v * sw[o*DD_ + c];
    }
#pragma unroll
    for (int o = 0; o < HID_; o++)
        g_g1[((size_t)(b*HID_ + o))*HW_ + n] = fmaxf(acc[o]*sa[o] + st[o], 0.f);
}

// ---------------- fused gate + ifft2 + abs + residual ----------------
__global__ void ifft2_gate_kernel(const float* __restrict__ x,
                                  const float* __restrict__ w2w,
                                  const float* __restrict__ w2b) {
    __shared__ float sr[64*65], si[64*65];
    __shared__ float w2s[HID_];
    int bc = blockIdx.x;
    int b = bc >> 8, c = bc & 255;
    int tid = threadIdx.x;
    if (tid < HID_) w2s[tid] = w2w[c*HID_ + tid];
    __syncthreads();
    float bias = w2b[c];
    float acc[8];
#pragma unroll
    for (int j = 0; j < 8; j++) acc[j] = bias;
    const float* g1p = g_g1 + (size_t)b*HID_*HW_;
#pragma unroll
    for (int o = 0; o < HID_; o++) {
        float w = w2s[o];
        const float* row = g1p + (size_t)o*HW_;
#pragma unroll
        for (int j = 0; j < 8; j++) acc[j] += w * row[tid + j*512];
    }
    const float* fre = g_fre + (size_t)bc*HW_;
    const float* fim = g_fim + (size_t)bc*HW_;
#pragma unroll
    for (int j = 0; j < 8; j++) {
        int e = tid + j*512;
        float gt = 1.f / (1.f + expf(-acc[j]));
        int r = e >> 6, w = e & 63;
        sr[r*65 + w] = gt * fre[e];
        si[r*65 + w] = gt * fim[e];
    }
    fft64_2d_dif8(sr, si, tid, -1.f);
    for (int e = tid; e < 4096; e += 512) {
        int r = e >> 6, w = e & 63;
        int d = dig8_6(r)*65 + dig8_6(w);
        float re = sr[d], im = si[d];
        float v = sqrtf(re*re + im*im) * (1.f/4096.f)
                + x[((size_t)b*HW_ + e)*C_ + (256 + c)];
        g_out2[((size_t)(b*512 + 256 + c))*HW_ + e] = v;
    }
}

// ---------------- final projection via fp16 mma, 4 warps of 64x64 ----------------
__global__ void proj_mma_kernel(const float* __restrict__ pb, float* __restrict__ out) {
    __shared__ uint32_t xs[128][20];
    __shared__ uint32_t ws[128][20];
    int b = blockIdx.z, nt = blockIdx.y, ot = blockIdx.x;
    int tid = threadIdx.x, lane = tid & 31, warp = tid >> 5;
    int wm = warp & 1, wn = warp >> 1;
    int g = lane >> 2, t = lane & 3;
    float acc[4][8][4];
#pragma unroll
    for (int i = 0; i < 4; i++)
#pragma unroll
        for (int j = 0; j < 8; j++)
#pragma unroll
            for (int q = 0; q < 4; q++) acc[i][j][q] = 0.f;

    int n0g = nt*128, o0g = ot*128;
    for (int kc = 0; kc < 512; kc += 32) {
        __syncthreads();
        // xs fill: 16 k-pairs x 32 n4-groups = 512 items
#pragma unroll
        for (int r = 0; r < 4; r++) {
            int e = tid + r*128;
            int kp = e >> 5, n4 = e & 31;
            const float* row0 = &g_out2[((size_t)(b*512 + kc + 2*kp))*HW_ + n0g + n4*4];
            float4 v0 = *(const float4*)row0;
            float4 v1 = *(const float4*)(row0 + HW_);
            xs[n4*4+0][kp] = h2bits(__floats2half2_rn(v0.x, v1.x));
            xs[n4*4+1][kp] = h2bits(__floats2half2_rn(v0.y, v1.y));
            xs[n4*4+2][kp] = h2bits(__floats2half2_rn(v0.z, v1.z));
            xs[n4*4+3][kp] = h2bits(__floats2half2_rn(v0.w, v1.w));
        }
        // ws fill: pre-packed half2 weights
#pragma unroll
        for (int r = 0; r < 4; r++) {
            int e = tid + r*128;
            int o = e >> 2, ch = e & 3;
            *(uint4*)&ws[o][ch*4] =
                *(const uint4*)&g_pw16[(size_t)(o0g + o)*256 + (kc >> 1) + ch*4];
        }
        __syncthreads();
#pragma unroll
        for (int ks = 0; ks < 2; ks++) {
            int kb = ks*8 + t;
            uint32_t a[4][4];
#pragma unroll
            for (int mi = 0; mi < 4; mi++) {
                int m0 = wm*64 + mi*16 + g;
                a[mi][0] = xs[m0][kb];
                a[mi][1] = xs[m0+8][kb];
                a[mi][2] = xs[m0][kb+4];
                a[mi][3] = xs[m0+8][kb+4];
            }
#pragma unroll
            for (int ni = 0; ni < 8; ni++) {
                int n0 = wn*64 + ni*8 + g;
                uint32_t b0 = ws[n0][kb];
                uint32_t b1 = ws[n0][kb+4];
                mma16h(acc[0][ni], a[0], b0, b1);
                mma16h(acc[1][ni], a[1], b0, b1);
                mma16h(acc[2][ni], a[2], b0, b1);
                mma16h(acc[3][ni], a[3], b0, b1);
            }
        }
    }
#pragma unroll
    for (int mi = 0; mi < 4; mi++) {
#pragma unroll
        for (int half = 0; half < 2; half++) {
            int n = n0g + wm*64 + mi*16 + g + half*8;
#pragma unroll
            for (int ni = 0; ni < 8; ni++) {
                int o = o0g + wn*64 + ni*8 + 2*t;
                float2 bias = *(const float2*)&pb[o];
                float v0 = acc[mi][ni][half*2+0] + bias.x;
                float v1 = acc[mi][ni][half*2+1] + bias.y;
                *(float2*)&out[((size_t)b*HW_ + n)*C_ + o] = make_float2(v0, v1);
            }
        }
    }
}

// ---------------- launch ----------------
extern "C" void kernel_launch(void* const* d_in, const int* in_sizes, int n_in,
                              void* d_out, int out_size) {
    const float* x       = (const float*)d_in[0];
    const float* conv2_w = (const float*)d_in[1];
    const float* conv2_b = (const float*)d_in[2];
    const float* bn2_g   = (const float*)d_in[3];
    const float* bn2_b   = (const float*)d_in[4];
    const float* bn2_m   = (const float*)d_in[5];
    const float* bn2_v   = (const float*)d_in[6];
    const float* temp    = (const float*)d_in[7];
    const float* w1_w    = (const float*)d_in[8];
    const float* w1_b    = (const float*)d_in[9];
    const float* bnw_g   = (const float*)d_in[10];
    const float* bnw_b   = (const float*)d_in[11];
    const float* bnw_m   = (const float*)d_in[12];
    const float* bnw_v   = (const float*)d_in[13];
    const float* w2_w    = (const float*)d_in[14];
    const float* w2_b    = (const float*)d_in[15];
    const float* proj_w  = (const float*)d_in[16];
    const float* proj_b  = (const float*)d_in[17];
    float* out = (float*)d_out;

    prep_kernel<<<1024, 256>>>(conv2_w, proj_w);
    conv_mma_kernel<<<dim3(2, 32, 8), 128>>>(x, conv2_b, bn2_g, bn2_b, bn2_m, bn2_v);
    fft2_fwd_kernel<<<1024, 512>>>();
    attn_gemm64_kernel<<<dim3(64, KSPLIT), 256>>>();
    attn_fin_kernel<<<64, 256>>>(temp);
    attn_apply_kernel<<<dim3(32, 64), 256>>>();
    ifft_row_kernel<<<2048, 512>>>(x);
    g1_kernel<<<dim3(16, 8), 256>>>(w1_w, w1_b, bnw_g, bnw_b, bnw_m, bnw_v);
    ifft2_gate_kernel<<<2048, 512>>>(x, w2_w, w2_b);
    proj_mma_kernel<<<dim3(4, 32, 8), 128>>>(proj_b, out);
}

// round 16
// speedup vs baseline: 1.6111x; 1.0333x over previous
#include <cuda_runtime.h>
#include <cuda_fp16.h>
#include <math.h>
#include <stdint.h>

#define B_  8
#define C_  512
#define DD_ 256
#define HW_ 4096
#define HEADS_ 8
#define CPH_ 32
#define HID_ 16
#define KSPLIT 8

// ---------------- scratch ----------------
__device__ __align__(16) uint32_t g_wt16[9*256*256];  // conv weights half2 [tap][co][cin/2]
__device__ __align__(16) uint32_t g_pw16[512*256];    // proj weights half2 [o][c/2]
__device__ __align__(16) __half  g_x16[(size_t)B_*HW_*C_];   // x as half, same layout
__device__ float2 g_twid[4096];
__device__ float  g_y   [(size_t)B_*DD_*HW_];
__device__ float  g_fre [(size_t)B_*DD_*HW_];
__device__ float  g_fim [(size_t)B_*DD_*HW_];
__device__ float  g_g1  [(size_t)B_*HID_*HW_];
__device__ float  g_attnS[KSPLIT*64*64*64];
__device__ float2 g_attn2[64*1024];
__device__ float  g_or  [(size_t)B_*DD_*HW_];
__device__ float  g_oi  [(size_t)B_*DD_*HW_];
__device__ __align__(16) __half g_out2h[(size_t)B_*C_*HW_];  // concat result as half

// ---------------- mma helpers ----------------
__device__ __forceinline__ void mma16h(float c[4], const uint32_t a[4], uint32_t b0, uint32_t b1) {
    asm volatile("mma.sync.aligned.m16n8k16.row.col.f32.f16.f16.f32 "
        "{%0,%1,%2,%3}, {%4,%5,%6,%7}, {%8,%9}, {%0,%1,%2,%3};"
        : "+f"(c[0]), "+f"(c[1]), "+f"(c[2]), "+f"(c[3])
        : "r"(a[0]), "r"(a[1]), "r"(a[2]), "r"(a[3]), "r"(b0), "r"(b1));
}
__device__ __forceinline__ uint32_t h2bits(__half2 h) {
    return *(uint32_t*)&h;
}
// octal digit reversals
__device__ __forceinline__ int dig8_6(int x)  { return ((x & 7) << 3) | (x >> 3); }
__device__ __forceinline__ int dig8_12(int x) {
    return ((x & 7) << 9) | (((x >> 3) & 7) << 6) | (((x >> 6) & 7) << 3) | (x >> 9);
}

// ---------------- radix-8 DIF butterfly ----------------
__device__ __forceinline__ void bfly8(float xr[8], float xi[8], float sign) {
    const float RH = 0.70710678118654752440f;
    float ur[4], ui[4], vr[4], vi[4];
#pragma unroll
    for (int m = 0; m < 4; m++) {
        ur[m] = xr[m] + xr[m+4]; ui[m] = xi[m] + xi[m+4];
        vr[m] = xr[m] - xr[m+4]; vi[m] = xi[m] - xi[m+4];
    }
    { float a = vr[1], b = vi[1]; vr[1] = RH*(a + sign*b); vi[1] = RH*(b - sign*a); }
    { float a = vr[2], b = vi[2]; vr[2] = sign*b;          vi[2] = -sign*a; }
    { float a = vr[3], b = vi[3]; vr[3] = RH*(sign*b - a); vi[3] = RH*(-b - sign*a); }
    float q0r = ur[0]+ur[2], q0i = ui[0]+ui[2];
    float q1r = ur[1]+ur[3], q1i = ui[1]+ui[3];
    float r0r = ur[0]-ur[2], r0i = ui[0]-ui[2];
    float d1r = ur[1]-ur[3], d1i = ui[1]-ui[3];
    float r1r = sign*d1i,    r1i = -sign*d1r;
    xr[0] = q0r+q1r; xi[0] = q0i+q1i;
    xr[2] = r0r+r1r; xi[2] = r0i+r1i;
    xr[4] = q0r-q1r; xi[4] = q0i-q1i;
    xr[6] = r0r-r1r; xi[6] = r0i-r1i;
    q0r = vr[0]+vr[2]; q0i = vi[0]+vi[2];
    q1r = vr[1]+vr[3]; q1i = vi[1]+vi[3];
    r0r = vr[0]-vr[2]; r0i = vi[0]-vi[2];
    d1r = vr[1]-vr[3]; d1i = vi[1]-vi[3];
    r1r = sign*d1i;    r1i = -sign*d1r;
    xr[1] = q0r+q1r; xi[1] = q0i+q1i;
    xr[3] = r0r+r1r; xi[3] = r0i+r1i;
    xr[5] = q0r-q1r; xi[5] = q0i-q1i;
    xr[7] = r0r-r1r; xi[7] = r0i-r1i;
}

// ---------------- prep ----------------
__global__ void prep_kernel(const float* __restrict__ cw, const float* __restrict__ pw) {
    int tid = blockIdx.x*blockDim.x + threadIdx.x;
    int stride = gridDim.x*blockDim.x;
    if (tid < 4096) {
        float s, c;
        sincosf(-6.28318530717958647692f * (float)tid / 4096.f, &s, &c);
        g_twid[tid] = make_float2(c, s);
    }
    for (int e = tid; e < 9*256*256; e += stride) {
        int tap = e / (256*256);
        int rem = e - tap*256*256;
        int co = rem >> 8;
        int cin = (rem & 255) * 2;
        float w0 = cw[(co*512 + cin)*9 + tap];
        float w1 = cw[(co*512 + cin + 1)*9 + tap];
        g_wt16[e] = h2bits(__floats2half2_rn(w0, w1));
    }
    for (int e = tid; e < 512*256; e += stride) {
        int o = e >> 8, c = (e & 255)*2;
        g_pw16[e] = h2bits(__floats2half2_rn(pw[o*512 + c], pw[o*512 + c + 1]));
    }
}

// ---------------- x -> half pre-convert (coalesced) ----------------
__global__ void x16_kernel(const float* __restrict__ x) {
    size_t i = ((size_t)blockIdx.x*256 + threadIdx.x) * 4;
    float4 v = *(const float4*)&x[i];
    __half2* dst = (__half2*)&g_x16[i];
    dst[0] = __floats2half2_rn(v.x, v.y);
    dst[1] = __floats2half2_rn(v.z, v.w);
}

// ---------------- conv via fp16 mma m16n8k16: 128co x 128pos, 4 warps 64x64 ------
__global__ void conv_mma_kernel(const float* __restrict__ cb,
                                const float* __restrict__ bg, const float* __restrict__ bb,
                                const float* __restrict__ bm, const float* __restrict__ bv) {
    __shared__ uint32_t xs[128][20];
    __shared__ uint32_t ws[128][20];
    int b = blockIdx.z, pt = blockIdx.y, ct = blockIdx.x;
    int tid = threadIdx.x, lane = tid & 31, warp = tid >> 5;
    int wm = warp & 1, wn = warp >> 1;
    int g = lane >> 2, t = lane & 3;
    float acc[4][8][4];
#pragma unroll
    for (int i = 0; i < 4; i++)
#pragma unroll
        for (int j = 0; j < 8; j++)
#pragma unroll
            for (int q = 0; q < 4; q++) acc[i][j][q] = 0.f;

    int pos0 = pt*128;
    for (int tap = 0; tap < 9; tap++) {
        int dh = 3*((tap/3) - 1), dw = 3*((tap%3) - 1);
        const uint32_t* wtp = g_wt16 + ((size_t)tap*256 + ct*128)*256;
        for (int kc = 0; kc < 512; kc += 32) {
            __syncthreads();
#pragma unroll
            for (int r = 0; r < 8; r++) {
                int e = tid + r*128;
                int pos = e >> 3, ch = e & 7;
                int gp = pos0 + pos;
                int ih = (gp >> 6) + dh, iw = (gp & 63) + dw;
                uint2 u = make_uint2(0u, 0u);
                if ((unsigned)ih < 64u && (unsigned)iw < 64u)
                    u = *(const uint2*)&g_x16[((size_t)(b*HW_) + ih*64 + iw)*C_ + kc + ch*4];
                *(uint2*)&xs[pos][ch*2] = u;
            }
#pragma unroll
            for (int r = 0; r < 4; r++) {
                int e = tid + r*128;
                int co = e >> 2, ch = e & 3;
                *(uint4*)&ws[co][ch*4] =
                    *(const uint4*)&wtp[(size_t)co*256 + (kc >> 1) + ch*4];
            }
            __syncthreads();
#pragma unroll
            for (int ks = 0; ks < 2; ks++) {
                int kb = ks*8 + t;
                uint32_t a[4][4];
#pragma unroll
                for (int mi = 0; mi < 4; mi++) {
                    int m0 = wm*64 + mi*16 + g;
                    a[mi][0] = ws[m0][kb];
                    a[mi][1] = ws[m0+8][kb];
                    a[mi][2] = ws[m0][kb+4];
                    a[mi][3] = ws[m0+8][kb+4];
                }
#pragma unroll
                for (int ni = 0; ni < 8; ni++) {
                    int n0 = wn*64 + ni*8 + g;
                    uint32_t b0 = xs[n0][kb];
                    uint32_t b1 = xs[n0][kb+4];
                    mma16h(acc[0][ni], a[0], b0, b1);
                    mma16h(acc[1][ni], a[1], b0, b1);
                    mma16h(acc[2][ni], a[2], b0, b1);
                    mma16h(acc[3][ni], a[3], b0, b1);
                }
            }
        }
    }
#pragma unroll
    for (int mi = 0; mi < 4; mi++) {
#pragma unroll
        for (int half = 0; half < 2; half++) {
            int o = ct*128 + wm*64 + mi*16 + g + half*8;
            float s = bg[o] * rsqrtf(bv[o] + 1e-5f);
            float t0 = cb[o]*s + bb[o] - bm[o]*s;
            float* dst = g_y + ((size_t)(b*DD_ + o))*HW_;
#pragma unroll
            for (int ni = 0; ni < 8; ni++) {
                int pos = pos0 + wn*64 + ni*8 + 2*t;
                float v0 = fmaxf(acc[mi][ni][half*2+0]*s + t0, 0.f);
                float v1 = fmaxf(acc[mi][ni][half*2+1]*s + t0, 0.f);
                *(float2*)&dst[pos] = make_float2(v0, v1);
            }
        }
    }
}

// ---------------- 64x64 2D FFT, radix-8 DIF ----------------
__device__ __forceinline__ void fft64_2d_dif8(float* sr, float* si, int tid, float sign) {
    float xr[8], xi[8];
    __syncthreads();
    {
        int row = tid & 63, j = tid >> 6;
        int base = row*65 + j;
#pragma unroll
        for (int m = 0; m < 8; m++) { xr[m] = sr[base + 8*m]; xi[m] = si[base + 8*m]; }
        bfly8(xr, xi, sign);
#pragma unroll
        for (int m = 1; m < 8; m++) {
            float2 w = g_twid[j*m*64];
            float wr = w.x, wi = sign*w.y;
            float a = xr[m], bb2 = xi[m];
            xr[m] = a*wr - bb2*wi; xi[m] = a*wi + bb2*wr;
        }
#pragma unroll
        for (int m = 0; m < 8; m++) { sr[base + 8*m] = xr[m]; si[base + 8*m] = xi[m]; }
    }
    __syncthreads();
    {
        int row = tid & 63, g = tid >> 6;
        int base = row*65 + g*8;
#pragma unroll
        for (int m = 0; m < 8; m++) { xr[m] = sr[base + m]; xi[m] = si[base + m]; }
        bfly8(xr, xi, sign);
#pragma unroll
        for (int m = 0; m < 8; m++) { sr[base + m] = xr[m]; si[base + m] = xi[m]; }
    }
    __syncthreads();
    {
        int col = tid & 63, j = tid >> 6;
        int base = j*65 + col;
#pragma unroll
        for (int m = 0; m < 8; m++) { xr[m] = sr[base + 520*m]; xi[m] = si[base + 520*m]; }
        bfly8(xr, xi, sign);
#pragma unroll
        for (int m = 1; m < 8; m++) {
            float2 w = g_twid[j*m*64];
            float wr = w.x, wi = sign*w.y;
            float a = xr[m], bb2 = xi[m];
            xr[m] = a*wr - bb2*wi; xi[m] = a*wi + bb2*wr;
        }
#pragma unroll
        for (int m = 0; m < 8; m++) { sr[base + 520*m] = xr[m]; si[base + 520*m] = xi[m]; }
    }
    __syncthreads();
    {
        int col = tid & 63, g = tid >> 6;
        int base = (g*8)*65 + col;
#pragma unroll
        for (int m = 0; m < 8; m++) { xr[m] = sr[base + 65*m]; xi[m] = si[base + 65*m]; }
        bfly8(xr, xi, sign);
#pragma unroll
        for (int m = 0; m < 8; m++) { sr[base + 65*m] = xr[m]; si[base + 65*m] = xi[m]; }
    }
    __syncthreads();
}

// forward fft2 of real conv output, TWO channels per block via packing
__global__ void fft2_fwd_kernel() {
    __shared__ float sr[64*65], si[64*65];
    int bp = blockIdx.x;
    int b = bp >> 7, cp = bp & 127;
    int c0 = cp*2;
    int tid = threadIdx.x;
    const float* s0 = g_y + ((size_t)(b*DD_ + c0))*HW_;
    const float* s1 = s0 + HW_;
    for (int e = tid; e < 4096; e += 512) {
        int r = e >> 6, w = e & 63;
        sr[r*65 + w] = s0[e];
        si[r*65 + w] = s1[e];
    }
    fft64_2d_dif8(sr, si, tid, 1.f);
    float* f0r = g_fre + ((size_t)(b*DD_ + c0))*HW_;
    float* f0i = g_fim + ((size_t)(b*DD_ + c0))*HW_;
    float* f1r = f0r + HW_;
    float* f1i = f0i + HW_;
    for (int e = tid; e < 4096; e += 512) {
        int r = e >> 6, w = e & 63;
        int rn = (64 - r) & 63, wn = (64 - w) & 63;
        float Zr  = sr[dig8_6(r)*65 + dig8_6(w)],   Zi  = si[dig8_6(r)*65 + dig8_6(w)];
        float Z2r = sr[dig8_6(rn)*65 + dig8_6(wn)], Z2i = si[dig8_6(rn)*65 + dig8_6(wn)];
        f0r[e] = 0.5f*(Zr + Z2r);
        f0i[e] = 0.5f*(Zi - Z2i);
        f1r[e] = 0.5f*(Zi + Z2i);
        f1i[e] = 0.5f*(Z2r - Zr);
    }
}

// ---------------- attention scores, fp16 mma ----------------
__global__ void attn_gemm64_kernel() {
    __shared__ uint32_t gs[64][20];
    int bh = blockIdx.x, kq = blockIdx.y;
    int tid = threadIdx.x, lane = tid & 31, warp = tid >> 5;
    int wm = warp & 3, wn = warp >> 2;
    int g = lane >> 2, t = lane & 3;
    float acc[4][4];
#pragma unroll
    for (int i = 0; i < 4; i++)
#pragma unroll
        for (int q = 0; q < 4; q++) acc[i][q] = 0.f;
    const float* fr = g_fre + (size_t)bh*CPH_*HW_;
    const float* fi = g_fim + (size_t)bh*CPH_*HW_;
    int kbeg = kq*(HW_/KSPLIT), kend = kbeg + HW_/KSPLIT;
    for (int k0 = kbeg; k0 < kend; k0 += 32) {
        __syncthreads();
#pragma unroll
        for (int r = 0; r < 2; r++) {
            int e = tid + r*256;
            int row = e >> 3, kqq = e & 7;
            const float* src = (row < 32) ? (fr + (size_t)row*HW_) : (fi + (size_t)(row-32)*HW_);
            float4 v = *(const float4*)&src[k0 + kqq*4];
            uint2 u;
            u.x = h2bits(__floats2half2_rn(v.x, v.y));
            u.y = h2bits(__floats2half2_rn(v.z, v.w));
            *(uint2*)&gs[row][kqq*2] = u;
        }
        __syncthreads();
#pragma unroll
        for (int ks = 0; ks < 2; ks++) {
            int kb = ks*8 + t;
            uint32_t a[4];
            a[0] = gs[wm*16+g][kb];
            a[1] = gs[wm*16+g+8][kb];
            a[2] = gs[wm*16+g][kb+4];
            a[3] = gs[wm*16+g+8][kb+4];
#pragma unroll
            for (int ni = 0; ni < 4; ni++) {
                int n0 = wn*32 + ni*8 + g;
                mma16h(acc[ni], a, gs[n0][kb], gs[n0][kb+4]);
            }
        }
    }
    float* S = g_attnS + ((size_t)(kq*64 + bh))*4096;
#pragma unroll
    for (int ni = 0; ni < 4; ni++) {
        int d = wn*32 + ni*8 + 2*t;
        int c0 = wm*16 + g;
        *(float2*)&S[(size_t)c0*64 + d]     = make_float2(acc[ni][0], acc[ni][1]);
        *(float2*)&S[(size_t)(c0+8)*64 + d] = make_float2(acc[ni][2], acc[ni][3]);
    }
}

// ---------------- attn finalize ----------------
__global__ void attn_fin_kernel(const float* __restrict__ temp) {
    int bh = blockIdx.x;
    int head = bh & 7;
    int tid = threadIdx.x;
    __shared__ float Ss[4096];
    __shared__ float ar_[32*33], ai_[32*33];
    __shared__ float inv[32];
    for (int p = tid; p < 4096; p += 256) {
        float s = 0.f;
#pragma unroll
        for (int q = 0; q < KSPLIT; q++)
            s += g_attnS[((size_t)(q*64 + bh))*4096 + p];
        Ss[p] = s;
    }
    __syncthreads();
    if (tid < 32)
        inv[tid] = rsqrtf(fmaxf(Ss[tid*64 + tid] + Ss[(32+tid)*64 + 32+tid], 1e-24f));
    __syncthreads();
    float tmp = temp[head];
    for (int p = tid; p < 1024; p += 256) {
        int cc = p >> 5, dd = p & 31;
        float sre = Ss[cc*64 + dd] - Ss[(32+cc)*64 + (32+dd)];
        float sim = Ss[cc*64 + (32+dd)] + Ss[(32+cc)*64 + dd];
        float sc = inv[cc] * inv[dd] * tmp;
        ar_[cc*33+dd] = sre*sc;
        ai_[cc*33+dd] = sim*sc;
    }
    __syncthreads();
    int w = tid >> 5, lane = tid & 31;
    for (int r = w; r < 32; r += 8) {
        float vr = ar_[r*33+lane];
        float m = vr;
        for (int o = 16; o; o >>= 1) m = fmaxf(m, __shfl_xor_sync(0xffffffffu, m, o));
        float e = expf(vr - m); float s = e;
        for (int o = 16; o; o >>= 1) s += __shfl_xor_sync(0xffffffffu, s, o);
        ar_[r*33+lane] = e / s;
        float vi = ai_[r*33+lane];
        m = vi;
        for (int o = 16; o; o >>= 1) m = fmaxf(m, __shfl_xor_sync(0xffffffffu, m, o));
        e = expf(vi - m); s = e;
        for (int o = 16; o; o >>= 1) s += __shfl_xor_sync(0xffffffffu, s, o);
        ai_[r*33+lane] = e / s;
    }
    __syncthreads();
    for (int p = tid; p < 1024; p += 256) {
        int k = p >> 5, dd = p & 31;
        float accr = 0.f, acci = 0.f;
#pragma unroll
        for (int cc = 0; cc < 32; cc++) {
            float2 w2 = g_twid[((k*cc) & 31) * 128];
            float wr = w2.x, wi = -w2.y;
            float xr = ar_[cc*33+dd], xi = ai_[cc*33+dd];
            accr += wr*xr - wi*xi;
            acci += wr*xi + wi*xr;
        }
        g_attn2[(size_t)bh*1024 + p] = make_float2(accr*(1.f/32.f), acci*(1.f/32.f));
    }
}

// ---------------- attn apply ----------------
__global__ void attn_apply_kernel() {
    __shared__ float sfr[32][132], sfi[32][132];
    __shared__ float2 a2s[32][32];
    int nc = blockIdx.x, bh = blockIdx.y;
    int tid = threadIdx.x;
    for (int p = tid; p < 1024; p += 256)
        a2s[p>>5][p&31] = g_attn2[(size_t)bh*1024 + p];
    const float* fr = g_fre + (size_t)bh*CPH_*HW_ + nc*128;
    const float* fi = g_fim + (size_t)bh*CPH_*HW_ + nc*128;
    for (int e = tid; e < 1024; e += 256) {
        int d = e >> 5, j = e & 31;
        *(float4*)&sfr[d][j*4] = *(const float4*)&fr[(size_t)d*HW_ + j*4];
        *(float4*)&sfi[d][j*4] = *(const float4*)&fi[(size_t)d*HW_ + j*4];
    }
    __syncthreads();
    int tx = tid & 15, ty = tid >> 4;
    int k0 = ty*2, n0 = tx*8;
    float ar0[8], ai0[8], ar1[8], ai1[8];
#pragma unroll
    for (int j = 0; j < 8; j++) { ar0[j]=0.f; ai0[j]=0.f; ar1[j]=0.f; ai1[j]=0.f; }
#pragma unroll
    for (int d = 0; d < 32; d++) {
        float2 a0 = a2s[k0][d], a1 = a2s[k0+1][d];
        float4 f0 = *(float4*)&sfr[d][n0], f1 = *(float4*)&sfr[d][n0+4];
        float4 h0 = *(float4*)&sfi[d][n0], h1 = *(float4*)&sfi[d][n0+4];
        float frv[8] = {f0.x,f0.y,f0.z,f0.w,f1.x,f1.y,f1.z,f1.w};
        float fiv[8] = {h0.x,h0.y,h0.z,h0.w,h1.x,h1.y,h1.z,h1.w};
#pragma unroll
        for (int j = 0; j < 8; j++) {
            ar0[j] += a0.x*frv[j] - a0.y*fiv[j];
            ai0[j] += a0.x*fiv[j] + a0.y*frv[j];
            ar1[j] += a1.x*frv[j] - a1.y*fiv[j];
            ai1[j] += a1.x*fiv[j] + a1.y*frv[j];
        }
    }
    size_t base0 = ((size_t)(bh*32 + k0))*HW_ + nc*128 + n0;
    size_t base1 = base0 + HW_;
    *(float4*)&g_or[base0]   = make_float4(ar0[0],ar0[1],ar0[2],ar0[3]);
    *(float4*)&g_or[base0+4] = make_float4(ar0[4],ar0[5],ar0[6],ar0[7]);
    *(float4*)&g_oi[base0]   = make_float4(ai0[0],ai0[1],ai0[2],ai0[3]);
    *(float4*)&g_oi[base0+4] = make_float4(ai0[4],ai0[5],ai0[6],ai0[7]);
    *(float4*)&g_or[base1]   = make_float4(ar1[0],ar1[1],ar1[2],ar1[3]);
    *(float4*)&g_or[base1+4] = make_float4(ar1[4],ar1[5],ar1[6],ar1[7]);
    *(float4*)&g_oi[base1]   = make_float4(ai1[0],ai1[1],ai1[2],ai1[3]);
    *(float4*)&g_oi[base1+4] = make_float4(ai1[4],ai1[5],ai1[6],ai1[7]);
}

// ---------------- row ifft4096 radix-8 DIF + abs + residual ----------------
#define SKW(i) ((i) + ((i) >> 7))
__global__ void ifft_row_kernel(const float* __restrict__ x) {
    __shared__ float sr[4128], si[4128];
    int gid = blockIdx.x;
    int b = gid >> 8, cg = gid & 255;
    int tid = threadIdx.x;
    const float* pr = g_or + (size_t)gid*HW_;
    const float* pi = g_oi + (size_t)gid*HW_;
    for (int nn = tid; nn < 4096; nn += 512) {
        int d = SKW(nn);
        sr[d] = pr[nn];
        si[d] = pi[nn];
    }
    float xr[8], xi[8];
#define IFFT_STAGE(L, LG, TS)                                                       \
    {                                                                               \
        __syncthreads();                                                            \
        int j = tid & ((L) - 1);                                                    \
        int g = tid >> (LG);                                                        \
        int base = g*((L) << 3) + j;                                                \
        _Pragma("unroll")                                                           \
        for (int m = 0; m < 8; m++) {                                               \
            int idx = SKW(base + m*(L));                                            \
            xr[m] = sr[idx]; xi[m] = si[idx];                                       \
        }                                                                           \
        bfly8(xr, xi, -1.f);                                                        \
        if ((L) > 1) {                                                              \
            _Pragma("unroll")                                                       \
            for (int m = 1; m < 8; m++) {                                           \
                float2 w = g_twid[j*m*(TS)];                                        \
                float wr = w.x, wi = -w.y;                                          \
                float a = xr[m], bb2 = xi[m];                                       \
                xr[m] = a*wr - bb2*wi; xi[m] = a*wi + bb2*wr;                       \
            }                                                                       \
        }                                                                           \
        _Pragma("unroll")                                                           \
        for (int m = 0; m < 8; m++) {                                               \
            int idx = SKW(base + m*(L));                                            \
            sr[idx] = xr[m]; si[idx] = xi[m];                                       \
        }                                                                           \
    }
    IFFT_STAGE(512, 9, 1)
    IFFT_STAGE(64, 6, 8)
    IFFT_STAGE(8, 3, 64)
    IFFT_STAGE(1, 0, 0)
#undef IFFT_STAGE
    __syncthreads();
    for (int nn = tid; nn < 4096; nn += 512) {
        int d = SKW(dig8_12(nn));
        float re = sr[d], im = si[d];
        float v = sqrtf(re*re + im*im) * (1.f/4096.f)
                + x[((size_t)b*HW_ + nn)*C_ + cg];
        g_out2h[((size_t)(b*512) + cg)*HW_ + nn] = __float2half(v);
    }
}

// ---------------- gating MLP stage 1 ----------------
__global__ void g1_kernel(const float* __restrict__ w1w, const float* __restrict__ w1b,
                          const float* __restrict__ bg, const float* __restrict__ bb,
                          const float* __restrict__ bm, const float* __restrict__ bv) {
    __shared__ float sw[HID_*DD_];
    __shared__ float sa[HID_], st[HID_];
    int b = blockIdx.y;
    int tid = threadIdx.x;
    int n = blockIdx.x*256 + tid;
    for (int e = tid; e < HID_*DD_; e += 256) sw[e] = w1w[e];
    if (tid < HID_) {
        float s = bg[tid] * rsqrtf(bv[tid] + 1e-5f);
        sa[tid] = s;
        st[tid] = w1b[tid]*s + bb[tid] - bm[tid]*s;
    }
    __syncthreads();
    float acc[HID_];
#pragma unroll
    for (int o = 0; o < HID_; o++) acc[o] = 0.f;
    const float* fr = g_fre + (size_t)b*DD_*HW_ + n;
    for (int c = 0; c < DD_; c++) {
        float v = fr[(size_t)c*HW_];
#pragma unroll
        for (int o = 0; o < HID_; o++) acc[o] += v * sw[o*DD_ + c];
    }
#pragma unroll
    for (int o = 0; o < HID_; o++)
        g_g1[((size_t)(b*HID_ + o))*HW_ + n] = fmaxf(acc[o]*sa[o] + st[o], 0.f);
}

// ---------------- fused gate + ifft2 + abs + residual ----------------
__global__ void ifft2_gate_kernel(const float* __restrict__ x,
                                  const float* __restrict__ w2w,
                                  const float* __restrict__ w2b) {
    __shared__ float sr[64*65], si[64*65];
    __shared__ float w2s[HID_];
    int bc = blockIdx.x;
    int b = bc >> 8, c = bc & 255;
    int tid = threadIdx.x;
    if (tid < HID_) w2s[tid] = w2w[c*HID_ + tid];
    __syncthreads();
    float bias = w2b[c];
    float acc[8];
#pragma unroll
    for (int j = 0; j < 8; j++) acc[j] = bias;
    const float* g1p = g_g1 + (size_t)b*HID_*HW_;
#pragma unroll
    for (int o = 0; o < HID_; o++) {
        float w = w2s[o];
        const float* row = g1p + (size_t)o*HW_;
#pragma unroll
        for (int j = 0; j < 8; j++) acc[j] += w * row[tid + j*512];
    }
    const float* fre = g_fre + (size_t)bc*HW_;
    const float* fim = g_fim + (size_t)bc*HW_;
#pragma unroll
    for (int j = 0; j < 8; j++) {
        int e = tid + j*512;
        float gt = 1.f / (1.f + expf(-acc[j]));
        int r = e >> 6, w = e & 63;
        sr[r*65 + w] = gt * fre[e];
        si[r*65 + w] = gt * fim[e];
    }
    fft64_2d_dif8(sr, si, tid, -1.f);
    for (int e = tid; e < 4096; e += 512) {
        int r = e >> 6, w = e & 63;
        int d = dig8_6(r)*65 + dig8_6(w);
        float re = sr[d], im = si[d];
        float v = sqrtf(re*re + im*im) * (1.f/4096.f)
                + x[((size_t)b*HW_ + e)*C_ + (256 + c)];
        g_out2h[((size_t)(b*512 + 256 + c))*HW_ + e] = __float2half(v);
    }
}

// ---------------- final projection via fp16 mma, 4 warps of 64x64 ----------------
__global__ void proj_mma_kernel(const float* __restrict__ pb, float* __restrict__ out) {
    __shared__ uint32_t xs[128][20];
    __shared__ uint32_t ws[128][20];
    int b = blockIdx.z, nt = blockIdx.y, ot = blockIdx.x;
    int tid = threadIdx.x, lane = tid & 31, warp = tid >> 5;
    int wm = warp & 1, wn = warp >> 1;
    int g = lane >> 2, t = lane & 3;
    float acc[4][8][4];
#pragma unroll
    for (int i = 0; i < 4; i++)
#pragma unroll
        for (int j = 0; j < 8; j++)
#pragma unroll
            for (int q = 0; q < 4; q++) acc[i][j][q] = 0.f;

    int n0g = nt*128, o0g = ot*128;
    for (int kc = 0; kc < 512; kc += 32) {
        __syncthreads();
        // xs fill: 16 k-pairs x 32 n4-groups; rows half, repack to k-pairs
#pragma unroll
        for (int r = 0; r < 4; r++) {
            int e = tid + r*128;
            int kp = e >> 5, n4 = e & 31;
            const __half* row0 = &g_out2h[((size_t)(b*512 + kc + 2*kp))*HW_ + n0g + n4*4];
            __half2 a0 = *(const __half2*)row0;          // n, n+1 of row k0
            __half2 a1 = *(const __half2*)(row0 + 2);    // n+2, n+3
            __half2 b0 = *(const __half2*)(row0 + HW_);
            __half2 b1 = *(const __half2*)(row0 + HW_ + 2);
            xs[n4*4+0][kp] = h2bits(__lows2half2(a0, b0));
            xs[n4*4+1][kp] = h2bits(__highs2half2(a0, b0));
            xs[n4*4+2][kp] = h2bits(__lows2half2(a1, b1));
            xs[n4*4+3][kp] = h2bits(__highs2half2(a1, b1));
        }
#pragma unroll
        for (int r = 0; r < 4; r++) {
            int e = tid + r*128;
            int o = e >> 2, ch = e & 3;
            *(uint4*)&ws[o][ch*4] =
                *(const uint4*)&g_pw16[(size_t)(o0g + o)*256 + (kc >> 1) + ch*4];
        }
        __syncthreads();
#pragma unroll
        for (int ks = 0; ks < 2; ks++) {
            int kb = ks*8 + t;
            uint32_t a[4][4];
#pragma unroll
            for (int mi = 0; mi < 4; mi++) {
                int m0 = wm*64 + mi*16 + g;
                a[mi][0] = xs[m0][kb];
                a[mi][1] = xs[m0+8][kb];
                a[mi][2] = xs[m0][kb+4];
                a[mi][3] = xs[m0+8][kb+4];
            }
#pragma unroll
            for (int ni = 0; ni < 8; ni++) {
                int n0 = wn*64 + ni*8 + g;
                uint32_t b0 = ws[n0][kb];
                uint32_t b1 = ws[n0][kb+4];
                mma16h(acc[0][ni], a[0], b0, b1);
                mma16h(acc[1][ni], a[1], b0, b1);
                mma16h(acc[2][ni], a[2], b0, b1);
                mma16h(acc[3][ni], a[3], b0, b1);
            }
        }
    }
#pragma unroll
    for (int mi = 0; mi < 4; mi++) {
#pragma unroll
        for (int half = 0; half < 2; half++) {
            int n = n0g + wm*64 + mi*16 + g + half*8;
#pragma unroll
            for (int ni = 0; ni < 8; ni++) {
                int o = o0g + wn*64 + ni*8 + 2*t;
                float2 bias = *(const float2*)&pb[o];
                float v0 = acc[mi][ni][half*2+0] + bias.x;
                float v1 = acc[mi][ni][half*2+1] + bias.y;
                *(float2*)&out[((size_t)b*HW_ + n)*C_ + o] = make_float2(v0, v1);
            }
        }
    }
}

// ---------------- launch ----------------
extern "C" void kernel_launch(void* const* d_in, const int* in_sizes, int n_in,
                              void* d_out, int out_size) {
    const float* x       = (const float*)d_in[0];
    const float* conv2_w = (const float*)d_in[1];
    const float* conv2_b = (const float*)d_in[2];
    const float* bn2_g   = (const float*)d_in[3];
    const float* bn2_b   = (const float*)d_in[4];
    const float* bn2_m   = (const float*)d_in[5];
    const float* bn2_v   = (const float*)d_in[6];
    const float* temp    = (const float*)d_in[7];
    const float* w1_w    = (const float*)d_in[8];
    const float* w1_b    = (const float*)d_in[9];
    const float* bnw_g   = (const float*)d_in[10];
    const float* bnw_b   = (const float*)d_in[11];
    const float* bnw_m   = (const float*)d_in[12];
    const float* bnw_v   = (const float*)d_in[13];
    const float* w2_w    = (const float*)d_in[14];
    const float* w2_b    = (const float*)d_in[15];
    const float* proj_w  = (const float*)d_in[16];
    const float* proj_b  = (const float*)d_in[17];
    float* out = (float*)d_out;

    prep_kernel<<<1024, 256>>>(conv2_w, proj_w);
    x16_kernel<<<16384, 256>>>(x);
    conv_mma_kernel<<<dim3(2, 32, 8), 128>>>(conv2_b, bn2_g, bn2_b, bn2_m, bn2_v);
    fft2_fwd_kernel<<<1024, 512>>>();
    attn_gemm64_kernel<<<dim3(64, KSPLIT), 256>>>();
    attn_fin_kernel<<<64, 256>>>(temp);
    attn_apply_kernel<<<dim3(32, 64), 256>>>();
    ifft_row_kernel<<<2048, 512>>>(x);
    g1_kernel<<<dim3(16, 8), 256>>>(w1_w, w1_b, bnw_g, bnw_b, bnw_m, bnw_v);
    ifft2_gate_kernel<<<2048, 512>>>(x, w2_w, w2_b);
    proj_mma_kernel<<<dim3(4, 32, 8), 128>>>(proj_b, out);
}

// round 17
// speedup vs baseline: 1.6527x; 1.0258x over previous
#include <cuda_runtime.h>
#include <cuda_fp16.h>
#include <math.h>
#include <stdint.h>

#define B_  8
#define C_  512
#define DD_ 256
#define HW_ 4096
#define HEADS_ 8
#define CPH_ 32
#define HID_ 16
#define KSPLIT 8

// ---------------- scratch ----------------
__device__ __align__(16) uint32_t g_wt16[9*256*256];  // conv weights half2 [tap][co][cin/2]
__device__ __align__(16) uint32_t g_pw16[512*256];    // proj weights half2 [o][c/2]
__device__ __align__(16) __half  g_x16[(size_t)B_*HW_*C_];
__device__ float2 g_twid[4096];
__device__ __align__(16) __half  g_y16 [(size_t)B_*DD_*HW_];
__device__ __align__(16) __half  g_fre [(size_t)B_*DD_*HW_];
__device__ __align__(16) __half  g_fim [(size_t)B_*DD_*HW_];
__device__ float  g_g1  [(size_t)B_*HID_*HW_];
__device__ float  g_attnS[KSPLIT*64*64*64];
__device__ float2 g_attn2[64*1024];
__device__ __align__(16) __half  g_or16[(size_t)B_*DD_*HW_];
__device__ __align__(16) __half  g_oi16[(size_t)B_*DD_*HW_];
__device__ __align__(16) __half  g_out2h[(size_t)B_*C_*HW_];

// ---------------- mma helpers ----------------
__device__ __forceinline__ void mma16h(float c[4], const uint32_t a[4], uint32_t b0, uint32_t b1) {
    asm volatile("mma.sync.aligned.m16n8k16.row.col.f32.f16.f16.f32 "
        "{%0,%1,%2,%3}, {%4,%5,%6,%7}, {%8,%9}, {%0,%1,%2,%3};"
        : "+f"(c[0]), "+f"(c[1]), "+f"(c[2]), "+f"(c[3])
        : "r"(a[0]), "r"(a[1]), "r"(a[2]), "r"(a[3]), "r"(b0), "r"(b1));
}
__device__ __forceinline__ uint32_t h2bits(__half2 h) {
    return *(uint32_t*)&h;
}
__device__ __forceinline__ int dig8_6(int x)  { return ((x & 7) << 3) | (x >> 3); }
__device__ __forceinline__ int dig8_12(int x) {
    return ((x & 7) << 9) | (((x >> 3) & 7) << 6) | (((x >> 6) & 7) << 3) | (x >> 9);
}

// ---------------- radix-8 DIF butterfly ----------------
__device__ __forceinline__ void bfly8(float xr[8], float xi[8], float sign) {
    const float RH = 0.70710678118654752440f;
    float ur[4], ui[4], vr[4], vi[4];
#pragma unroll
    for (int m = 0; m < 4; m++) {
        ur[m] = xr[m] + xr[m+4]; ui[m] = xi[m] + xi[m+4];
        vr[m] = xr[m] - xr[m+4]; vi[m] = xi[m] - xi[m+4];
    }
    { float a = vr[1], b = vi[1]; vr[1] = RH*(a + sign*b); vi[1] = RH*(b - sign*a); }
    { float a = vr[2], b = vi[2]; vr[2] = sign*b;          vi[2] = -sign*a; }
    { float a = vr[3], b = vi[3]; vr[3] = RH*(sign*b - a); vi[3] = RH*(-b - sign*a); }
    float q0r = ur[0]+ur[2], q0i = ui[0]+ui[2];
    float q1r = ur[1]+ur[3], q1i = ui[1]+ui[3];
    float r0r = ur[0]-ur[2], r0i = ui[0]-ui[2];
    float d1r = ur[1]-ur[3], d1i = ui[1]-ui[3];
    float r1r = sign*d1i,    r1i = -sign*d1r;
    xr[0] = q0r+q1r; xi[0] = q0i+q1i;
    xr[2] = r0r+r1r; xi[2] = r0i+r1i;
    xr[4] = q0r-q1r; xi[4] = q0i-q1i;
    xr[6] = r0r-r1r; xi[6] = r0i-r1i;
    q0r = vr[0]+vr[2]; q0i = vi[0]+vi[2];
    q1r = vr[1]+vr[3]; q1i = vi[1]+vi[3];
    r0r = vr[0]-vr[2]; r0i = vi[0]-vi[2];
    d1r = vr[1]-vr[3]; d1i = vi[1]-vi[3];
    r1r = sign*d1i;    r1i = -sign*d1r;
    xr[1] = q0r+q1r; xi[1] = q0i+q1i;
    xr[3] = r0r+r1r; xi[3] = r0i+r1i;
    xr[5] = q0r-q1r; xi[5] = q0i-q1i;
    xr[7] = r0r-r1r; xi[7] = r0i-r1i;
}

// ---------------- prep ----------------
__global__ void prep_kernel(const float* __restrict__ cw, const float* __restrict__ pw) {
    int tid = blockIdx.x*blockDim.x + threadIdx.x;
    int stride = gridDim.x*blockDim.x;
    if (tid < 4096) {
        float s, c;
        sincosf(-6.28318530717958647692f * (float)tid / 4096.f, &s, &c);
        g_twid[tid] = make_float2(c, s);
    }
    for (int e = tid; e < 9*256*256; e += stride) {
        int tap = e / (256*256);
        int rem = e - tap*256*256;
        int co = rem >> 8;
        int cin = (rem & 255) * 2;
        float w0 = cw[(co*512 + cin)*9 + tap];
        float w1 = cw[(co*512 + cin + 1)*9 + tap];
        g_wt16[e] = h2bits(__floats2half2_rn(w0, w1));
    }
    for (int e = tid; e < 512*256; e += stride) {
        int o = e >> 8, c = (e & 255)*2;
        g_pw16[e] = h2bits(__floats2half2_rn(pw[o*512 + c], pw[o*512 + c + 1]));
    }
}

// ---------------- x -> half pre-convert ----------------
__global__ void x16_kernel(const float* __restrict__ x) {
    size_t i = ((size_t)blockIdx.x*256 + threadIdx.x) * 4;
    float4 v = *(const float4*)&x[i];
    __half2* dst = (__half2*)&g_x16[i];
    dst[0] = __floats2half2_rn(v.x, v.y);
    dst[1] = __floats2half2_rn(v.z, v.w);
}

// ---------------- conv via fp16 mma m16n8k16 ----------------
__global__ void conv_mma_kernel(const float* __restrict__ cb,
                                const float* __restrict__ bg, const float* __restrict__ bb,
                                const float* __restrict__ bm, const float* __restrict__ bv) {
    __shared__ uint32_t xs[128][20];
    __shared__ uint32_t ws[128][20];
    int b = blockIdx.z, pt = blockIdx.y, ct = blockIdx.x;
    int tid = threadIdx.x, lane = tid & 31, warp = tid >> 5;
    int wm = warp & 1, wn = warp >> 1;
    int g = lane >> 2, t = lane & 3;
    float acc[4][8][4];
#pragma unroll
    for (int i = 0; i < 4; i++)
#pragma unroll
        for (int j = 0; j < 8; j++)
#pragma unroll
            for (int q = 0; q < 4; q++) acc[i][j][q] = 0.f;

    int pos0 = pt*128;
    for (int tap = 0; tap < 9; tap++) {
        int dh = 3*((tap/3) - 1), dw = 3*((tap%3) - 1);
        const uint32_t* wtp = g_wt16 + ((size_t)tap*256 + ct*128)*256;
        for (int kc = 0; kc < 512; kc += 32) {
            __syncthreads();
#pragma unroll
            for (int r = 0; r < 8; r++) {
                int e = tid + r*128;
                int pos = e >> 3, ch = e & 7;
                int gp = pos0 + pos;
                int ih = (gp >> 6) + dh, iw = (gp & 63) + dw;
                uint2 u = make_uint2(0u, 0u);
                if ((unsigned)ih < 64u && (unsigned)iw < 64u)
                    u = *(const uint2*)&g_x16[((size_t)(b*HW_) + ih*64 + iw)*C_ + kc + ch*4];
                *(uint2*)&xs[pos][ch*2] = u;
            }
#pragma unroll
            for (int r = 0; r < 4; r++) {
                int e = tid + r*128;
                int co = e >> 2, ch = e & 3;
                *(uint4*)&ws[co][ch*4] =
                    *(const uint4*)&wtp[(size_t)co*256 + (kc >> 1) + ch*4];
            }
            __syncthreads();
#pragma unroll
            for (int ks = 0; ks < 2; ks++) {
                int kb = ks*8 + t;
                uint32_t a[4][4];
#pragma unroll
                for (int mi = 0; mi < 4; mi++) {
                    int m0 = wm*64 + mi*16 + g;
                    a[mi][0] = ws[m0][kb];
                    a[mi][1] = ws[m0+8][kb];
                    a[mi][2] = ws[m0][kb+4];
                    a[mi][3] = ws[m0+8][kb+4];
                }
#pragma unroll
                for (int ni = 0; ni < 8; ni++) {
                    int n0 = wn*64 + ni*8 + g;
                    uint32_t b0 = xs[n0][kb];
                    uint32_t b1 = xs[n0][kb+4];
                    mma16h(acc[0][ni], a[0], b0, b1);
                    mma16h(acc[1][ni], a[1], b0, b1);
                    mma16h(acc[2][ni], a[2], b0, b1);
                    mma16h(acc[3][ni], a[3], b0, b1);
                }
            }
        }
    }
#pragma unroll
    for (int mi = 0; mi < 4; mi++) {
#pragma unroll
        for (int half = 0; half < 2; half++) {
            int o = ct*128 + wm*64 + mi*16 + g + half*8;
            float s = bg[o] * rsqrtf(bv[o] + 1e-5f);
            float t0 = cb[o]*s + bb[o] - bm[o]*s;
            __half* dst = g_y16 + ((size_t)(b*DD_ + o))*HW_;
#pragma unroll
            for (int ni = 0; ni < 8; ni++) {
                int pos = pos0 + wn*64 + ni*8 + 2*t;
                float v0 = fmaxf(acc[mi][ni][half*2+0]*s + t0, 0.f);
                float v1 = fmaxf(acc[mi][ni][half*2+1]*s + t0, 0.f);
                *(__half2*)&dst[pos] = __floats2half2_rn(v0, v1);
            }
        }
    }
}

// ---------------- 64x64 2D FFT, radix-8 DIF ----------------
__device__ __forceinline__ void fft64_2d_dif8(float* sr, float* si, int tid, float sign) {
    float xr[8], xi[8];
    __syncthreads();
    {
        int row = tid & 63, j = tid >> 6;
        int base = row*65 + j;
#pragma unroll
        for (int m = 0; m < 8; m++) { xr[m] = sr[base + 8*m]; xi[m] = si[base + 8*m]; }
        bfly8(xr, xi, sign);
#pragma unroll
        for (int m = 1; m < 8; m++) {
            float2 w = g_twid[j*m*64];
            float wr = w.x, wi = sign*w.y;
            float a = xr[m], bb2 = xi[m];
            xr[m] = a*wr - bb2*wi; xi[m] = a*wi + bb2*wr;
        }
#pragma unroll
        for (int m = 0; m < 8; m++) { sr[base + 8*m] = xr[m]; si[base + 8*m] = xi[m]; }
    }
    __syncthreads();
    {
        int row = tid & 63, g = tid >> 6;
        int base = row*65 + g*8;
#pragma unroll
        for (int m = 0; m < 8; m++) { xr[m] = sr[base + m]; xi[m] = si[base + m]; }
        bfly8(xr, xi, sign);
#pragma unroll
        for (int m = 0; m < 8; m++) { sr[base + m] = xr[m]; si[base + m] = xi[m]; }
    }
    __syncthreads();
    {
        int col = tid & 63, j = tid >> 6;
        int base = j*65 + col;
#pragma unroll
        for (int m = 0; m < 8; m++) { xr[m] = sr[base + 520*m]; xi[m] = si[base + 520*m]; }
        bfly8(xr, xi, sign);
#pragma unroll
        for (int m = 1; m < 8; m++) {
            float2 w = g_twid[j*m*64];
            float wr = w.x, wi = sign*w.y;
            float a = xr[m], bb2 = xi[m];
            xr[m] = a*wr - bb2*wi; xi[m] = a*wi + bb2*wr;
        }
#pragma unroll
        for (int m = 0; m < 8; m++) { sr[base + 520*m] = xr[m]; si[base + 520*m] = xi[m]; }
    }
    __syncthreads();
    {
        int col = tid & 63, g = tid >> 6;
        int base = (g*8)*65 + col;
#pragma unroll
        for (int m = 0; m < 8; m++) { xr[m] = sr[base + 65*m]; xi[m] = si[base + 65*m]; }
        bfly8(xr, xi, sign);
#pragma unroll
        for (int m = 0; m < 8; m++) { sr[base + 65*m] = xr[m]; si[base + 65*m] = xi[m]; }
    }
    __syncthreads();
}

// forward fft2 of real conv output, TWO channels per block via packing
__global__ void fft2_fwd_kernel() {
    __shared__ float sr[64*65], si[64*65];
    int bp = blockIdx.x;
    int b = bp >> 7, cp = bp & 127;
    int c0 = cp*2;
    int tid = threadIdx.x;
    const __half* s0 = g_y16 + ((size_t)(b*DD_ + c0))*HW_;
    const __half* s1 = s0 + HW_;
    for (int e = tid; e < 4096; e += 512) {
        int r = e >> 6, w = e & 63;
        sr[r*65 + w] = __half2float(s0[e]);
        si[r*65 + w] = __half2float(s1[e]);
    }
    fft64_2d_dif8(sr, si, tid, 1.f);
    __half* f0r = g_fre + ((size_t)(b*DD_ + c0))*HW_;
    __half* f0i = g_fim + ((size_t)(b*DD_ + c0))*HW_;
    __half* f1r = f0r + HW_;
    __half* f1i = f0i + HW_;
    for (int e = tid; e < 4096; e += 512) {
        int r = e >> 6, w = e & 63;
        int rn = (64 - r) & 63, wn = (64 - w) & 63;
        float Zr  = sr[dig8_6(r)*65 + dig8_6(w)],   Zi  = si[dig8_6(r)*65 + dig8_6(w)];
        float Z2r = sr[dig8_6(rn)*65 + dig8_6(wn)], Z2i = si[dig8_6(rn)*65 + dig8_6(wn)];
        f0r[e] = __float2half(0.5f*(Zr + Z2r));
        f0i[e] = __float2half(0.5f*(Zi - Z2i));
        f1r[e] = __float2half(0.5f*(Zi + Z2i));
        f1i[e] = __float2half(0.5f*(Z2r - Zr));
    }
}

// ---------------- attention scores, fp16 mma (direct half loads) ----------------
__global__ void attn_gemm64_kernel() {
    __shared__ uint32_t gs[64][20];
    int bh = blockIdx.x, kq = blockIdx.y;
    int tid = threadIdx.x, lane = tid & 31, warp = tid >> 5;
    int wm = warp & 3, wn = warp >> 2;
    int g = lane >> 2, t = lane & 3;
    float acc[4][4];
#pragma unroll
    for (int i = 0; i < 4; i++)
#pragma unroll
        for (int q = 0; q < 4; q++) acc[i][q] = 0.f;
    const __half* fr = g_fre + (size_t)bh*CPH_*HW_;
    const __half* fi = g_fim + (size_t)bh*CPH_*HW_;
    int kbeg = kq*(HW_/KSPLIT), kend = kbeg + HW_/KSPLIT;
    for (int k0 = kbeg; k0 < kend; k0 += 32) {
        __syncthreads();
#pragma unroll
        for (int r = 0; r < 2; r++) {
            int e = tid + r*256;
            int row = e >> 3, kqq = e & 7;
            const __half* src = (row < 32) ? (fr + (size_t)row*HW_) : (fi + (size_t)(row-32)*HW_);
            *(uint2*)&gs[row][kqq*2] = *(const uint2*)&src[k0 + kqq*4];
        }
        __syncthreads();
#pragma unroll
        for (int ks = 0; ks < 2; ks++) {
            int kb = ks*8 + t;
            uint32_t a[4];
            a[0] = gs[wm*16+g][kb];
            a[1] = gs[wm*16+g+8][kb];
            a[2] = gs[wm*16+g][kb+4];
            a[3] = gs[wm*16+g+8][kb+4];
#pragma unroll
            for (int ni = 0; ni < 4; ni++) {
                int n0 = wn*32 + ni*8 + g;
                mma16h(acc[ni], a, gs[n0][kb], gs[n0][kb+4]);
            }
        }
    }
    float* S = g_attnS + ((size_t)(kq*64 + bh))*4096;
#pragma unroll
    for (int ni = 0; ni < 4; ni++) {
        int d = wn*32 + ni*8 + 2*t;
        int c0 = wm*16 + g;
        *(float2*)&S[(size_t)c0*64 + d]     = make_float2(acc[ni][0], acc[ni][1]);
        *(float2*)&S[(size_t)(c0+8)*64 + d] = make_float2(acc[ni][2], acc[ni][3]);
    }
}

// ---------------- attn finalize ----------------
__global__ void attn_fin_kernel(const float* __restrict__ temp) {
    int bh = blockIdx.x;
    int head = bh & 7;
    int tid = threadIdx.x;
    __shared__ float Ss[4096];
    __shared__ float ar_[32*33], ai_[32*33];
    __shared__ float inv[32];
    for (int p = tid; p < 4096; p += 256) {
        float s = 0.f;
#pragma unroll
        for (int q = 0; q < KSPLIT; q++)
            s += g_attnS[((size_t)(q*64 + bh))*4096 + p];
        Ss[p] = s;
    }
    __syncthreads();
    if (tid < 32)
        inv[tid] = rsqrtf(fmaxf(Ss[tid*64 + tid] + Ss[(32+tid)*64 + 32+tid], 1e-24f));
    __syncthreads();
    float tmp = temp[head];
    for (int p = tid; p < 1024; p += 256) {
        int cc = p >> 5, dd = p & 31;
        float sre = Ss[cc*64 + dd] - Ss[(32+cc)*64 + (32+dd)];
        float sim = Ss[cc*64 + (32+dd)] + Ss[(32+cc)*64 + dd];
        float sc = inv[cc] * inv[dd] * tmp;
        ar_[cc*33+dd] = sre*sc;
        ai_[cc*33+dd] = sim*sc;
    }
    __syncthreads();
    int w = tid >> 5, lane = tid & 31;
    for (int r = w; r < 32; r += 8) {
        float vr = ar_[r*33+lane];
        float m = vr;
        for (int o = 16; o; o >>= 1) m = fmaxf(m, __shfl_xor_sync(0xffffffffu, m, o));
        float e = expf(vr - m); float s = e;
        for (int o = 16; o; o >>= 1) s += __shfl_xor_sync(0xffffffffu, s, o);
        ar_[r*33+lane] = e / s;
        float vi = ai_[r*33+lane];
        m = vi;
        for (int o = 16; o; o >>= 1) m = fmaxf(m, __shfl_xor_sync(0xffffffffu, m, o));
        e = expf(vi - m); s = e;
        for (int o = 16; o; o >>= 1) s += __shfl_xor_sync(0xffffffffu, s, o);
        ai_[r*33+lane] = e / s;
    }
    __syncthreads();
    for (int p = tid; p < 1024; p += 256) {
        int k = p >> 5, dd = p & 31;
        float accr = 0.f, acci = 0.f;
#pragma unroll
        for (int cc = 0; cc < 32; cc++) {
            float2 w2 = g_twid[((k*cc) & 31) * 128];
            float wr = w2.x, wi = -w2.y;
            float xr = ar_[cc*33+dd], xi = ai_[cc*33+dd];
            accr += wr*xr - wi*xi;
            acci += wr*xi + wi*xr;
        }
        g_attn2[(size_t)bh*1024 + p] = make_float2(accr*(1.f/32.f), acci*(1.f/32.f));
    }
}

// ---------------- attn apply ----------------
__global__ void attn_apply_kernel() {
    __shared__ float sfr[32][132], sfi[32][132];
    __shared__ float2 a2s[32][32];
    int nc = blockIdx.x, bh = blockIdx.y;
    int tid = threadIdx.x;
    for (int p = tid; p < 1024; p += 256)
        a2s[p>>5][p&31] = g_attn2[(size_t)bh*1024 + p];
    const __half* fr = g_fre + (size_t)bh*CPH_*HW_ + nc*128;
    const __half* fi = g_fim + (size_t)bh*CPH_*HW_ + nc*128;
    for (int e = tid; e < 1024; e += 256) {
        int d = e >> 5, j = e & 31;
        uint2 ur = *(const uint2*)&fr[(size_t)d*HW_ + j*4];
        uint2 ui = *(const uint2*)&fi[(size_t)d*HW_ + j*4];
        float2 r0 = __half22float2(*(__half2*)&ur.x);
        float2 r1 = __half22float2(*(__half2*)&ur.y);
        float2 i0 = __half22float2(*(__half2*)&ui.x);
        float2 i1 = __half22float2(*(__half2*)&ui.y);
        *(float4*)&sfr[d][j*4] = make_float4(r0.x, r0.y, r1.x, r1.y);
        *(float4*)&sfi[d][j*4] = make_float4(i0.x, i0.y, i1.x, i1.y);
    }
    __syncthreads();
    int tx = tid & 15, ty = tid >> 4;
    int k0 = ty*2, n0 = tx*8;
    float ar0[8], ai0[8], ar1[8], ai1[8];
#pragma unroll
    for (int j = 0; j < 8; j++) { ar0[j]=0.f; ai0[j]=0.f; ar1[j]=0.f; ai1[j]=0.f; }
#pragma unroll
    for (int d = 0; d < 32; d++) {
        float2 a0 = a2s[k0][d], a1 = a2s[k0+1][d];
        float4 f0 = *(float4*)&sfr[d][n0], f1 = *(float4*)&sfr[d][n0+4];
        float4 h0 = *(float4*)&sfi[d][n0], h1 = *(float4*)&sfi[d][n0+4];
        float frv[8] = {f0.x,f0.y,f0.z,f0.w,f1.x,f1.y,f1.z,f1.w};
        float fiv[8] = {h0.x,h0.y,h0.z,h0.w,h1.x,h1.y,h1.z,h1.w};
#pragma unroll
        for (int j = 0; j < 8; j++) {
            ar0[j] += a0.x*frv[j] - a0.y*fiv[j];
            ai0[j] += a0.x*fiv[j] + a0.y*frv[j];
            ar1[j] += a1.x*frv[j] - a1.y*fiv[j];
            ai1[j] += a1.x*fiv[j] + a1.y*frv[j];
        }
    }
    size_t base0 = ((size_t)(bh*32 + k0))*HW_ + nc*128 + n0;
    size_t base1 = base0 + HW_;
    {
        __half2 h0 = __floats2half2_rn(ar0[0], ar0[1]);
        __half2 h1 = __floats2half2_rn(ar0[2], ar0[3]);
        __half2 h2 = __floats2half2_rn(ar0[4], ar0[5]);
        __half2 h3 = __floats2half2_rn(ar0[6], ar0[7]);
        *(uint4*)&g_or16[base0] = make_uint4(h2bits(h0), h2bits(h1), h2bits(h2), h2bits(h3));
        h0 = __floats2half2_rn(ai0[0], ai0[1]);
        h1 = __floats2half2_rn(ai0[2], ai0[3]);
        h2 = __floats2half2_rn(ai0[4], ai0[5]);
        h3 = __floats2half2_rn(ai0[6], ai0[7]);
        *(uint4*)&g_oi16[base0] = make_uint4(h2bits(h0), h2bits(h1), h2bits(h2), h2bits(h3));
        h0 = __floats2half2_rn(ar1[0], ar1[1]);
        h1 = __floats2half2_rn(ar1[2], ar1[3]);
        h2 = __floats2half2_rn(ar1[4], ar1[5]);
        h3 = __floats2half2_rn(ar1[6], ar1[7]);
        *(uint4*)&g_or16[base1] = make_uint4(h2bits(h0), h2bits(h1), h2bits(h2), h2bits(h3));
        h0 = __floats2half2_rn(ai1[0], ai1[1]);
        h1 = __floats2half2_rn(ai1[2], ai1[3]);
        h2 = __floats2half2_rn(ai1[4], ai1[5]);
        h3 = __floats2half2_rn(ai1[6], ai1[7]);
        *(uint4*)&g_oi16[base1] = make_uint4(h2bits(h0), h2bits(h1), h2bits(h2), h2bits(h3));
    }
}

// ---------------- row ifft4096 radix-8 DIF + abs + residual ----------------
#define SKW(i) ((i) + ((i) >> 7))
__global__ void ifft_row_kernel(const float* __restrict__ x) {
    __shared__ float sr[4128], si[4128];
    int gid = blockIdx.x;
    int b = gid >> 8, cg = gid & 255;
    int tid = threadIdx.x;
    const __half* pr = g_or16 + (size_t)gid*HW_;
    const __half* pi = g_oi16 + (size_t)gid*HW_;
    for (int nn = tid; nn < 4096; nn += 512) {
        int d = SKW(nn);
        sr[d] = __half2float(pr[nn]);
        si[d] = __half2float(pi[nn]);
    }
    float xr[8], xi[8];
#define IFFT_STAGE(L, LG, TS)                                                       \
    {                                                                               \
        __syncthreads();                                                            \
        int j = tid & ((L) - 1);                                                    \
        int g = tid >> (LG);                                                        \
        int base = g*((L) << 3) + j;                                                \
        _Pragma("unroll")                                                           \
        for (int m = 0; m < 8; m++) {                                               \
            int idx = SKW(base + m*(L));                                            \
            xr[m] = sr[idx]; xi[m] = si[idx];                                       \
        }                                                                           \
        bfly8(xr, xi, -1.f);                                                        \
        if ((L) > 1) {                                                              \
            _Pragma("unroll")                                                       \
            for (int m = 1; m < 8; m++) {                                           \
                float2 w = g_twid[j*m*(TS)];                                        \
                float wr = w.x, wi = -w.y;                                          \
                float a = xr[m], bb2 = xi[m];                                       \
                xr[m] = a*wr - bb2*wi; xi[m] = a*wi + bb2*wr;                       \
            }                                                                       \
        }                                                                           \
        _Pragma("unroll")                                                           \
        for (int m = 0; m < 8; m++) {                                               \
            int idx = SKW(base + m*(L));                                            \
            sr[idx] = xr[m]; si[idx] = xi[m];                                       \
        }                                                                           \
    }
    IFFT_STAGE(512, 9, 1)
    IFFT_STAGE(64, 6, 8)
    IFFT_STAGE(8, 3, 64)
    IFFT_STAGE(1, 0, 0)
#undef IFFT_STAGE
    __syncthreads();
    for (int nn = tid; nn < 4096; nn += 512) {
        int d = SKW(dig8_12(nn));
        float re = sr[d], im = si[d];
        float v = sqrtf(re*re + im*im) * (1.f/4096.f)
                + x[((size_t)b*HW_ + nn)*C_ + cg];
        g_out2h[((size_t)(b*512) + cg)*HW_ + nn] = __float2half(v);
    }
}

// ---------------- gating MLP stage 1 ----------------
__global__ void g1_kernel(const float* __restrict__ w1w, const float* __restrict__ w1b,
                          const float* __restrict__ bg, const float* __restrict__ bb,
                          const float* __restrict__ bm, const float* __restrict__ bv) {
    __shared__ float sw[HID_*DD_];
    __shared__ float sa[HID_], st[HID_];
    int b = blockIdx.y;
    int tid = threadIdx.x;
    int n = blockIdx.x*256 + tid;
    for (int e = tid; e < HID_*DD_; e += 256) sw[e] = w1w[e];
    if (tid < HID_) {
        float s = bg[tid] * rsqrtf(bv[tid] + 1e-5f);
        sa[tid] = s;
        st[tid] = w1b[tid]*s + bb[tid] - bm[tid]*s;
    }
    __syncthreads();
    float acc[HID_];
#pragma unroll
    for (int o = 0; o < HID_; o++) acc[o] = 0.f;
    const __half* fr = g_fre + (size_t)b*DD_*HW_ + n;
    for (int c = 0; c < DD_; c++) {
        float v = __half2float(fr[(size_t)c*HW_]);
#pragma unroll
        for (int o = 0; o < HID_; o++) acc[o] += v * sw[o*DD_ + c];
    }
#pragma unroll
    for (int o = 0; o < HID_; o++)
        g_g1[((size_t)(b*HID_ + o))*HW_ + n] = fmaxf(acc[o]*sa[o] + st[o], 0.f);
}

// ---------------- fused gate + ifft2 + abs + residual ----------------
__global__ void ifft2_gate_kernel(const float* __restrict__ x,
                                  const float* __restrict__ w2w,
                                  const float* __restrict__ w2b) {
    __shared__ float sr[64*65], si[64*65];
    __shared__ float w2s[HID_];
    int bc = blockIdx.x;
    int b = bc >> 8, c = bc & 255;
    int tid = threadIdx.x;
    if (tid < HID_) w2s[tid] = w2w[c*HID_ + tid];
    __syncthreads();
    float bias = w2b[c];
    float acc[8];
#pragma unroll
    for (int j = 0; j < 8; j++) acc[j] = bias;
    const float* g1p = g_g1 + (size_t)b*HID_*HW_;
#pragma unroll
    for (int o = 0; o < HID_; o++) {
        float w = w2s[o];
        const float* row = g1p + (size_t)o*HW_;
#pragma unroll
        for (int j = 0; j < 8; j++) acc[j] += w * row[tid + j*512];
    }
    const __half* fre = g_fre + (size_t)bc*HW_;
    const __half* fim = g_fim + (size_t)bc*HW_;
#pragma unroll
    for (int j = 0; j < 8; j++) {
        int e = tid + j*512;
        float gt = 1.f / (1.f + expf(-acc[j]));
        int r = e >> 6, w = e & 63;
        sr[r*65 + w] = gt * __half2float(fre[e]);
        si[r*65 + w] = gt * __half2float(fim[e]);
    }
    fft64_2d_dif8(sr, si, tid, -1.f);
    for (int e = tid; e < 4096; e += 512) {
        int r = e >> 6, w = e & 63;
        int d = dig8_6(r)*65 + dig8_6(w);
        float re = sr[d], im = si[d];
        float v = sqrtf(re*re + im*im) * (1.f/4096.f)
                + x[((size_t)b*HW_ + e)*C_ + (256 + c)];
        g_out2h[((size_t)(b*512 + 256 + c))*HW_ + e] = __float2half(v);
    }
}

// ---------------- final projection via fp16 mma ----------------
__global__ void proj_mma_kernel(const float* __restrict__ pb, float* __restrict__ out) {
    __shared__ uint32_t xs[128][20];
    __shared__ uint32_t ws[128][20];
    int b = blockIdx.z, nt = blockIdx.y, ot = blockIdx.x;
    int tid = threadIdx.x, lane = tid & 31, warp = tid >> 5;
    int wm = warp & 1, wn = warp >> 1;
    int g = lane >> 2, t = lane & 3;
    float acc[4][8][4];
#pragma unroll
    for (int i = 0; i < 4; i++)
#pragma unroll
        for (int j = 0; j < 8; j++)
#pragma unroll
            for (int q = 0; q < 4; q++) acc[i][j][q] = 0.f;

    int n0g = nt*128, o0g = ot*128;
    for (int kc = 0; kc < 512; kc += 32) {
        __syncthreads();
#pragma unroll
        for (int r = 0; r < 4; r++) {
            int e = tid + r*128;
            int kp = e >> 5, n4 = e & 31;
            const __half* row0 = &g_out2h[((size_t)(b*512 + kc + 2*kp))*HW_ + n0g + n4*4];
            __half2 a0 = *(const __half2*)row0;
            __half2 a1 = *(const __half2*)(row0 + 2);
            __half2 b0 = *(const __half2*)(row0 + HW_);
            __half2 b1 = *(const __half2*)(row0 + HW_ + 2);
            xs[n4*4+0][kp] = h2bits(__lows2half2(a0, b0));
            xs[n4*4+1][kp] = h2bits(__highs2half2(a0, b0));
            xs[n4*4+2][kp] = h2bits(__lows2half2(a1, b1));
            xs[n4*4+3][kp] = h2bits(__highs2half2(a1, b1));
        }
#pragma unroll
        for (int r = 0; r < 4; r++) {
            int e = tid + r*128;
            int o = e >> 2, ch = e & 3;
            *(uint4*)&ws[o][ch*4] =
                *(const uint4*)&g_pw16[(size_t)(o0g + o)*256 + (kc >> 1) + ch*4];
        }
        __syncthreads();
#pragma unroll
        for (int ks = 0; ks < 2; ks++) {
            int kb = ks*8 + t;
            uint32_t a[4][4];
#pragma unroll
            for (int mi = 0; mi < 4; mi++) {
                int m0 = wm*64 + mi*16 + g;
                a[mi][0] = xs[m0][kb];
                a[mi][1] = xs[m0+8][kb];
                a[mi][2] = xs[m0][kb+4];
                a[mi][3] = xs[m0+8][kb+4];
            }
#pragma unroll
            for (int ni = 0; ni < 8; ni++) {
                int n0 = wn*64 + ni*8 + g;
                uint32_t b0 = ws[n0][kb];
                uint32_t b1 = ws[n0][kb+4];
                mma16h(acc[0][ni], a[0], b0, b1);
                mma16h(acc[1][ni], a[1], b0, b1);
                mma16h(acc[2][ni], a[2], b0, b1);
                mma16h(acc[3][ni], a[3], b0, b1);
            }
        }
    }
#pragma unroll
    for (int mi = 0; mi < 4; mi++) {
#pragma unroll
        for (int half = 0; half < 2; half++) {
            int n = n0g + wm*64 + mi*16 + g + half*8;
#pragma unroll
            for (int ni = 0; ni < 8; ni++) {
                int o = o0g + wn*64 + ni*8 + 2*t;
                float2 bias = *(const float2*)&pb[o];
                float v0 = acc[mi][ni][half*2+0] + bias.x;
                float v1 = acc[mi][ni][half*2+1] + bias.y;
                *(float2*)&out[((size_t)b*HW_ + n)*C_ + o] = make_float2(v0, v1);
            }
        }
    }
}

// ---------------- launch ----------------
extern "C" void kernel_launch(void* const* d_in, const int* in_sizes, int n_in,
                              void* d_out, int out_size) {
    const float* x       = (const float*)d_in[0];
    const float* conv2_w = (const float*)d_in[1];
    const float* conv2_b = (const float*)d_in[2];
    const float* bn2_g   = (const float*)d_in[3];
    const float* bn2_b   = (const float*)d_in[4];
    const float* bn2_m   = (const float*)d_in[5];
    const float* bn2_v   = (const float*)d_in[6];
    const float* temp    = (const float*)d_in[7];
    const float* w1_w    = (const float*)d_in[8];
    const float* w1_b    = (const float*)d_in[9];
    const float* bnw_g   = (const float*)d_in[10];
    const float* bnw_b   = (const float*)d_in[11];
    const float* bnw_m   = (const float*)d_in[12];
    const float* bnw_v   = (const float*)d_in[13];
    const float* w2_w    = (const float*)d_in[14];
    const float* w2_b    = (const float*)d_in[15];
    const float* proj_w  = (const float*)d_in[16];
    const float* proj_b  = (const float*)d_in[17];
    float* out = (float*)d_out;

    prep_kernel<<<1024, 256>>>(conv2_w, proj_w);
    x16_kernel<<<16384, 256>>>(x);
    conv_mma_kernel<<<dim3(2, 32, 8), 128>>>(conv2_b, bn2_g, bn2_b, bn2_m, bn2_v);
    fft2_fwd_kernel<<<1024, 512>>>();
    attn_gemm64_kernel<<<dim3(64, KSPLIT), 256>>>();
    attn_fin_kernel<<<64, 256>>>(temp);
    attn_apply_kernel<<<dim3(32, 64), 256>>>();
    ifft_row_kernel<<<2048, 512>>>(x);
    g1_kernel<<<dim3(16, 8), 256>>>(w1_w, w1_b, bnw_g, bnw_b, bnw_m, bnw_v);
    ifft2_gate_kernel<<<2048, 512>>>(x, w2_w, w2_b);
    proj_mma_kernel<<<dim3(4, 32, 8), 128>>>(proj_b, out);
}